// round 2
// baseline (speedup 1.0000x reference)
#include <cuda_runtime.h>
#include <math.h>

#define BB 4
#define SS 2048
#define HH 16
#define DD 64
#define HID 1024
#define BS (BB*SS)

// Scratch (device globals: allocation-free rule)
__device__ float g_Q [BB*HH*SS*DD];   // [b,h,s,d]
__device__ float g_KT[BB*HH*DD*SS];   // [b,h,d,s]  (transposed for coalesced QK^T)
__device__ float g_V [BB*HH*SS*DD];   // [b,h,s,d]
__device__ float g_attn[BS*HID];      // [b,s,h*d] = [B,S,HID]

// ---------------------------------------------------------------------------
// Kernel 1: QKV projection.  out = x @ W + b for W in {Wq,Wk,Wv}
// grid = (BS/64, HID/64, 3), block = 256
// ---------------------------------------------------------------------------
__global__ void qkv_kernel(const float* __restrict__ x,
                           const float* __restrict__ Wq, const float* __restrict__ bq,
                           const float* __restrict__ Wk, const float* __restrict__ bk,
                           const float* __restrict__ Wv, const float* __restrict__ bv) {
    __shared__ float xs[64 * 65];  // xs[k][m]  (x transposed)
    __shared__ float ws[64 * 65];  // ws[k][n]

    const int m0    = blockIdx.x * 64;
    const int h     = blockIdx.y;          // c0 = h*64
    const int which = blockIdx.z;
    const int c0    = h * 64;

    const float* Wp = (which == 0) ? Wq : (which == 1) ? Wk : Wv;
    const float* bp = (which == 0) ? bq : (which == 1) ? bk : bv;

    const int tid = threadIdx.x;
    for (int idx = tid; idx < 64 * 64; idx += 256) {
        int r = idx >> 6, c = idx & 63;
        xs[c * 65 + r] = x[(m0 + r) * DD + c];       // coalesced read, stride-65 write
        ws[r * 65 + c] = Wp[r * HID + c0 + c];       // coalesced read+write
    }
    __syncthreads();

    const int ty = tid >> 4, tx = tid & 15;
    float acc[4][4] = {};
    #pragma unroll 4
    for (int k = 0; k < 64; k++) {
        float a[4], bfr[4];
        #pragma unroll
        for (int i = 0; i < 4; i++) a[i]   = xs[k * 65 + ty * 4 + i];
        #pragma unroll
        for (int j = 0; j < 4; j++) bfr[j] = ws[k * 65 + tx * 4 + j];
        #pragma unroll
        for (int i = 0; i < 4; i++)
            #pragma unroll
            for (int j = 0; j < 4; j++)
                acc[i][j] = fmaf(a[i], bfr[j], acc[i][j]);
    }

    const int b   = m0 / SS;     // 64-row tile never crosses a batch boundary
    const int ss0 = m0 % SS;
    #pragma unroll
    for (int i = 0; i < 4; i++) {
        const int s = ss0 + ty * 4 + i;
        #pragma unroll
        for (int j = 0; j < 4; j++) {
            const int d   = tx * 4 + j;
            const float v = acc[i][j] + bp[c0 + d];
            if (which == 1) {
                g_KT[(((size_t)b * HH + h) * DD + d) * SS + s] = v;
            } else if (which == 0) {
                g_Q [(((size_t)b * HH + h) * SS + s) * DD + d] = v;
            } else {
                g_V [(((size_t)b * HH + h) * SS + s) * DD + d] = v;
            }
        }
    }
}

// ---------------------------------------------------------------------------
// Kernel 2: causal flash attention, fp32.
// grid = (S/64, H, B), block = 256, dyn smem = 4 * 64*65*4 bytes
// ---------------------------------------------------------------------------
__global__ void attn_kernel() {
    extern __shared__ float smem[];
    float* Qs = smem;                 // Qs[d][m]   64x65
    float* Ks = Qs + 64 * 65;         // Ks[d][n]
    float* Vs = Ks + 64 * 65;         // Vs[n][d]
    float* Ps = Vs + 64 * 65;         // Ps[n][m]

    const int qt = blockIdx.x;
    const int h  = blockIdx.y;
    const int b  = blockIdx.z;
    const int q0 = qt * 64;

    const int tid = threadIdx.x;
    const int ty  = tid >> 4, tx = tid & 15;

    const float* Qbase  = g_Q  + (((size_t)b * HH + h) * SS) * DD;
    const float* KTbase = g_KT + (((size_t)b * HH + h) * DD) * SS;
    const float* Vbase  = g_V  + (((size_t)b * HH + h) * SS) * DD;

    for (int idx = tid; idx < 64 * 64; idx += 256) {
        int r = idx >> 6, c = idx & 63;
        Qs[c * 65 + r] = Qbase[(size_t)(q0 + r) * DD + c];
    }

    float o[4][4] = {};
    float m_i[4], l_i[4];
    #pragma unroll
    for (int i = 0; i < 4; i++) { m_i[i] = -INFINITY; l_i[i] = 0.f; }

    for (int kt = 0; kt <= qt; kt++) {
        __syncthreads();   // prior GEMM2 reads of Vs/Ps done (and Q load on iter 0)
        const int k0 = kt * 64;
        for (int idx = tid; idx < 64 * 64; idx += 256) {
            int r = idx >> 6, c = idx & 63;
            Ks[r * 65 + c] = KTbase[(size_t)r * SS + k0 + c];        // Ks[d][n]
            Vs[r * 65 + c] = Vbase[(size_t)(k0 + r) * DD + c];       // Vs[n][d]
        }
        __syncthreads();

        // ---- S = Q K^T ----
        float acc[4][4] = {};
        #pragma unroll 4
        for (int k = 0; k < 64; k++) {
            float a[4], bfr[4];
            #pragma unroll
            for (int i = 0; i < 4; i++) a[i]   = Qs[k * 65 + ty * 4 + i];
            #pragma unroll
            for (int j = 0; j < 4; j++) bfr[j] = Ks[k * 65 + tx * 4 + j];
            #pragma unroll
            for (int i = 0; i < 4; i++)
                #pragma unroll
                for (int j = 0; j < 4; j++)
                    acc[i][j] = fmaf(a[i], bfr[j], acc[i][j]);
        }

        // ---- scale + causal mask + row max ----
        const bool diag = (kt == qt);
        float rmax[4];
        #pragma unroll
        for (int i = 0; i < 4; i++) {
            rmax[i] = -INFINITY;
            const int gi = q0 + ty * 4 + i;
            #pragma unroll
            for (int j = 0; j < 4; j++) {
                float v = acc[i][j] * 0.125f;
                if (diag && (k0 + tx * 4 + j) > gi) v = -INFINITY;
                acc[i][j] = v;
                rmax[i] = fmaxf(rmax[i], v);
            }
        }
        #pragma unroll
        for (int i = 0; i < 4; i++)
            #pragma unroll
            for (int off = 1; off < 16; off <<= 1)
                rmax[i] = fmaxf(rmax[i], __shfl_xor_sync(0xffffffffu, rmax[i], off));

        // ---- online softmax update ----
        float rsum[4];
        #pragma unroll
        for (int i = 0; i < 4; i++) {
            const float nm   = fmaxf(m_i[i], rmax[i]);
            const float corr = __expf(m_i[i] - nm);
            m_i[i] = nm;
            float s = 0.f;
            #pragma unroll
            for (int j = 0; j < 4; j++) {
                acc[i][j] = __expf(acc[i][j] - nm);
                s += acc[i][j];
            }
            rsum[i] = s;
            l_i[i] *= corr;
            #pragma unroll
            for (int j = 0; j < 4; j++) o[i][j] *= corr;
        }
        #pragma unroll
        for (int i = 0; i < 4; i++) {
            #pragma unroll
            for (int off = 1; off < 16; off <<= 1)
                rsum[i] += __shfl_xor_sync(0xffffffffu, rsum[i], off);
            l_i[i] += rsum[i];
        }

        // ---- P to smem (transposed) ----
        #pragma unroll
        for (int i = 0; i < 4; i++)
            #pragma unroll
            for (int j = 0; j < 4; j++)
                Ps[(tx * 4 + j) * 65 + ty * 4 + i] = acc[i][j];
        __syncthreads();

        // ---- O += P V ----
        #pragma unroll 4
        for (int n = 0; n < 64; n++) {
            float p[4], vv[4];
            #pragma unroll
            for (int i = 0; i < 4; i++) p[i]  = Ps[n * 65 + ty * 4 + i];
            #pragma unroll
            for (int j = 0; j < 4; j++) vv[j] = Vs[n * 65 + tx * 4 + j];
            #pragma unroll
            for (int i = 0; i < 4; i++)
                #pragma unroll
                for (int j = 0; j < 4; j++)
                    o[i][j] = fmaf(p[i], vv[j], o[i][j]);
        }
    }

    // ---- epilogue: normalize, write attn output as [B,S,H,D] ----
    #pragma unroll
    for (int i = 0; i < 4; i++) {
        const float inv = 1.f / l_i[i];
        const int s = q0 + ty * 4 + i;
        #pragma unroll
        for (int j = 0; j < 4; j++)
            g_attn[(((size_t)b * SS + s) * HH + h) * DD + tx * 4 + j] = o[i][j] * inv;
    }
}

// ---------------------------------------------------------------------------
// Kernel 3: output projection. Y[8192,64] = attn[8192,1024] @ Wo[1024,64] + bo
// grid = BS/64, block = 256
// ---------------------------------------------------------------------------
__global__ void oproj_kernel(const float* __restrict__ Wo,
                             const float* __restrict__ bo,
                             float* __restrict__ out) {
    __shared__ float As[64 * 65];   // As[k][m]
    __shared__ float Ws2[64 * 65];  // Ws2[k][n]
    const int m0  = blockIdx.x * 64;
    const int tid = threadIdx.x;
    const int ty  = tid >> 4, tx = tid & 15;

    float acc[4][4] = {};
    for (int kt = 0; kt < HID / 64; kt++) {
        __syncthreads();
        for (int idx = tid; idx < 64 * 64; idx += 256) {
            int r = idx >> 6, c = idx & 63;
            As [c * 65 + r] = g_attn[(size_t)(m0 + r) * HID + kt * 64 + c];
            Ws2[r * 65 + c] = Wo[(size_t)(kt * 64 + r) * DD + c];
        }
        __syncthreads();
        #pragma unroll 4
        for (int k = 0; k < 64; k++) {
            float a[4], w[4];
            #pragma unroll
            for (int i = 0; i < 4; i++) a[i] = As[k * 65 + ty * 4 + i];
            #pragma unroll
            for (int j = 0; j < 4; j++) w[j] = Ws2[k * 65 + tx * 4 + j];
            #pragma unroll
            for (int i = 0; i < 4; i++)
                #pragma unroll
                for (int j = 0; j < 4; j++)
                    acc[i][j] = fmaf(a[i], w[j], acc[i][j]);
        }
    }
    #pragma unroll
    for (int i = 0; i < 4; i++)
        #pragma unroll
        for (int j = 0; j < 4; j++)
            out[(size_t)(m0 + ty * 4 + i) * DD + tx * 4 + j] = acc[i][j] + bo[tx * 4 + j];
}

// ---------------------------------------------------------------------------
extern "C" void kernel_launch(void* const* d_in, const int* in_sizes, int n_in,
                              void* d_out, int out_size) {
    (void)in_sizes; (void)n_in; (void)out_size;
    const float* x  = (const float*)d_in[0];
    const float* Wq = (const float*)d_in[1];
    const float* bq = (const float*)d_in[2];
    const float* Wk = (const float*)d_in[3];
    const float* bk = (const float*)d_in[4];
    const float* Wv = (const float*)d_in[5];
    const float* bv = (const float*)d_in[6];
    const float* Wo = (const float*)d_in[7];
    const float* bo = (const float*)d_in[8];
    float* out = (float*)d_out;

    qkv_kernel<<<dim3(BS / 64, HID / 64, 3), 256>>>(x, Wq, bq, Wk, bk, Wv, bv);

    const int attn_smem = 4 * 64 * 65 * (int)sizeof(float);  // 66,560 B
    cudaFuncSetAttribute(attn_kernel, cudaFuncAttributeMaxDynamicSharedMemorySize, attn_smem);
    attn_kernel<<<dim3(SS / 64, HH, BB), 256, attn_smem>>>();

    oproj_kernel<<<BS / 64, 256>>>(Wo, bo, out);
}

// round 4
// speedup vs baseline: 2.2710x; 2.2710x over previous
#include <cuda_runtime.h>
#include <cuda_bf16.h>
#include <math.h>
#include <stdint.h>

#define BB 4
#define SS 2048
#define HH 16
#define DD 64
#define HID 1024
#define BS (BB*SS)

// ---------------- scratch (device globals: allocation-free rule) ------------
// All [b,h,s,d]. Q pre-scaled by (1/sqrt(D)) * log2(e)  (base-2 softmax).
__device__ __nv_bfloat16 g_Qh[BB*HH*SS*DD];
__device__ __nv_bfloat16 g_Ql[BB*HH*SS*DD];
__device__ __nv_bfloat16 g_Kh[BB*HH*SS*DD];
__device__ __nv_bfloat16 g_Kl[BB*HH*SS*DD];
__device__ __nv_bfloat16 g_Vh[BB*HH*SS*DD];
__device__ __nv_bfloat16 g_Vl[BB*HH*SS*DD];
__device__ float g_attn[BS*HID];              // [B,S,HID]

// ---------------- helpers ---------------------------------------------------
static __device__ __forceinline__ uint32_t smem_u32(const void* p) {
    return (uint32_t)__cvta_generic_to_shared(p);
}

static __device__ __forceinline__ void ldm_x4(uint32_t* r, uint32_t addr) {
    asm volatile("ldmatrix.sync.aligned.m8n8.x4.shared.b16 {%0,%1,%2,%3}, [%4];"
                 : "=r"(r[0]), "=r"(r[1]), "=r"(r[2]), "=r"(r[3]) : "r"(addr));
}
static __device__ __forceinline__ void ldm_x4_t(uint32_t* r, uint32_t addr) {
    asm volatile("ldmatrix.sync.aligned.m8n8.x4.trans.shared.b16 {%0,%1,%2,%3}, [%4];"
                 : "=r"(r[0]), "=r"(r[1]), "=r"(r[2]), "=r"(r[3]) : "r"(addr));
}
static __device__ __forceinline__ void mma16816(float* c,
                                                uint32_t a0, uint32_t a1, uint32_t a2, uint32_t a3,
                                                uint32_t b0, uint32_t b1) {
    asm volatile(
        "mma.sync.aligned.m16n8k16.row.col.f32.bf16.bf16.f32 "
        "{%0,%1,%2,%3}, {%4,%5,%6,%7}, {%8,%9}, {%0,%1,%2,%3};"
        : "+f"(c[0]), "+f"(c[1]), "+f"(c[2]), "+f"(c[3])
        : "r"(a0), "r"(a1), "r"(a2), "r"(a3), "r"(b0), "r"(b1));
}
static __device__ __forceinline__ uint32_t pack2bf(float f0, float f1) {
    __nv_bfloat162 t = __halves2bfloat162(__float2bfloat16(f0), __float2bfloat16(f1));
    return *reinterpret_cast<uint32_t*>(&t);
}

// ---------------------------------------------------------------------------
// Kernel 1: QKV projection -> bf16 hi/lo.  Q pre-scaled by log2e/sqrt(D).
// grid = (BS/64, HID/64, 3), block = 256
// ---------------------------------------------------------------------------
__global__ void qkv_kernel(const float* __restrict__ x,
                           const float* __restrict__ Wq, const float* __restrict__ bq,
                           const float* __restrict__ Wk, const float* __restrict__ bk,
                           const float* __restrict__ Wv, const float* __restrict__ bv) {
    __shared__ float xs[64 * 65];
    __shared__ float ws[64 * 65];

    const int m0    = blockIdx.x * 64;
    const int h     = blockIdx.y;
    const int which = blockIdx.z;
    const int c0    = h * 64;

    const float* Wp = (which == 0) ? Wq : (which == 1) ? Wk : Wv;
    const float* bp = (which == 0) ? bq : (which == 1) ? bk : bv;

    const int tid = threadIdx.x;
    for (int idx = tid; idx < 64 * 64; idx += 256) {
        int r = idx >> 6, c = idx & 63;
        xs[c * 65 + r] = x[(m0 + r) * DD + c];
        ws[r * 65 + c] = Wp[r * HID + c0 + c];
    }
    __syncthreads();

    const int ty = tid >> 4, tx = tid & 15;
    float acc[4][4] = {};
    #pragma unroll 4
    for (int k = 0; k < 64; k++) {
        float a[4], bfr[4];
        #pragma unroll
        for (int i = 0; i < 4; i++) a[i]   = xs[k * 65 + ty * 4 + i];
        #pragma unroll
        for (int j = 0; j < 4; j++) bfr[j] = ws[k * 65 + tx * 4 + j];
        #pragma unroll
        for (int i = 0; i < 4; i++)
            #pragma unroll
            for (int j = 0; j < 4; j++)
                acc[i][j] = fmaf(a[i], bfr[j], acc[i][j]);
    }

    const int b   = m0 / SS;
    const int ss0 = m0 % SS;
    const float scale = (which == 0) ? 0.125f * 1.4426950408889634f : 1.0f;
    #pragma unroll
    for (int i = 0; i < 4; i++) {
        const int s = ss0 + ty * 4 + i;
        #pragma unroll
        for (int j = 0; j < 4; j++) {
            const int d   = tx * 4 + j;
            const float v = (acc[i][j] + bp[c0 + d]) * scale;
            __nv_bfloat16 hi = __float2bfloat16(v);
            __nv_bfloat16 lo = __float2bfloat16(v - __bfloat162float(hi));
            size_t idx = (((size_t)b * HH + h) * SS + s) * DD + d;
            if (which == 0)      { g_Qh[idx] = hi; g_Ql[idx] = lo; }
            else if (which == 1) { g_Kh[idx] = hi; g_Kl[idx] = lo; }
            else                 { g_Vh[idx] = hi; g_Vl[idx] = lo; }
        }
    }
}

// ---------------------------------------------------------------------------
// Kernel 2: causal flash attention on mma.sync bf16 (hi/lo split, f32 accum).
// grid = (S/64, H, B), block = 128 (4 warps, each owns 16 query rows).
// ---------------------------------------------------------------------------
// smem: 6 tiles of 64 rows x 64 bf16, row stride 72 elems (144B, pad kills
// ldmatrix bank conflicts). Offsets in bytes:
#define TILE_B   (64 * 144)            // 9216
#define SQH 0
#define SQL (SQH + TILE_B)
#define SKH (SQL + TILE_B)
#define SKL (SKH + TILE_B)
#define SVH (SKL + TILE_B)
#define SVL (SVH + TILE_B)
#define ATTN_SMEM (6 * TILE_B)         // 55296

__global__ void __launch_bounds__(128) attn_kernel() {
    extern __shared__ char smem[];
    const uint32_t smb = smem_u32(smem);

    const int qt = blockIdx.x;
    const int h  = blockIdx.y;
    const int b  = blockIdx.z;
    const int q0 = qt * 64;

    const int tid  = threadIdx.x;
    const int w    = tid >> 5;
    const int lane = tid & 31;

    const size_t bh = (size_t)b * HH + h;
    const __nv_bfloat16* Qh = g_Qh + (bh * SS + q0) * DD;
    const __nv_bfloat16* Ql = g_Ql + (bh * SS + q0) * DD;
    const __nv_bfloat16* Kh = g_Kh + bh * SS * DD;
    const __nv_bfloat16* Kl = g_Kl + bh * SS * DD;
    const __nv_bfloat16* Vh = g_Vh + bh * SS * DD;
    const __nv_bfloat16* Vl = g_Vl + bh * SS * DD;

    // ---- fill Q tile ----
    for (int idx = tid; idx < 512; idx += 128) {
        int r = idx >> 3, ch = idx & 7;
        *(uint4*)(smem + SQH + r * 144 + ch * 16) = *(const uint4*)(Qh + (size_t)r * DD + ch * 8);
        *(uint4*)(smem + SQL + r * 144 + ch * 16) = *(const uint4*)(Ql + (size_t)r * DD + ch * 8);
    }
    __syncthreads();

    // ---- Q fragments (held in registers for the whole CTA lifetime) ----
    uint32_t qh[4][4], qlr[4][4];
    {
        const uint32_t qbase = smb + SQH + (uint32_t)((w * 16 + (lane & 15)) * 144 + (lane >> 4) * 16);
        #pragma unroll
        for (int kk = 0; kk < 4; kk++) {
            ldm_x4(qh[kk],  qbase + kk * 32);
            ldm_x4(qlr[kk], qbase + kk * 32 + (SQL - SQH));
        }
    }

    // per-lane ldmatrix bases for K and V
    const uint32_t kbase = smb + SKH +
        (uint32_t)(((lane & 7) + ((lane >> 4) & 1) * 8) * 144 + ((lane >> 3) & 1) * 16);
    const uint32_t vbase = smb + SVH +
        (uint32_t)(((lane & 7) + ((lane >> 3) & 1) * 8) * 144 + ((lane >> 4) & 1) * 16);

    float o[8][4];
    #pragma unroll
    for (int j = 0; j < 8; j++)
        #pragma unroll
        for (int e = 0; e < 4; e++) o[j][e] = 0.f;
    float m0 = -1e30f, m1 = -1e30f, l0 = 0.f, l1 = 0.f;

    const int rg0 = q0 + w * 16 + (lane >> 2);   // my first global query row

    for (int kt = 0; kt <= qt; kt++) {
        const int k0 = kt * 64;
        const bool diag = (kt == qt);

        __syncthreads();   // previous iteration's ldmatrix reads of K/V done
        for (int idx = tid; idx < 512; idx += 128) {
            int r = idx >> 3, ch = idx & 7;
            const size_t g = (size_t)(k0 + r) * DD + ch * 8;
            *(uint4*)(smem + SKH + r * 144 + ch * 16) = *(const uint4*)(Kh + g);
            *(uint4*)(smem + SKL + r * 144 + ch * 16) = *(const uint4*)(Kl + g);
            *(uint4*)(smem + SVH + r * 144 + ch * 16) = *(const uint4*)(Vh + g);
            *(uint4*)(smem + SVL + r * 144 + ch * 16) = *(const uint4*)(Vl + g);
        }
        __syncthreads();

        // ---- S = Q K^T (hi*hi + hi*lo + lo*hi) ----
        float sacc[8][4];
        #pragma unroll
        for (int j = 0; j < 8; j++)
            #pragma unroll
            for (int e = 0; e < 4; e++) sacc[j][e] = 0.f;

        #pragma unroll
        for (int jj = 0; jj < 4; jj++) {
            #pragma unroll
            for (int kk = 0; kk < 4; kk++) {
                uint32_t bhr[4], blr[4];
                const uint32_t ka = kbase + (uint32_t)(jj * 16 * 144 + kk * 32);
                ldm_x4(bhr, ka);
                ldm_x4(blr, ka + (SKL - SKH));
                mma16816(sacc[2*jj],   qh[kk][0], qh[kk][1], qh[kk][2], qh[kk][3], bhr[0], bhr[1]);
                mma16816(sacc[2*jj],   qh[kk][0], qh[kk][1], qh[kk][2], qh[kk][3], blr[0], blr[1]);
                mma16816(sacc[2*jj],   qlr[kk][0], qlr[kk][1], qlr[kk][2], qlr[kk][3], bhr[0], bhr[1]);
                mma16816(sacc[2*jj+1], qh[kk][0], qh[kk][1], qh[kk][2], qh[kk][3], bhr[2], bhr[3]);
                mma16816(sacc[2*jj+1], qh[kk][0], qh[kk][1], qh[kk][2], qh[kk][3], blr[2], blr[3]);
                mma16816(sacc[2*jj+1], qlr[kk][0], qlr[kk][1], qlr[kk][2], qlr[kk][3], bhr[2], bhr[3]);
            }
        }

        // ---- causal mask (diag tile only) ----
        if (diag) {
            #pragma unroll
            for (int j = 0; j < 8; j++) {
                const int cbase = k0 + j * 8 + 2 * (lane & 3);
                if (cbase     > rg0)     sacc[j][0] = -1e30f;
                if (cbase + 1 > rg0)     sacc[j][1] = -1e30f;
                if (cbase     > rg0 + 8) sacc[j][2] = -1e30f;
                if (cbase + 1 > rg0 + 8) sacc[j][3] = -1e30f;
            }
        }

        // ---- online softmax (base-2; log2e folded into Q scale) ----
        float mx0 = -1e30f, mx1 = -1e30f;
        #pragma unroll
        for (int j = 0; j < 8; j++) {
            mx0 = fmaxf(mx0, fmaxf(sacc[j][0], sacc[j][1]));
            mx1 = fmaxf(mx1, fmaxf(sacc[j][2], sacc[j][3]));
        }
        mx0 = fmaxf(mx0, __shfl_xor_sync(0xffffffffu, mx0, 1));
        mx0 = fmaxf(mx0, __shfl_xor_sync(0xffffffffu, mx0, 2));
        mx1 = fmaxf(mx1, __shfl_xor_sync(0xffffffffu, mx1, 1));
        mx1 = fmaxf(mx1, __shfl_xor_sync(0xffffffffu, mx1, 2));

        const float nm0 = fmaxf(m0, mx0);
        const float nm1 = fmaxf(m1, mx1);
        const float corr0 = exp2f(m0 - nm0);
        const float corr1 = exp2f(m1 - nm1);
        m0 = nm0; m1 = nm1;

        uint32_t ph[8][2], pl[8][2];
        float s0 = 0.f, s1 = 0.f;
        #pragma unroll
        for (int j = 0; j < 8; j++) {
            float p0 = exp2f(sacc[j][0] - nm0);
            float p1 = exp2f(sacc[j][1] - nm0);
            float p2 = exp2f(sacc[j][2] - nm1);
            float p3 = exp2f(sacc[j][3] - nm1);
            s0 += p0 + p1;
            s1 += p2 + p3;
            __nv_bfloat16 h0 = __float2bfloat16(p0), h1 = __float2bfloat16(p1);
            __nv_bfloat16 h2 = __float2bfloat16(p2), h3 = __float2bfloat16(p3);
            ph[j][0] = pack2bf(p0, p1);   // relies on rn; identical to h0,h1
            ph[j][1] = pack2bf(p2, p3);
            pl[j][0] = pack2bf(p0 - __bfloat162float(h0), p1 - __bfloat162float(h1));
            pl[j][1] = pack2bf(p2 - __bfloat162float(h2), p3 - __bfloat162float(h3));
        }
        s0 += __shfl_xor_sync(0xffffffffu, s0, 1);
        s0 += __shfl_xor_sync(0xffffffffu, s0, 2);
        s1 += __shfl_xor_sync(0xffffffffu, s1, 1);
        s1 += __shfl_xor_sync(0xffffffffu, s1, 2);
        l0 = l0 * corr0 + s0;
        l1 = l1 * corr1 + s1;

        #pragma unroll
        for (int j = 0; j < 8; j++) {
            o[j][0] *= corr0; o[j][1] *= corr0;
            o[j][2] *= corr1; o[j][3] *= corr1;
        }

        // ---- O += P V (Ph*Vh + Ph*Vl + Pl*Vh) ----
        #pragma unroll
        for (int dd = 0; dd < 4; dd++) {
            #pragma unroll
            for (int kk = 0; kk < 4; kk++) {
                uint32_t vh[4], vl[4];
                const uint32_t va = vbase + (uint32_t)(kk * 16 * 144 + dd * 32);
                ldm_x4_t(vh, va);
                ldm_x4_t(vl, va + (SVL - SVH));
                mma16816(o[2*dd],   ph[2*kk][0], ph[2*kk][1], ph[2*kk+1][0], ph[2*kk+1][1], vh[0], vh[1]);
                mma16816(o[2*dd],   ph[2*kk][0], ph[2*kk][1], ph[2*kk+1][0], ph[2*kk+1][1], vl[0], vl[1]);
                mma16816(o[2*dd],   pl[2*kk][0], pl[2*kk][1], pl[2*kk+1][0], pl[2*kk+1][1], vh[0], vh[1]);
                mma16816(o[2*dd+1], ph[2*kk][0], ph[2*kk][1], ph[2*kk+1][0], ph[2*kk+1][1], vh[2], vh[3]);
                mma16816(o[2*dd+1], ph[2*kk][0], ph[2*kk][1], ph[2*kk+1][0], ph[2*kk+1][1], vl[2], vl[3]);
                mma16816(o[2*dd+1], pl[2*kk][0], pl[2*kk][1], pl[2*kk+1][0], pl[2*kk+1][1], vh[2], vh[3]);
            }
        }
    }

    // ---- epilogue: normalize and write [B,S,HID] ----
    const float inv0 = 1.f / l0;
    const float inv1 = 1.f / l1;
    float* dst0 = g_attn + ((size_t)b * SS + rg0) * HID + h * 64;
    float* dst1 = dst0 + (size_t)8 * HID;
    #pragma unroll
    for (int j = 0; j < 8; j++) {
        const int c = j * 8 + 2 * (lane & 3);
        dst0[c]     = o[j][0] * inv0;
        dst0[c + 1] = o[j][1] * inv0;
        dst1[c]     = o[j][2] * inv1;
        dst1[c + 1] = o[j][3] * inv1;
    }
}

// ---------------------------------------------------------------------------
// Kernel 3: output projection. Y[8192,64] = attn[8192,1024] @ Wo[1024,64] + bo
// ---------------------------------------------------------------------------
__global__ void oproj_kernel(const float* __restrict__ Wo,
                             const float* __restrict__ bo,
                             float* __restrict__ out) {
    __shared__ float As[64 * 65];
    __shared__ float Ws2[64 * 65];
    const int m0  = blockIdx.x * 64;
    const int tid = threadIdx.x;
    const int ty  = tid >> 4, tx = tid & 15;

    float acc[4][4] = {};
    for (int kt = 0; kt < HID / 64; kt++) {
        __syncthreads();
        for (int idx = tid; idx < 64 * 64; idx += 256) {
            int r = idx >> 6, c = idx & 63;
            As [c * 65 + r] = g_attn[(size_t)(m0 + r) * HID + kt * 64 + c];
            Ws2[r * 65 + c] = Wo[(size_t)(kt * 64 + r) * DD + c];
        }
        __syncthreads();
        #pragma unroll 4
        for (int k = 0; k < 64; k++) {
            float a[4], wv[4];
            #pragma unroll
            for (int i = 0; i < 4; i++) a[i]  = As[k * 65 + ty * 4 + i];
            #pragma unroll
            for (int j = 0; j < 4; j++) wv[j] = Ws2[k * 65 + tx * 4 + j];
            #pragma unroll
            for (int i = 0; i < 4; i++)
                #pragma unroll
                for (int j = 0; j < 4; j++)
                    acc[i][j] = fmaf(a[i], wv[j], acc[i][j]);
        }
    }
    #pragma unroll
    for (int i = 0; i < 4; i++)
        #pragma unroll
        for (int j = 0; j < 4; j++)
            out[(size_t)(m0 + ty * 4 + i) * DD + tx * 4 + j] = acc[i][j] + bo[tx * 4 + j];
}

// ---------------------------------------------------------------------------
extern "C" void kernel_launch(void* const* d_in, const int* in_sizes, int n_in,
                              void* d_out, int out_size) {
    (void)in_sizes; (void)n_in; (void)out_size;
    const float* x  = (const float*)d_in[0];
    const float* Wq = (const float*)d_in[1];
    const float* bq = (const float*)d_in[2];
    const float* Wk = (const float*)d_in[3];
    const float* bk = (const float*)d_in[4];
    const float* Wv = (const float*)d_in[5];
    const float* bv = (const float*)d_in[6];
    const float* Wo = (const float*)d_in[7];
    const float* bo = (const float*)d_in[8];
    float* out = (float*)d_out;

    qkv_kernel<<<dim3(BS / 64, HID / 64, 3), 256>>>(x, Wq, bq, Wk, bk, Wv, bv);

    cudaFuncSetAttribute(attn_kernel, cudaFuncAttributeMaxDynamicSharedMemorySize, ATTN_SMEM);
    attn_kernel<<<dim3(SS / 64, HH, BB), 128, ATTN_SMEM>>>();

    oproj_kernel<<<BS / 64, 256>>>(Wo, bo, out);
}

// round 6
// speedup vs baseline: 2.8633x; 1.2608x over previous
#include <cuda_runtime.h>
#include <cuda_bf16.h>
#include <math.h>
#include <stdint.h>

#define BB 4
#define SS 2048
#define HH 16
#define DD 64
#define HID 1024
#define BS (BB*SS)
#define LOG2E 1.4426950408889634f

// ---------------- scratch (device globals: allocation-free rule) ------------
__device__ __nv_bfloat16 g_xh[BS*DD];          // x split
__device__ __nv_bfloat16 g_xl[BS*DD];
__device__ __nv_bfloat16 g_WTh[3*HID*DD];      // W^T split: [which][n][k]
__device__ __nv_bfloat16 g_WTl[3*HID*DD];
// Q pre-scaled by (1/sqrt(D)) * log2(e). All [b,h,s,d].
__device__ __nv_bfloat16 g_Qh[BB*HH*SS*DD];
__device__ __nv_bfloat16 g_Ql[BB*HH*SS*DD];
__device__ __nv_bfloat16 g_Kh[BB*HH*SS*DD];
__device__ __nv_bfloat16 g_Kl[BB*HH*SS*DD];
__device__ __nv_bfloat16 g_Vh[BB*HH*SS*DD];
__device__ __nv_bfloat16 g_Vl[BB*HH*SS*DD];
__device__ float g_attn[BS*HID];               // [B,S,HID]

// ---------------- helpers ---------------------------------------------------
static __device__ __forceinline__ uint32_t smem_u32(const void* p) {
    return (uint32_t)__cvta_generic_to_shared(p);
}
static __device__ __forceinline__ void ldm_x4(uint32_t* r, uint32_t addr) {
    asm volatile("ldmatrix.sync.aligned.m8n8.x4.shared.b16 {%0,%1,%2,%3}, [%4];"
                 : "=r"(r[0]), "=r"(r[1]), "=r"(r[2]), "=r"(r[3]) : "r"(addr));
}
static __device__ __forceinline__ void ldm_x4_t(uint32_t* r, uint32_t addr) {
    asm volatile("ldmatrix.sync.aligned.m8n8.x4.trans.shared.b16 {%0,%1,%2,%3}, [%4];"
                 : "=r"(r[0]), "=r"(r[1]), "=r"(r[2]), "=r"(r[3]) : "r"(addr));
}
static __device__ __forceinline__ void mma16816(float* c,
                                                uint32_t a0, uint32_t a1, uint32_t a2, uint32_t a3,
                                                uint32_t b0, uint32_t b1) {
    asm volatile(
        "mma.sync.aligned.m16n8k16.row.col.f32.bf16.bf16.f32 "
        "{%0,%1,%2,%3}, {%4,%5,%6,%7}, {%8,%9}, {%0,%1,%2,%3};"
        : "+f"(c[0]), "+f"(c[1]), "+f"(c[2]), "+f"(c[3])
        : "r"(a0), "r"(a1), "r"(a2), "r"(a3), "r"(b0), "r"(b1));
}
static __device__ __forceinline__ uint32_t pack2bf(float f0, float f1) {
    __nv_bfloat162 t = __halves2bfloat162(__float2bfloat16(f0), __float2bfloat16(f1));
    return *reinterpret_cast<uint32_t*>(&t);
}
#define CPA(dst, src) asm volatile("cp.async.ca.shared.global [%0], [%1], 16;" :: "r"(dst), "l"(src))
#define CPC()   asm volatile("cp.async.commit_group;" ::: "memory")
#define CPW1()  asm volatile("cp.async.wait_group 1;" ::: "memory")
#define CPW0()  asm volatile("cp.async.wait_group 0;" ::: "memory")

// ---------------------------------------------------------------------------
// Kernel 0: prep — split x and W^T to bf16 hi/lo.
// ---------------------------------------------------------------------------
#define NX (BS*DD)          // 524288
#define NW (3*HID*DD)       // 196608
__global__ void prep_kernel(const float* __restrict__ x,
                            const float* __restrict__ Wq,
                            const float* __restrict__ Wk,
                            const float* __restrict__ Wv) {
    for (int idx = blockIdx.x * blockDim.x + threadIdx.x; idx < NX + NW;
         idx += gridDim.x * blockDim.x) {
        if (idx < NX) {
            float f = x[idx];
            __nv_bfloat16 hi = __float2bfloat16(f);
            g_xh[idx] = hi;
            g_xl[idx] = __float2bfloat16(f - __bfloat162float(hi));
        } else {
            int r = idx - NX;
            int which = r >> 16;
            int t = r & 65535;
            int n = t >> 6, k = t & 63;
            const float* W = (which == 0) ? Wq : (which == 1) ? Wk : Wv;
            float f = W[k * HID + n];
            __nv_bfloat16 hi = __float2bfloat16(f);
            g_WTh[r] = hi;
            g_WTl[r] = __float2bfloat16(f - __bfloat162float(hi));
        }
    }
}

// ---------------------------------------------------------------------------
// Kernel 1: QKV projection via HMMA (bf16 hi/lo, 3 combos).
// grid = (BS/64, HID/64, 3), block = 128 (4 warps, each 16 rows x 64 cols)
// ---------------------------------------------------------------------------
#define QKV_XH 0
#define QKV_XL 9216
#define QKV_WH 18432
#define QKV_WL 27648
__global__ void __launch_bounds__(128) qkv_mma_kernel(const float* __restrict__ bq,
                                                      const float* __restrict__ bk,
                                                      const float* __restrict__ bv) {
    __shared__ __align__(16) char smem[4 * 9216];
    const uint32_t smb = smem_u32(smem);

    const int m0    = blockIdx.x * 64;
    const int h     = blockIdx.y;          // column tile = head
    const int which = blockIdx.z;
    const int c0    = h * 64;

    const int tid  = threadIdx.x;
    const int w    = tid >> 5;
    const int lane = tid & 31;

    const float* bp = (which == 0) ? bq : (which == 1) ? bk : bv;

    // fill tiles: x rows (m) and W^T rows (n), both 64 x 64 bf16, hi/lo
    for (int idx = tid; idx < 2048; idx += 128) {
        int arr = idx >> 9, rem = idx & 511, r = rem >> 3, ch = rem & 7;
        const __nv_bfloat16* src;
        if      (arr == 0) src = g_xh  + (size_t)(m0 + r) * DD + ch * 8;
        else if (arr == 1) src = g_xl  + (size_t)(m0 + r) * DD + ch * 8;
        else if (arr == 2) src = g_WTh + (size_t)which * HID * DD + (size_t)(c0 + r) * DD + ch * 8;
        else               src = g_WTl + (size_t)which * HID * DD + (size_t)(c0 + r) * DD + ch * 8;
        *(uint4*)(smem + arr * 9216 + r * 144 + ch * 16) = *(const uint4*)src;
    }
    __syncthreads();

    uint32_t ah[4][4], al[4][4];
    {
        const uint32_t abase = smb + QKV_XH + (uint32_t)((w * 16 + (lane & 15)) * 144 + (lane >> 4) * 16);
        #pragma unroll
        for (int kk = 0; kk < 4; kk++) {
            ldm_x4(ah[kk], abase + kk * 32);
            ldm_x4(al[kk], abase + kk * 32 + (QKV_XL - QKV_XH));
        }
    }
    const uint32_t bbase = smb + QKV_WH +
        (uint32_t)(((lane & 7) + ((lane >> 4) & 1) * 8) * 144 + ((lane >> 3) & 1) * 16);

    float sacc[8][4];
    #pragma unroll
    for (int j = 0; j < 8; j++)
        #pragma unroll
        for (int e = 0; e < 4; e++) sacc[j][e] = 0.f;

    #pragma unroll
    for (int jj = 0; jj < 4; jj++) {
        #pragma unroll
        for (int kk = 0; kk < 4; kk++) {
            uint32_t bhr[4], blr[4];
            const uint32_t ba = bbase + (uint32_t)(jj * 16 * 144 + kk * 32);
            ldm_x4(bhr, ba);
            ldm_x4(blr, ba + (QKV_WL - QKV_WH));
            mma16816(sacc[2*jj],   ah[kk][0], ah[kk][1], ah[kk][2], ah[kk][3], bhr[0], bhr[1]);
            mma16816(sacc[2*jj],   ah[kk][0], ah[kk][1], ah[kk][2], ah[kk][3], blr[0], blr[1]);
            mma16816(sacc[2*jj],   al[kk][0], al[kk][1], al[kk][2], al[kk][3], bhr[0], bhr[1]);
            mma16816(sacc[2*jj+1], ah[kk][0], ah[kk][1], ah[kk][2], ah[kk][3], bhr[2], bhr[3]);
            mma16816(sacc[2*jj+1], ah[kk][0], ah[kk][1], ah[kk][2], ah[kk][3], blr[2], blr[3]);
            mma16816(sacc[2*jj+1], al[kk][0], al[kk][1], al[kk][2], al[kk][3], bhr[2], bhr[3]);
        }
    }

    // epilogue: + bias, scale (Q only), split hi/lo, store [b,h,s,d]
    __nv_bfloat16* Ah = (which == 0) ? g_Qh : (which == 1) ? g_Kh : g_Vh;
    __nv_bfloat16* Al = (which == 0) ? g_Ql : (which == 1) ? g_Kl : g_Vl;
    const float scale = (which == 0) ? 0.125f * LOG2E : 1.0f;
    const int b   = m0 >> 11;           // /SS
    const int ss0 = m0 & 2047;
    const int r0  = w * 16 + (lane >> 2);
    const size_t base0 = (((size_t)b * HH + h) * SS + (ss0 + r0)) * DD;
    const size_t base1 = base0 + (size_t)8 * DD;
    #pragma unroll
    for (int j = 0; j < 8; j++) {
        const int c = j * 8 + 2 * (lane & 3);
        {
            float v0 = (sacc[j][0] + bp[c0 + c]) * scale;
            float v1 = (sacc[j][1] + bp[c0 + c + 1]) * scale;
            __nv_bfloat16 h0 = __float2bfloat16(v0), h1 = __float2bfloat16(v1);
            *(uint32_t*)&Ah[base0 + c] = pack2bf(v0, v1);
            *(uint32_t*)&Al[base0 + c] = pack2bf(v0 - __bfloat162float(h0), v1 - __bfloat162float(h1));
        }
        {
            float v0 = (sacc[j][2] + bp[c0 + c]) * scale;
            float v1 = (sacc[j][3] + bp[c0 + c + 1]) * scale;
            __nv_bfloat16 h0 = __float2bfloat16(v0), h1 = __float2bfloat16(v1);
            *(uint32_t*)&Ah[base1 + c] = pack2bf(v0, v1);
            *(uint32_t*)&Al[base1 + c] = pack2bf(v0 - __bfloat162float(h0), v1 - __bfloat162float(h1));
        }
    }
}

// ---------------------------------------------------------------------------
// Kernel 2: causal flash attention (HMMA hi/lo), Q-tile 128, 8 warps,
// double-buffered cp.async K/V.  grid = (S/128, H, B), block = 256.
// ---------------------------------------------------------------------------
#define SQH 0
#define SQL 18432
#define SKV 36864            // two buffers of 36864 (KH,KL,VH,VL @ 9216 each)
#define ATTN_SMEM (36864 + 2*36864)   // 110592

__global__ void __launch_bounds__(256) attn_kernel() {
    extern __shared__ char smem[];
    const uint32_t smb = smem_u32(smem);

    const int qt = blockIdx.x;
    const int h  = blockIdx.y;
    const int b  = blockIdx.z;
    const int q0 = qt * 128;

    const int tid  = threadIdx.x;
    const int w    = tid >> 5;
    const int lane = tid & 31;

    const size_t bh = (size_t)b * HH + h;
    const __nv_bfloat16* Qh = g_Qh + (bh * SS + q0) * DD;
    const __nv_bfloat16* Ql = g_Ql + (bh * SS + q0) * DD;
    const __nv_bfloat16* Kh = g_Kh + bh * SS * DD;
    const __nv_bfloat16* Kl = g_Kl + bh * SS * DD;
    const __nv_bfloat16* Vh = g_Vh + bh * SS * DD;
    const __nv_bfloat16* Vl = g_Vl + bh * SS * DD;

    const int ktmax = 2 * qt + 1;

    // prefetch K/V tile 0 into buffer 0
    {
        const uint32_t base = smb + SKV;
        for (int idx = tid; idx < 2048; idx += 256) {
            int arr = idx >> 9, rem = idx & 511, r = rem >> 3, ch = rem & 7;
            const __nv_bfloat16* src;
            if      (arr == 0) src = Kh + (size_t)r * DD + ch * 8;
            else if (arr == 1) src = Kl + (size_t)r * DD + ch * 8;
            else if (arr == 2) src = Vh + (size_t)r * DD + ch * 8;
            else               src = Vl + (size_t)r * DD + ch * 8;
            CPA(base + arr * 9216 + r * 144 + ch * 16, src);
        }
        CPC();
    }

    // load Q tile (128 rows x 64 bf16, hi/lo)
    for (int idx = tid; idx < 1024; idx += 256) {
        int r = idx >> 3, ch = idx & 7;
        *(uint4*)(smem + SQH + r * 144 + ch * 16) = *(const uint4*)(Qh + (size_t)r * DD + ch * 8);
        *(uint4*)(smem + SQL + r * 144 + ch * 16) = *(const uint4*)(Ql + (size_t)r * DD + ch * 8);
    }
    __syncthreads();

    uint32_t qh[4][4], qlr[4][4];
    {
        const uint32_t qbase = smb + SQH + (uint32_t)((w * 16 + (lane & 15)) * 144 + (lane >> 4) * 16);
        #pragma unroll
        for (int kk = 0; kk < 4; kk++) {
            ldm_x4(qh[kk],  qbase + kk * 32);
            ldm_x4(qlr[kk], qbase + kk * 32 + (SQL - SQH));
        }
    }

    float o[8][4];
    #pragma unroll
    for (int j = 0; j < 8; j++)
        #pragma unroll
        for (int e = 0; e < 4; e++) o[j][e] = 0.f;
    float m0 = -1e30f, m1 = -1e30f, l0 = 0.f, l1 = 0.f;

    const int rg0  = q0 + w * 16 + (lane >> 2);     // my first global query row
    const int wmax = q0 + w * 16 + 15;              // warp's last query row

    for (int kt = 0; kt <= ktmax; kt++) {
        const int k0 = kt * 64;
        const int buf = kt & 1;

        if (kt < ktmax) {   // prefetch next tile into other buffer
            const int nk0 = (kt + 1) * 64;
            const uint32_t base = smb + SKV + (buf ^ 1) * 36864;
            for (int idx = tid; idx < 2048; idx += 256) {
                int arr = idx >> 9, rem = idx & 511, r = rem >> 3, ch = rem & 7;
                const __nv_bfloat16* src;
                if      (arr == 0) src = Kh + (size_t)(nk0 + r) * DD + ch * 8;
                else if (arr == 1) src = Kl + (size_t)(nk0 + r) * DD + ch * 8;
                else if (arr == 2) src = Vh + (size_t)(nk0 + r) * DD + ch * 8;
                else               src = Vl + (size_t)(nk0 + r) * DD + ch * 8;
                CPA(base + arr * 9216 + r * 144 + ch * 16, src);
            }
            CPC();
            CPW1();
        } else {
            CPW0();
        }
        __syncthreads();   // buf[kt&1] complete for all threads

        if (k0 <= wmax) {  // warp has at least one unmasked row in this tile
            const uint32_t kvb = smb + SKV + buf * 36864;
            const uint32_t kbase = kvb +
                (uint32_t)(((lane & 7) + ((lane >> 4) & 1) * 8) * 144 + ((lane >> 3) & 1) * 16);
            const uint32_t vbase = kvb + 18432 +
                (uint32_t)(((lane & 7) + ((lane >> 3) & 1) * 8) * 144 + ((lane >> 4) & 1) * 16);

            // ---- S = Q K^T ----
            float sacc[8][4];
            #pragma unroll
            for (int j = 0; j < 8; j++)
                #pragma unroll
                for (int e = 0; e < 4; e++) sacc[j][e] = 0.f;

            #pragma unroll
            for (int jj = 0; jj < 4; jj++) {
                #pragma unroll
                for (int kk = 0; kk < 4; kk++) {
                    uint32_t bhr[4], blr[4];
                    const uint32_t ka = kbase + (uint32_t)(jj * 16 * 144 + kk * 32);
                    ldm_x4(bhr, ka);
                    ldm_x4(blr, ka + 9216);
                    mma16816(sacc[2*jj],   qh[kk][0], qh[kk][1], qh[kk][2], qh[kk][3], bhr[0], bhr[1]);
                    mma16816(sacc[2*jj],   qh[kk][0], qh[kk][1], qh[kk][2], qh[kk][3], blr[0], blr[1]);
                    mma16816(sacc[2*jj],   qlr[kk][0], qlr[kk][1], qlr[kk][2], qlr[kk][3], bhr[0], bhr[1]);
                    mma16816(sacc[2*jj+1], qh[kk][0], qh[kk][1], qh[kk][2], qh[kk][3], bhr[2], bhr[3]);
                    mma16816(sacc[2*jj+1], qh[kk][0], qh[kk][1], qh[kk][2], qh[kk][3], blr[2], blr[3]);
                    mma16816(sacc[2*jj+1], qlr[kk][0], qlr[kk][1], qlr[kk][2], qlr[kk][3], bhr[2], bhr[3]);
                }
            }

            // ---- causal mask ----
            if (k0 + 63 > rg0) {
                #pragma unroll
                for (int j = 0; j < 8; j++) {
                    const int cbase = k0 + j * 8 + 2 * (lane & 3);
                    if (cbase     > rg0)     sacc[j][0] = -1e30f;
                    if (cbase + 1 > rg0)     sacc[j][1] = -1e30f;
                    if (cbase     > rg0 + 8) sacc[j][2] = -1e30f;
                    if (cbase + 1 > rg0 + 8) sacc[j][3] = -1e30f;
                }
            }

            // ---- online softmax (base-2) ----
            float mx0 = -1e30f, mx1 = -1e30f;
            #pragma unroll
            for (int j = 0; j < 8; j++) {
                mx0 = fmaxf(mx0, fmaxf(sacc[j][0], sacc[j][1]));
                mx1 = fmaxf(mx1, fmaxf(sacc[j][2], sacc[j][3]));
            }
            mx0 = fmaxf(mx0, __shfl_xor_sync(0xffffffffu, mx0, 1));
            mx0 = fmaxf(mx0, __shfl_xor_sync(0xffffffffu, mx0, 2));
            mx1 = fmaxf(mx1, __shfl_xor_sync(0xffffffffu, mx1, 1));
            mx1 = fmaxf(mx1, __shfl_xor_sync(0xffffffffu, mx1, 2));

            const float nm0 = fmaxf(m0, mx0);
            const float nm1 = fmaxf(m1, mx1);
            const float corr0 = exp2f(m0 - nm0);
            const float corr1 = exp2f(m1 - nm1);
            m0 = nm0; m1 = nm1;

            uint32_t ph[8][2], pl[8][2];
            float s0 = 0.f, s1 = 0.f;
            #pragma unroll
            for (int j = 0; j < 8; j++) {
                float p0 = exp2f(sacc[j][0] - nm0);
                float p1 = exp2f(sacc[j][1] - nm0);
                float p2 = exp2f(sacc[j][2] - nm1);
                float p3 = exp2f(sacc[j][3] - nm1);
                s0 += p0 + p1;
                s1 += p2 + p3;
                __nv_bfloat16 h0 = __float2bfloat16(p0), h1 = __float2bfloat16(p1);
                __nv_bfloat16 h2 = __float2bfloat16(p2), h3 = __float2bfloat16(p3);
                ph[j][0] = pack2bf(p0, p1);
                ph[j][1] = pack2bf(p2, p3);
                pl[j][0] = pack2bf(p0 - __bfloat162float(h0), p1 - __bfloat162float(h1));
                pl[j][1] = pack2bf(p2 - __bfloat162float(h2), p3 - __bfloat162float(h3));
            }
            s0 += __shfl_xor_sync(0xffffffffu, s0, 1);
            s0 += __shfl_xor_sync(0xffffffffu, s0, 2);
            s1 += __shfl_xor_sync(0xffffffffu, s1, 1);
            s1 += __shfl_xor_sync(0xffffffffu, s1, 2);
            l0 = l0 * corr0 + s0;
            l1 = l1 * corr1 + s1;

            #pragma unroll
            for (int j = 0; j < 8; j++) {
                o[j][0] *= corr0; o[j][1] *= corr0;
                o[j][2] *= corr1; o[j][3] *= corr1;
            }

            // ---- O += P V ----
            #pragma unroll
            for (int dd = 0; dd < 4; dd++) {
                #pragma unroll
                for (int kk = 0; kk < 4; kk++) {
                    uint32_t vh[4], vl[4];
                    const uint32_t va = vbase + (uint32_t)(kk * 16 * 144 + dd * 32);
                    ldm_x4_t(vh, va);
                    ldm_x4_t(vl, va + 9216);
                    mma16816(o[2*dd],   ph[2*kk][0], ph[2*kk][1], ph[2*kk+1][0], ph[2*kk+1][1], vh[0], vh[1]);
                    mma16816(o[2*dd],   ph[2*kk][0], ph[2*kk][1], ph[2*kk+1][0], ph[2*kk+1][1], vl[0], vl[1]);
                    mma16816(o[2*dd],   pl[2*kk][0], pl[2*kk][1], pl[2*kk+1][0], pl[2*kk+1][1], vh[0], vh[1]);
                    mma16816(o[2*dd+1], ph[2*kk][0], ph[2*kk][1], ph[2*kk+1][0], ph[2*kk+1][1], vh[2], vh[3]);
                    mma16816(o[2*dd+1], ph[2*kk][0], ph[2*kk][1], ph[2*kk+1][0], ph[2*kk+1][1], vl[2], vl[3]);
                    mma16816(o[2*dd+1], pl[2*kk][0], pl[2*kk][1], pl[2*kk+1][0], pl[2*kk+1][1], vh[2], vh[3]);
                }
            }
        }
        __syncthreads();   // all warps done reading buf[kt&1] before refill
    }

    // ---- epilogue: normalize and write [B,S,HID] ----
    const float inv0 = 1.f / l0;
    const float inv1 = 1.f / l1;
    float* dst0 = g_attn + ((size_t)b * SS + rg0) * HID + h * 64;
    float* dst1 = dst0 + (size_t)8 * HID;
    #pragma unroll
    for (int j = 0; j < 8; j++) {
        const int c = j * 8 + 2 * (lane & 3);
        dst0[c]     = o[j][0] * inv0;
        dst0[c + 1] = o[j][1] * inv0;
        dst1[c]     = o[j][2] * inv1;
        dst1[c + 1] = o[j][3] * inv1;
    }
}

// ---------------------------------------------------------------------------
// Kernel 3: output projection (vectorized LDS).  grid = BS/64, block = 256.
// ---------------------------------------------------------------------------
__global__ void oproj_kernel(const float* __restrict__ Wo,
                             const float* __restrict__ bo,
                             float* __restrict__ out) {
    __shared__ float As[64 * 68];    // [k][m], 16B-aligned rows
    __shared__ float Ws2[64 * 68];   // [k][n]
    const int m0  = blockIdx.x * 64;
    const int tid = threadIdx.x;
    const int ty  = tid >> 4, tx = tid & 15;

    float acc[4][4] = {};
    for (int kt = 0; kt < HID / 64; kt++) {
        __syncthreads();
        for (int idx = tid; idx < 64 * 64; idx += 256) {
            int r = idx >> 6, c = idx & 63;
            As [c * 68 + r] = g_attn[(size_t)(m0 + r) * HID + kt * 64 + c];
            Ws2[r * 68 + c] = Wo[(size_t)(kt * 64 + r) * DD + c];
        }
        __syncthreads();
        #pragma unroll 8
        for (int k = 0; k < 64; k++) {
            float4 a = *(const float4*)&As [k * 68 + ty * 4];
            float4 wv = *(const float4*)&Ws2[k * 68 + tx * 4];
            const float* ap = &a.x;
            const float* wp = &wv.x;
            #pragma unroll
            for (int i = 0; i < 4; i++)
                #pragma unroll
                for (int j = 0; j < 4; j++)
                    acc[i][j] = fmaf(ap[i], wp[j], acc[i][j]);
        }
    }
    #pragma unroll
    for (int i = 0; i < 4; i++)
        #pragma unroll
        for (int j = 0; j < 4; j++)
            out[(size_t)(m0 + ty * 4 + i) * DD + tx * 4 + j] = acc[i][j] + bo[tx * 4 + j];
}

// ---------------------------------------------------------------------------
extern "C" void kernel_launch(void* const* d_in, const int* in_sizes, int n_in,
                              void* d_out, int out_size) {
    (void)in_sizes; (void)n_in; (void)out_size;
    const float* x  = (const float*)d_in[0];
    const float* Wq = (const float*)d_in[1];
    const float* bq = (const float*)d_in[2];
    const float* Wk = (const float*)d_in[3];
    const float* bk = (const float*)d_in[4];
    const float* Wv = (const float*)d_in[5];
    const float* bv = (const float*)d_in[6];
    const float* Wo = (const float*)d_in[7];
    const float* bo = (const float*)d_in[8];
    float* out = (float*)d_out;

    prep_kernel<<<1024, 256>>>(x, Wq, Wk, Wv);

    qkv_mma_kernel<<<dim3(BS / 64, HID / 64, 3), 128>>>(bq, bk, bv);

    cudaFuncSetAttribute(attn_kernel, cudaFuncAttributeMaxDynamicSharedMemorySize, ATTN_SMEM);
    attn_kernel<<<dim3(SS / 128, HH, BB), 256, ATTN_SMEM>>>();

    oproj_kernel<<<BS / 64, 256>>>(Wo, bo, out);
}

// round 7
// speedup vs baseline: 3.2810x; 1.1459x over previous
#include <cuda_runtime.h>
#include <cuda_bf16.h>
#include <math.h>
#include <stdint.h>

#define BB 4
#define SS 2048
#define HH 16
#define DD 64
#define HID 1024
#define BS (BB*SS)
#define LOG2E 1.4426950408889634f

// ---------------- scratch (device globals: allocation-free rule) ------------
__device__ __nv_bfloat16 g_xh[BS*DD];          // x split
__device__ __nv_bfloat16 g_xl[BS*DD];
__device__ __nv_bfloat16 g_WTh[3*HID*DD];      // QKV W^T split: [which][n][k]
__device__ __nv_bfloat16 g_WTl[3*HID*DD];
__device__ __nv_bfloat16 g_WoTh[DD*HID];       // Wo^T split: [n][k]  n<64,k<1024
__device__ __nv_bfloat16 g_WoTl[DD*HID];
// Q pre-scaled by (1/sqrt(D)) * log2(e). All [b,h,s,d].
__device__ __nv_bfloat16 g_Qh[BB*HH*SS*DD];
__device__ __nv_bfloat16 g_Ql[BB*HH*SS*DD];
__device__ __nv_bfloat16 g_Kh[BB*HH*SS*DD];
__device__ __nv_bfloat16 g_Kl[BB*HH*SS*DD];
__device__ __nv_bfloat16 g_Vh[BB*HH*SS*DD];
__device__ __nv_bfloat16 g_Vl[BB*HH*SS*DD];
__device__ __nv_bfloat16 g_attnh[BS*HID];      // attn out split, [B,S,HID]
__device__ __nv_bfloat16 g_attnl[BS*HID];

// ---------------- helpers ---------------------------------------------------
static __device__ __forceinline__ uint32_t smem_u32(const void* p) {
    return (uint32_t)__cvta_generic_to_shared(p);
}
static __device__ __forceinline__ void ldm_x4(uint32_t* r, uint32_t addr) {
    asm volatile("ldmatrix.sync.aligned.m8n8.x4.shared.b16 {%0,%1,%2,%3}, [%4];"
                 : "=r"(r[0]), "=r"(r[1]), "=r"(r[2]), "=r"(r[3]) : "r"(addr));
}
static __device__ __forceinline__ void ldm_x4_t(uint32_t* r, uint32_t addr) {
    asm volatile("ldmatrix.sync.aligned.m8n8.x4.trans.shared.b16 {%0,%1,%2,%3}, [%4];"
                 : "=r"(r[0]), "=r"(r[1]), "=r"(r[2]), "=r"(r[3]) : "r"(addr));
}
static __device__ __forceinline__ void mma16816(float* c,
                                                uint32_t a0, uint32_t a1, uint32_t a2, uint32_t a3,
                                                uint32_t b0, uint32_t b1) {
    asm volatile(
        "mma.sync.aligned.m16n8k16.row.col.f32.bf16.bf16.f32 "
        "{%0,%1,%2,%3}, {%4,%5,%6,%7}, {%8,%9}, {%0,%1,%2,%3};"
        : "+f"(c[0]), "+f"(c[1]), "+f"(c[2]), "+f"(c[3])
        : "r"(a0), "r"(a1), "r"(a2), "r"(a3), "r"(b0), "r"(b1));
}
static __device__ __forceinline__ uint32_t pack2bf(float f0, float f1) {
    __nv_bfloat162 t = __halves2bfloat162(__float2bfloat16(f0), __float2bfloat16(f1));
    return *reinterpret_cast<uint32_t*>(&t);
}
#define CPA(dst, src) asm volatile("cp.async.ca.shared.global [%0], [%1], 16;" :: "r"(dst), "l"(src))
#define CPC()   asm volatile("cp.async.commit_group;" ::: "memory")
#define CPW1()  asm volatile("cp.async.wait_group 1;" ::: "memory")
#define CPW0()  asm volatile("cp.async.wait_group 0;" ::: "memory")

// ---------------------------------------------------------------------------
// Kernel 0: prep — split x, W^T (QKV) and Wo^T to bf16 hi/lo.
// ---------------------------------------------------------------------------
#define NX (BS*DD)          // 524288
#define NW (3*HID*DD)       // 196608
#define NWO (DD*HID)        // 65536
__global__ void prep_kernel(const float* __restrict__ x,
                            const float* __restrict__ Wq,
                            const float* __restrict__ Wk,
                            const float* __restrict__ Wv,
                            const float* __restrict__ Wo) {
    for (int idx = blockIdx.x * blockDim.x + threadIdx.x; idx < NX + NW + NWO;
         idx += gridDim.x * blockDim.x) {
        if (idx < NX) {
            float f = x[idx];
            __nv_bfloat16 hi = __float2bfloat16(f);
            g_xh[idx] = hi;
            g_xl[idx] = __float2bfloat16(f - __bfloat162float(hi));
        } else if (idx < NX + NW) {
            int r = idx - NX;
            int which = r >> 16;
            int t = r & 65535;
            int n = t >> 6, k = t & 63;
            const float* W = (which == 0) ? Wq : (which == 1) ? Wk : Wv;
            float f = W[k * HID + n];
            __nv_bfloat16 hi = __float2bfloat16(f);
            g_WTh[r] = hi;
            g_WTl[r] = __float2bfloat16(f - __bfloat162float(hi));
        } else {
            int r = idx - NX - NW;          // r = n*1024 + k
            int n = r >> 10, k = r & 1023;
            float f = Wo[k * DD + n];
            __nv_bfloat16 hi = __float2bfloat16(f);
            g_WoTh[r] = hi;
            g_WoTl[r] = __float2bfloat16(f - __bfloat162float(hi));
        }
    }
}

// ---------------------------------------------------------------------------
// Kernel 1: QKV projection via HMMA (bf16 hi/lo, 3 combos).
// grid = (BS/64, HID/64, 3), block = 128 (4 warps, each 16 rows x 64 cols)
// ---------------------------------------------------------------------------
#define QKV_XH 0
#define QKV_XL 9216
#define QKV_WH 18432
#define QKV_WL 27648
__global__ void __launch_bounds__(128) qkv_mma_kernel(const float* __restrict__ bq,
                                                      const float* __restrict__ bk,
                                                      const float* __restrict__ bv) {
    __shared__ __align__(16) char smem[4 * 9216];
    const uint32_t smb = smem_u32(smem);

    const int m0    = blockIdx.x * 64;
    const int h     = blockIdx.y;
    const int which = blockIdx.z;
    const int c0    = h * 64;

    const int tid  = threadIdx.x;
    const int w    = tid >> 5;
    const int lane = tid & 31;

    const float* bp = (which == 0) ? bq : (which == 1) ? bk : bv;

    for (int idx = tid; idx < 2048; idx += 128) {
        int arr = idx >> 9, rem = idx & 511, r = rem >> 3, ch = rem & 7;
        const __nv_bfloat16* src;
        if      (arr == 0) src = g_xh  + (size_t)(m0 + r) * DD + ch * 8;
        else if (arr == 1) src = g_xl  + (size_t)(m0 + r) * DD + ch * 8;
        else if (arr == 2) src = g_WTh + (size_t)which * HID * DD + (size_t)(c0 + r) * DD + ch * 8;
        else               src = g_WTl + (size_t)which * HID * DD + (size_t)(c0 + r) * DD + ch * 8;
        *(uint4*)(smem + arr * 9216 + r * 144 + ch * 16) = *(const uint4*)src;
    }
    __syncthreads();

    uint32_t ah[4][4], al[4][4];
    {
        const uint32_t abase = smb + QKV_XH + (uint32_t)((w * 16 + (lane & 15)) * 144 + (lane >> 4) * 16);
        #pragma unroll
        for (int kk = 0; kk < 4; kk++) {
            ldm_x4(ah[kk], abase + kk * 32);
            ldm_x4(al[kk], abase + kk * 32 + (QKV_XL - QKV_XH));
        }
    }
    const uint32_t bbase = smb + QKV_WH +
        (uint32_t)(((lane & 7) + ((lane >> 4) & 1) * 8) * 144 + ((lane >> 3) & 1) * 16);

    float sacc[8][4];
    #pragma unroll
    for (int j = 0; j < 8; j++)
        #pragma unroll
        for (int e = 0; e < 4; e++) sacc[j][e] = 0.f;

    #pragma unroll
    for (int jj = 0; jj < 4; jj++) {
        #pragma unroll
        for (int kk = 0; kk < 4; kk++) {
            uint32_t bhr[4], blr[4];
            const uint32_t ba = bbase + (uint32_t)(jj * 16 * 144 + kk * 32);
            ldm_x4(bhr, ba);
            ldm_x4(blr, ba + (QKV_WL - QKV_WH));
            mma16816(sacc[2*jj],   ah[kk][0], ah[kk][1], ah[kk][2], ah[kk][3], bhr[0], bhr[1]);
            mma16816(sacc[2*jj],   ah[kk][0], ah[kk][1], ah[kk][2], ah[kk][3], blr[0], blr[1]);
            mma16816(sacc[2*jj],   al[kk][0], al[kk][1], al[kk][2], al[kk][3], bhr[0], bhr[1]);
            mma16816(sacc[2*jj+1], ah[kk][0], ah[kk][1], ah[kk][2], ah[kk][3], bhr[2], bhr[3]);
            mma16816(sacc[2*jj+1], ah[kk][0], ah[kk][1], ah[kk][2], ah[kk][3], blr[2], blr[3]);
            mma16816(sacc[2*jj+1], al[kk][0], al[kk][1], al[kk][2], al[kk][3], bhr[2], bhr[3]);
        }
    }

    __nv_bfloat16* Ah = (which == 0) ? g_Qh : (which == 1) ? g_Kh : g_Vh;
    __nv_bfloat16* Al = (which == 0) ? g_Ql : (which == 1) ? g_Kl : g_Vl;
    const float scale = (which == 0) ? 0.125f * LOG2E : 1.0f;
    const int b   = m0 >> 11;
    const int ss0 = m0 & 2047;
    const int r0  = w * 16 + (lane >> 2);
    const size_t base0 = (((size_t)b * HH + h) * SS + (ss0 + r0)) * DD;
    const size_t base1 = base0 + (size_t)8 * DD;
    #pragma unroll
    for (int j = 0; j < 8; j++) {
        const int c = j * 8 + 2 * (lane & 3);
        {
            float v0 = (sacc[j][0] + bp[c0 + c]) * scale;
            float v1 = (sacc[j][1] + bp[c0 + c + 1]) * scale;
            __nv_bfloat16 h0 = __float2bfloat16(v0), h1 = __float2bfloat16(v1);
            *(uint32_t*)&Ah[base0 + c] = pack2bf(v0, v1);
            *(uint32_t*)&Al[base0 + c] = pack2bf(v0 - __bfloat162float(h0), v1 - __bfloat162float(h1));
        }
        {
            float v0 = (sacc[j][2] + bp[c0 + c]) * scale;
            float v1 = (sacc[j][3] + bp[c0 + c + 1]) * scale;
            __nv_bfloat16 h0 = __float2bfloat16(v0), h1 = __float2bfloat16(v1);
            *(uint32_t*)&Ah[base1 + c] = pack2bf(v0, v1);
            *(uint32_t*)&Al[base1 + c] = pack2bf(v0 - __bfloat162float(h0), v1 - __bfloat162float(h1));
        }
    }
}

// ---------------------------------------------------------------------------
// Kernel 2: causal flash attention (HMMA hi/lo), Q-tile 128, 8 warps,
// double-buffered cp.async K/V.  grid = (S/128, H, B), block = 256.
// ---------------------------------------------------------------------------
#define SQH 0
#define SQL 18432
#define SKV 36864            // two buffers of 36864 (KH,KL,VH,VL @ 9216 each)
#define ATTN_SMEM (36864 + 2*36864)   // 110592

__global__ void __launch_bounds__(256) attn_kernel() {
    extern __shared__ char smem[];
    const uint32_t smb = smem_u32(smem);

    const int qt = blockIdx.x;
    const int h  = blockIdx.y;
    const int b  = blockIdx.z;
    const int q0 = qt * 128;

    const int tid  = threadIdx.x;
    const int w    = tid >> 5;
    const int lane = tid & 31;

    const size_t bh = (size_t)b * HH + h;
    const __nv_bfloat16* Qh = g_Qh + (bh * SS + q0) * DD;
    const __nv_bfloat16* Ql = g_Ql + (bh * SS + q0) * DD;
    const __nv_bfloat16* Kh = g_Kh + bh * SS * DD;
    const __nv_bfloat16* Kl = g_Kl + bh * SS * DD;
    const __nv_bfloat16* Vh = g_Vh + bh * SS * DD;
    const __nv_bfloat16* Vl = g_Vl + bh * SS * DD;

    const int ktmax = 2 * qt + 1;

    {
        const uint32_t base = smb + SKV;
        for (int idx = tid; idx < 2048; idx += 256) {
            int arr = idx >> 9, rem = idx & 511, r = rem >> 3, ch = rem & 7;
            const __nv_bfloat16* src;
            if      (arr == 0) src = Kh + (size_t)r * DD + ch * 8;
            else if (arr == 1) src = Kl + (size_t)r * DD + ch * 8;
            else if (arr == 2) src = Vh + (size_t)r * DD + ch * 8;
            else               src = Vl + (size_t)r * DD + ch * 8;
            CPA(base + arr * 9216 + r * 144 + ch * 16, src);
        }
        CPC();
    }

    for (int idx = tid; idx < 1024; idx += 256) {
        int r = idx >> 3, ch = idx & 7;
        *(uint4*)(smem + SQH + r * 144 + ch * 16) = *(const uint4*)(Qh + (size_t)r * DD + ch * 8);
        *(uint4*)(smem + SQL + r * 144 + ch * 16) = *(const uint4*)(Ql + (size_t)r * DD + ch * 8);
    }
    __syncthreads();

    uint32_t qh[4][4], qlr[4][4];
    {
        const uint32_t qbase = smb + SQH + (uint32_t)((w * 16 + (lane & 15)) * 144 + (lane >> 4) * 16);
        #pragma unroll
        for (int kk = 0; kk < 4; kk++) {
            ldm_x4(qh[kk],  qbase + kk * 32);
            ldm_x4(qlr[kk], qbase + kk * 32 + (SQL - SQH));
        }
    }

    float o[8][4];
    #pragma unroll
    for (int j = 0; j < 8; j++)
        #pragma unroll
        for (int e = 0; e < 4; e++) o[j][e] = 0.f;
    float m0 = -1e30f, m1 = -1e30f, l0 = 0.f, l1 = 0.f;

    const int rg0  = q0 + w * 16 + (lane >> 2);
    const int wmax = q0 + w * 16 + 15;

    for (int kt = 0; kt <= ktmax; kt++) {
        const int k0 = kt * 64;
        const int buf = kt & 1;

        if (kt < ktmax) {
            const int nk0 = (kt + 1) * 64;
            const uint32_t base = smb + SKV + (buf ^ 1) * 36864;
            for (int idx = tid; idx < 2048; idx += 256) {
                int arr = idx >> 9, rem = idx & 511, r = rem >> 3, ch = rem & 7;
                const __nv_bfloat16* src;
                if      (arr == 0) src = Kh + (size_t)(nk0 + r) * DD + ch * 8;
                else if (arr == 1) src = Kl + (size_t)(nk0 + r) * DD + ch * 8;
                else if (arr == 2) src = Vh + (size_t)(nk0 + r) * DD + ch * 8;
                else               src = Vl + (size_t)(nk0 + r) * DD + ch * 8;
                CPA(base + arr * 9216 + r * 144 + ch * 16, src);
            }
            CPC();
            CPW1();
        } else {
            CPW0();
        }
        __syncthreads();

        if (k0 <= wmax) {
            const uint32_t kvb = smb + SKV + buf * 36864;
            const uint32_t kbase = kvb +
                (uint32_t)(((lane & 7) + ((lane >> 4) & 1) * 8) * 144 + ((lane >> 3) & 1) * 16);
            const uint32_t vbase = kvb + 18432 +
                (uint32_t)(((lane & 7) + ((lane >> 3) & 1) * 8) * 144 + ((lane >> 4) & 1) * 16);

            float sacc[8][4];
            #pragma unroll
            for (int j = 0; j < 8; j++)
                #pragma unroll
                for (int e = 0; e < 4; e++) sacc[j][e] = 0.f;

            #pragma unroll
            for (int jj = 0; jj < 4; jj++) {
                #pragma unroll
                for (int kk = 0; kk < 4; kk++) {
                    uint32_t bhr[4], blr[4];
                    const uint32_t ka = kbase + (uint32_t)(jj * 16 * 144 + kk * 32);
                    ldm_x4(bhr, ka);
                    ldm_x4(blr, ka + 9216);
                    mma16816(sacc[2*jj],   qh[kk][0], qh[kk][1], qh[kk][2], qh[kk][3], bhr[0], bhr[1]);
                    mma16816(sacc[2*jj],   qh[kk][0], qh[kk][1], qh[kk][2], qh[kk][3], blr[0], blr[1]);
                    mma16816(sacc[2*jj],   qlr[kk][0], qlr[kk][1], qlr[kk][2], qlr[kk][3], bhr[0], bhr[1]);
                    mma16816(sacc[2*jj+1], qh[kk][0], qh[kk][1], qh[kk][2], qh[kk][3], bhr[2], bhr[3]);
                    mma16816(sacc[2*jj+1], qh[kk][0], qh[kk][1], qh[kk][2], qh[kk][3], blr[2], blr[3]);
                    mma16816(sacc[2*jj+1], qlr[kk][0], qlr[kk][1], qlr[kk][2], qlr[kk][3], bhr[2], bhr[3]);
                }
            }

            if (k0 + 63 > rg0) {
                #pragma unroll
                for (int j = 0; j < 8; j++) {
                    const int cbase = k0 + j * 8 + 2 * (lane & 3);
                    if (cbase     > rg0)     sacc[j][0] = -1e30f;
                    if (cbase + 1 > rg0)     sacc[j][1] = -1e30f;
                    if (cbase     > rg0 + 8) sacc[j][2] = -1e30f;
                    if (cbase + 1 > rg0 + 8) sacc[j][3] = -1e30f;
                }
            }

            float mx0 = -1e30f, mx1 = -1e30f;
            #pragma unroll
            for (int j = 0; j < 8; j++) {
                mx0 = fmaxf(mx0, fmaxf(sacc[j][0], sacc[j][1]));
                mx1 = fmaxf(mx1, fmaxf(sacc[j][2], sacc[j][3]));
            }
            mx0 = fmaxf(mx0, __shfl_xor_sync(0xffffffffu, mx0, 1));
            mx0 = fmaxf(mx0, __shfl_xor_sync(0xffffffffu, mx0, 2));
            mx1 = fmaxf(mx1, __shfl_xor_sync(0xffffffffu, mx1, 1));
            mx1 = fmaxf(mx1, __shfl_xor_sync(0xffffffffu, mx1, 2));

            const float nm0 = fmaxf(m0, mx0);
            const float nm1 = fmaxf(m1, mx1);
            const float corr0 = exp2f(m0 - nm0);
            const float corr1 = exp2f(m1 - nm1);
            m0 = nm0; m1 = nm1;

            uint32_t ph[8][2], pl[8][2];
            float s0 = 0.f, s1 = 0.f;
            #pragma unroll
            for (int j = 0; j < 8; j++) {
                float p0 = exp2f(sacc[j][0] - nm0);
                float p1 = exp2f(sacc[j][1] - nm0);
                float p2 = exp2f(sacc[j][2] - nm1);
                float p3 = exp2f(sacc[j][3] - nm1);
                s0 += p0 + p1;
                s1 += p2 + p3;
                __nv_bfloat16 h0 = __float2bfloat16(p0), h1 = __float2bfloat16(p1);
                __nv_bfloat16 h2 = __float2bfloat16(p2), h3 = __float2bfloat16(p3);
                ph[j][0] = pack2bf(p0, p1);
                ph[j][1] = pack2bf(p2, p3);
                pl[j][0] = pack2bf(p0 - __bfloat162float(h0), p1 - __bfloat162float(h1));
                pl[j][1] = pack2bf(p2 - __bfloat162float(h2), p3 - __bfloat162float(h3));
            }
            s0 += __shfl_xor_sync(0xffffffffu, s0, 1);
            s0 += __shfl_xor_sync(0xffffffffu, s0, 2);
            s1 += __shfl_xor_sync(0xffffffffu, s1, 1);
            s1 += __shfl_xor_sync(0xffffffffu, s1, 2);
            l0 = l0 * corr0 + s0;
            l1 = l1 * corr1 + s1;

            #pragma unroll
            for (int j = 0; j < 8; j++) {
                o[j][0] *= corr0; o[j][1] *= corr0;
                o[j][2] *= corr1; o[j][3] *= corr1;
            }

            #pragma unroll
            for (int dd = 0; dd < 4; dd++) {
                #pragma unroll
                for (int kk = 0; kk < 4; kk++) {
                    uint32_t vh[4], vl[4];
                    const uint32_t va = vbase + (uint32_t)(kk * 16 * 144 + dd * 32);
                    ldm_x4_t(vh, va);
                    ldm_x4_t(vl, va + 9216);
                    mma16816(o[2*dd],   ph[2*kk][0], ph[2*kk][1], ph[2*kk+1][0], ph[2*kk+1][1], vh[0], vh[1]);
                    mma16816(o[2*dd],   ph[2*kk][0], ph[2*kk][1], ph[2*kk+1][0], ph[2*kk+1][1], vl[0], vl[1]);
                    mma16816(o[2*dd],   pl[2*kk][0], pl[2*kk][1], pl[2*kk+1][0], pl[2*kk+1][1], vh[0], vh[1]);
                    mma16816(o[2*dd+1], ph[2*kk][0], ph[2*kk][1], ph[2*kk+1][0], ph[2*kk+1][1], vh[2], vh[3]);
                    mma16816(o[2*dd+1], ph[2*kk][0], ph[2*kk][1], ph[2*kk+1][0], ph[2*kk+1][1], vl[2], vl[3]);
                    mma16816(o[2*dd+1], pl[2*kk][0], pl[2*kk][1], pl[2*kk+1][0], pl[2*kk+1][1], vh[2], vh[3]);
                }
            }
        }
        __syncthreads();
    }

    // ---- epilogue: normalize, split hi/lo, write bf16 [B,S,HID] ----
    const float inv0 = 1.f / l0;
    const float inv1 = 1.f / l1;
    const size_t db0 = ((size_t)b * SS + rg0) * HID + h * 64;
    const size_t db1 = db0 + (size_t)8 * HID;
    #pragma unroll
    for (int j = 0; j < 8; j++) {
        const int c = j * 8 + 2 * (lane & 3);
        {
            float v0 = o[j][0] * inv0, v1 = o[j][1] * inv0;
            __nv_bfloat16 h0 = __float2bfloat16(v0), h1 = __float2bfloat16(v1);
            *(uint32_t*)&g_attnh[db0 + c] = pack2bf(v0, v1);
            *(uint32_t*)&g_attnl[db0 + c] = pack2bf(v0 - __bfloat162float(h0), v1 - __bfloat162float(h1));
        }
        {
            float v0 = o[j][2] * inv1, v1 = o[j][3] * inv1;
            __nv_bfloat16 h0 = __float2bfloat16(v0), h1 = __float2bfloat16(v1);
            *(uint32_t*)&g_attnh[db1 + c] = pack2bf(v0, v1);
            *(uint32_t*)&g_attnl[db1 + c] = pack2bf(v0 - __bfloat162float(h0), v1 - __bfloat162float(h1));
        }
    }
}

// ---------------------------------------------------------------------------
// Kernel 3: output projection via HMMA.  Y[8192,64] = A[8192,1024] @ Wo + bo.
// grid = BS/64, block = 128 (4 warps).  K=1024 in 16 double-buffered steps.
// ---------------------------------------------------------------------------
// smem per buffer: AH,AL,WH,WL @ 9216 each = 36864; two buffers = 73728.
#define OPROJ_SMEM (2 * 36864)
__global__ void __launch_bounds__(128) oproj_mma_kernel(const float* __restrict__ bo,
                                                        float* __restrict__ out) {
    extern __shared__ char smem[];
    const uint32_t smb = smem_u32(smem);

    const int m0  = blockIdx.x * 64;
    const int tid = threadIdx.x;
    const int w   = tid >> 5;
    const int lane = tid & 31;

    // prefetch k-step 0 into buffer 0
    {
        const uint32_t base = smb;
        for (int idx = tid; idx < 2048; idx += 128) {
            int arr = idx >> 9, rem = idx & 511, r = rem >> 3, ch = rem & 7;
            const __nv_bfloat16* src;
            if      (arr == 0) src = g_attnh + (size_t)(m0 + r) * HID + ch * 8;
            else if (arr == 1) src = g_attnl + (size_t)(m0 + r) * HID + ch * 8;
            else if (arr == 2) src = g_WoTh + (size_t)r * HID + ch * 8;
            else               src = g_WoTl + (size_t)r * HID + ch * 8;
            CPA(base + arr * 9216 + r * 144 + ch * 16, src);
        }
        CPC();
    }

    float sacc[8][4];
    #pragma unroll
    for (int j = 0; j < 8; j++)
        #pragma unroll
        for (int e = 0; e < 4; e++) sacc[j][e] = 0.f;

    const uint32_t a_off = (uint32_t)((w * 16 + (lane & 15)) * 144 + (lane >> 4) * 16);
    const uint32_t b_off = (uint32_t)(((lane & 7) + ((lane >> 4) & 1) * 8) * 144 + ((lane >> 3) & 1) * 16);

    for (int kt = 0; kt < 16; kt++) {
        const int buf = kt & 1;
        if (kt < 15) {
            const int nk0 = (kt + 1) * 64;
            const uint32_t base = smb + (buf ^ 1) * 36864;
            for (int idx = tid; idx < 2048; idx += 128) {
                int arr = idx >> 9, rem = idx & 511, r = rem >> 3, ch = rem & 7;
                const __nv_bfloat16* src;
                if      (arr == 0) src = g_attnh + (size_t)(m0 + r) * HID + nk0 + ch * 8;
                else if (arr == 1) src = g_attnl + (size_t)(m0 + r) * HID + nk0 + ch * 8;
                else if (arr == 2) src = g_WoTh + (size_t)r * HID + nk0 + ch * 8;
                else               src = g_WoTl + (size_t)r * HID + nk0 + ch * 8;
                CPA(base + arr * 9216 + r * 144 + ch * 16, src);
            }
            CPC();
            CPW1();
        } else {
            CPW0();
        }
        __syncthreads();

        const uint32_t bb = smb + buf * 36864;
        const uint32_t abase = bb + a_off;
        const uint32_t bbase = bb + 18432 + b_off;

        #pragma unroll
        for (int kk = 0; kk < 4; kk++) {
            uint32_t ah[4], al[4];
            ldm_x4(ah, abase + kk * 32);
            ldm_x4(al, abase + kk * 32 + 9216);
            #pragma unroll
            for (int jj = 0; jj < 4; jj++) {
                uint32_t bhr[4], blr[4];
                const uint32_t ba = bbase + (uint32_t)(jj * 16 * 144 + kk * 32);
                ldm_x4(bhr, ba);
                ldm_x4(blr, ba + 9216);
                mma16816(sacc[2*jj],   ah[0], ah[1], ah[2], ah[3], bhr[0], bhr[1]);
                mma16816(sacc[2*jj],   ah[0], ah[1], ah[2], ah[3], blr[0], blr[1]);
                mma16816(sacc[2*jj],   al[0], al[1], al[2], al[3], bhr[0], bhr[1]);
                mma16816(sacc[2*jj+1], ah[0], ah[1], ah[2], ah[3], bhr[2], bhr[3]);
                mma16816(sacc[2*jj+1], ah[0], ah[1], ah[2], ah[3], blr[2], blr[3]);
                mma16816(sacc[2*jj+1], al[0], al[1], al[2], al[3], bhr[2], bhr[3]);
            }
        }
        __syncthreads();
    }

    // epilogue: + bias, write fp32 out
    const int r0 = w * 16 + (lane >> 2);
    #pragma unroll
    for (int j = 0; j < 8; j++) {
        const int c = j * 8 + 2 * (lane & 3);
        out[(size_t)(m0 + r0) * DD + c]     = sacc[j][0] + bo[c];
        out[(size_t)(m0 + r0) * DD + c + 1] = sacc[j][1] + bo[c + 1];
        out[(size_t)(m0 + r0 + 8) * DD + c]     = sacc[j][2] + bo[c];
        out[(size_t)(m0 + r0 + 8) * DD + c + 1] = sacc[j][3] + bo[c + 1];
    }
}

// ---------------------------------------------------------------------------
extern "C" void kernel_launch(void* const* d_in, const int* in_sizes, int n_in,
                              void* d_out, int out_size) {
    (void)in_sizes; (void)n_in; (void)out_size;
    const float* x  = (const float*)d_in[0];
    const float* Wq = (const float*)d_in[1];
    const float* bq = (const float*)d_in[2];
    const float* Wk = (const float*)d_in[3];
    const float* bk = (const float*)d_in[4];
    const float* Wv = (const float*)d_in[5];
    const float* bv = (const float*)d_in[6];
    const float* Wo = (const float*)d_in[7];
    const float* bo = (const float*)d_in[8];
    float* out = (float*)d_out;

    prep_kernel<<<1024, 256>>>(x, Wq, Wk, Wv, Wo);

    qkv_mma_kernel<<<dim3(BS / 64, HID / 64, 3), 128>>>(bq, bk, bv);

    cudaFuncSetAttribute(attn_kernel, cudaFuncAttributeMaxDynamicSharedMemorySize, ATTN_SMEM);
    attn_kernel<<<dim3(SS / 128, HH, BB), 256, ATTN_SMEM>>>();

    cudaFuncSetAttribute(oproj_mma_kernel, cudaFuncAttributeMaxDynamicSharedMemorySize, OPROJ_SMEM);
    oproj_mma_kernel<<<BS / 64, 128, OPROJ_SMEM>>>(bo, out);
}

// round 8
// speedup vs baseline: 5.1501x; 1.5697x over previous
#include <cuda_runtime.h>
#include <cuda_fp16.h>
#include <math.h>
#include <stdint.h>

#define BB 4
#define SS 2048
#define HH 16
#define DD 64
#define HID 1024
#define BS (BB*SS)
#define LOG2E 1.4426950408889634f

// ---------------- scratch (device globals: allocation-free rule) ------------
__device__ __half g_xh[BS*DD];           // x split (compensated operand)
__device__ __half g_xl[BS*DD];
__device__ __half g_WTh[3*HID*DD];       // QKV W^T hi only: [which][n][k]
__device__ __half g_WoTh[DD*HID];        // Wo^T hi only: [n][k]
// Q pre-scaled by (1/sqrt(D)) * log2(e). All [b,h,s,d].
__device__ __half g_Qh[BB*HH*SS*DD];
__device__ __half g_Ql[BB*HH*SS*DD];
__device__ __half g_Kh[BB*HH*SS*DD];     // hi only (uncompensated)
__device__ __half g_Vh[BB*HH*SS*DD];     // hi only
__device__ __half g_attnh[BS*HID];       // attn out split, [B,S,HID]
__device__ __half g_attnl[BS*HID];

// ---------------- helpers ---------------------------------------------------
static __device__ __forceinline__ uint32_t smem_u32(const void* p) {
    return (uint32_t)__cvta_generic_to_shared(p);
}
static __device__ __forceinline__ void ldm_x4(uint32_t* r, uint32_t addr) {
    asm volatile("ldmatrix.sync.aligned.m8n8.x4.shared.b16 {%0,%1,%2,%3}, [%4];"
                 : "=r"(r[0]), "=r"(r[1]), "=r"(r[2]), "=r"(r[3]) : "r"(addr));
}
static __device__ __forceinline__ void ldm_x4_t(uint32_t* r, uint32_t addr) {
    asm volatile("ldmatrix.sync.aligned.m8n8.x4.trans.shared.b16 {%0,%1,%2,%3}, [%4];"
                 : "=r"(r[0]), "=r"(r[1]), "=r"(r[2]), "=r"(r[3]) : "r"(addr));
}
static __device__ __forceinline__ void mma16816(float* c,
                                                uint32_t a0, uint32_t a1, uint32_t a2, uint32_t a3,
                                                uint32_t b0, uint32_t b1) {
    asm volatile(
        "mma.sync.aligned.m16n8k16.row.col.f32.f16.f16.f32 "
        "{%0,%1,%2,%3}, {%4,%5,%6,%7}, {%8,%9}, {%0,%1,%2,%3};"
        : "+f"(c[0]), "+f"(c[1]), "+f"(c[2]), "+f"(c[3])
        : "r"(a0), "r"(a1), "r"(a2), "r"(a3), "r"(b0), "r"(b1));
}
static __device__ __forceinline__ uint32_t pack2h(float f0, float f1) {
    __half2 t = __halves2half2(__float2half_rn(f0), __float2half_rn(f1));
    return *reinterpret_cast<uint32_t*>(&t);
}
static __device__ __forceinline__ float ex2(float x) {
    float y;
    asm("ex2.approx.ftz.f32 %0, %1;" : "=f"(y) : "f"(x));
    return y;
}
#define CPA(dst, src) asm volatile("cp.async.ca.shared.global [%0], [%1], 16;" :: "r"(dst), "l"(src))
#define CPC()   asm volatile("cp.async.commit_group;" ::: "memory")
#define CPW1()  asm volatile("cp.async.wait_group 1;" ::: "memory")
#define CPW0()  asm volatile("cp.async.wait_group 0;" ::: "memory")

// ---------------------------------------------------------------------------
// Kernel 0: prep — split x to fp16 hi/lo; W^T, Wo^T to fp16 hi.
// ---------------------------------------------------------------------------
#define NX (BS*DD)          // 524288
#define NW (3*HID*DD)       // 196608
#define NWO (DD*HID)        // 65536
__global__ void prep_kernel(const float* __restrict__ x,
                            const float* __restrict__ Wq,
                            const float* __restrict__ Wk,
                            const float* __restrict__ Wv,
                            const float* __restrict__ Wo) {
    for (int idx = blockIdx.x * blockDim.x + threadIdx.x; idx < NX + NW + NWO;
         idx += gridDim.x * blockDim.x) {
        if (idx < NX) {
            float f = x[idx];
            __half hi = __float2half_rn(f);
            g_xh[idx] = hi;
            g_xl[idx] = __float2half_rn(f - __half2float(hi));
        } else if (idx < NX + NW) {
            int r = idx - NX;
            int which = r >> 16;
            int t = r & 65535;
            int n = t >> 6, k = t & 63;
            const float* W = (which == 0) ? Wq : (which == 1) ? Wk : Wv;
            g_WTh[r] = __float2half_rn(W[k * HID + n]);
        } else {
            int r = idx - NX - NW;          // r = n*1024 + k
            int n = r >> 10, k = r & 1023;
            g_WoTh[r] = __float2half_rn(Wo[k * DD + n]);
        }
    }
}

// ---------------------------------------------------------------------------
// Kernel 1: QKV projection via HMMA: (xh+xl) @ Wh.
// grid = (BS/64, HID/64, 3), block = 128.
// ---------------------------------------------------------------------------
__global__ void __launch_bounds__(128) qkv_mma_kernel(const float* __restrict__ bq,
                                                      const float* __restrict__ bk,
                                                      const float* __restrict__ bv) {
    __shared__ __align__(16) char smem[3 * 9216];   // XH, XL, WH
    const uint32_t smb = smem_u32(smem);

    const int m0    = blockIdx.x * 64;
    const int h     = blockIdx.y;
    const int which = blockIdx.z;
    const int c0    = h * 64;

    const int tid  = threadIdx.x;
    const int w    = tid >> 5;
    const int lane = tid & 31;

    const float* bp = (which == 0) ? bq : (which == 1) ? bk : bv;

    for (int idx = tid; idx < 1536; idx += 128) {
        int arr = idx >> 9, rem = idx & 511, r = rem >> 3, ch = rem & 7;
        const __half* src;
        if      (arr == 0) src = g_xh  + (size_t)(m0 + r) * DD + ch * 8;
        else if (arr == 1) src = g_xl  + (size_t)(m0 + r) * DD + ch * 8;
        else               src = g_WTh + (size_t)which * HID * DD + (size_t)(c0 + r) * DD + ch * 8;
        *(uint4*)(smem + arr * 9216 + r * 144 + ch * 16) = *(const uint4*)src;
    }
    __syncthreads();

    uint32_t ah[4][4], al[4][4];
    {
        const uint32_t abase = smb + (uint32_t)((w * 16 + (lane & 15)) * 144 + (lane >> 4) * 16);
        #pragma unroll
        for (int kk = 0; kk < 4; kk++) {
            ldm_x4(ah[kk], abase + kk * 32);
            ldm_x4(al[kk], abase + kk * 32 + 9216);
        }
    }
    const uint32_t bbase = smb + 18432 +
        (uint32_t)(((lane & 7) + ((lane >> 4) & 1) * 8) * 144 + ((lane >> 3) & 1) * 16);

    float sacc[8][4];
    #pragma unroll
    for (int j = 0; j < 8; j++)
        #pragma unroll
        for (int e = 0; e < 4; e++) sacc[j][e] = 0.f;

    #pragma unroll
    for (int jj = 0; jj < 4; jj++) {
        #pragma unroll
        for (int kk = 0; kk < 4; kk++) {
            uint32_t bhr[4];
            ldm_x4(bhr, bbase + (uint32_t)(jj * 16 * 144 + kk * 32));
            mma16816(sacc[2*jj],   ah[kk][0], ah[kk][1], ah[kk][2], ah[kk][3], bhr[0], bhr[1]);
            mma16816(sacc[2*jj],   al[kk][0], al[kk][1], al[kk][2], al[kk][3], bhr[0], bhr[1]);
            mma16816(sacc[2*jj+1], ah[kk][0], ah[kk][1], ah[kk][2], ah[kk][3], bhr[2], bhr[3]);
            mma16816(sacc[2*jj+1], al[kk][0], al[kk][1], al[kk][2], al[kk][3], bhr[2], bhr[3]);
        }
    }

    const float scale = (which == 0) ? 0.125f * LOG2E : 1.0f;
    const int b   = m0 >> 11;
    const int ss0 = m0 & 2047;
    const int r0  = w * 16 + (lane >> 2);
    const size_t base0 = (((size_t)b * HH + h) * SS + (ss0 + r0)) * DD;
    const size_t base1 = base0 + (size_t)8 * DD;

    if (which == 0) {   // Q: hi + lo (compensated side of QK^T)
        #pragma unroll
        for (int j = 0; j < 8; j++) {
            const int c = j * 8 + 2 * (lane & 3);
            {
                float v0 = (sacc[j][0] + bp[c0 + c]) * scale;
                float v1 = (sacc[j][1] + bp[c0 + c + 1]) * scale;
                __half h0 = __float2half_rn(v0), h1 = __float2half_rn(v1);
                *(uint32_t*)&g_Qh[base0 + c] = pack2h(v0, v1);
                *(uint32_t*)&g_Ql[base0 + c] = pack2h(v0 - __half2float(h0), v1 - __half2float(h1));
            }
            {
                float v0 = (sacc[j][2] + bp[c0 + c]) * scale;
                float v1 = (sacc[j][3] + bp[c0 + c + 1]) * scale;
                __half h0 = __float2half_rn(v0), h1 = __float2half_rn(v1);
                *(uint32_t*)&g_Qh[base1 + c] = pack2h(v0, v1);
                *(uint32_t*)&g_Ql[base1 + c] = pack2h(v0 - __half2float(h0), v1 - __half2float(h1));
            }
        }
    } else {            // K, V: hi only
        __half* Ah = (which == 1) ? g_Kh : g_Vh;
        #pragma unroll
        for (int j = 0; j < 8; j++) {
            const int c = j * 8 + 2 * (lane & 3);
            *(uint32_t*)&Ah[base0 + c] = pack2h(sacc[j][0] + bp[c0 + c], sacc[j][1] + bp[c0 + c + 1]);
            *(uint32_t*)&Ah[base1 + c] = pack2h(sacc[j][2] + bp[c0 + c], sacc[j][3] + bp[c0 + c + 1]);
        }
    }
}

// ---------------------------------------------------------------------------
// Kernel 2: causal flash attention (fp16 HMMA, A-side compensated).
// Q-tile 128, K-tile 128 (two 64-key halves), double-buffered cp.async.
// grid = (S/128, H, B), block = 256.
// ---------------------------------------------------------------------------
#define SQH 0
#define SQL 18432
#define SKV 36864            // two buffers of 36864 (KH, VH @ 18432 each)
#define ATTN_SMEM (36864 + 2*36864)   // 110592

__global__ void __launch_bounds__(256) attn_kernel() {
    extern __shared__ char smem[];
    const uint32_t smb = smem_u32(smem);

    const int qt = blockIdx.x;
    const int h  = blockIdx.y;
    const int b  = blockIdx.z;
    const int q0 = qt * 128;

    const int tid  = threadIdx.x;
    const int w    = tid >> 5;
    const int lane = tid & 31;

    const size_t bh = (size_t)b * HH + h;
    const __half* Qh = g_Qh + (bh * SS + q0) * DD;
    const __half* Ql = g_Ql + (bh * SS + q0) * DD;
    const __half* Kh = g_Kh + bh * SS * DD;
    const __half* Vh = g_Vh + bh * SS * DD;

    const int ktmax = qt;   // 128-key tiles, kt <= qt

    // prefetch K/V tile 0 into buffer 0 (K: 128x64, V: 128x64)
    {
        const uint32_t base = smb + SKV;
        for (int idx = tid; idx < 2048; idx += 256) {
            int arr = idx >> 10, rem = idx & 1023, r = rem >> 3, ch = rem & 7;
            const __half* src = (arr == 0) ? (Kh + (size_t)r * DD + ch * 8)
                                           : (Vh + (size_t)r * DD + ch * 8);
            CPA(base + arr * 18432 + r * 144 + ch * 16, src);
        }
        CPC();
    }

    // load Q tile (hi + lo)
    for (int idx = tid; idx < 1024; idx += 256) {
        int r = idx >> 3, ch = idx & 7;
        *(uint4*)(smem + SQH + r * 144 + ch * 16) = *(const uint4*)(Qh + (size_t)r * DD + ch * 8);
        *(uint4*)(smem + SQL + r * 144 + ch * 16) = *(const uint4*)(Ql + (size_t)r * DD + ch * 8);
    }
    __syncthreads();

    uint32_t qh[4][4], qlr[4][4];
    {
        const uint32_t qbase = smb + SQH + (uint32_t)((w * 16 + (lane & 15)) * 144 + (lane >> 4) * 16);
        #pragma unroll
        for (int kk = 0; kk < 4; kk++) {
            ldm_x4(qh[kk],  qbase + kk * 32);
            ldm_x4(qlr[kk], qbase + kk * 32 + (SQL - SQH));
        }
    }

    float o[8][4];
    #pragma unroll
    for (int j = 0; j < 8; j++)
        #pragma unroll
        for (int e = 0; e < 4; e++) o[j][e] = 0.f;
    float m0 = -1e30f, m1 = -1e30f, l0 = 0.f, l1 = 0.f;

    const int rg0  = q0 + w * 16 + (lane >> 2);
    const int wmax = q0 + w * 16 + 15;

    const uint32_t klane = (uint32_t)(((lane & 7) + ((lane >> 4) & 1) * 8) * 144 + ((lane >> 3) & 1) * 16);
    const uint32_t vlane = (uint32_t)(((lane & 7) + ((lane >> 3) & 1) * 8) * 144 + ((lane >> 4) & 1) * 16);

    for (int kt = 0; kt <= ktmax; kt++) {
        const int buf = kt & 1;

        if (kt < ktmax) {
            const int nk0 = (kt + 1) * 128;
            const uint32_t base = smb + SKV + (buf ^ 1) * 36864;
            for (int idx = tid; idx < 2048; idx += 256) {
                int arr = idx >> 10, rem = idx & 1023, r = rem >> 3, ch = rem & 7;
                const __half* src = (arr == 0) ? (Kh + (size_t)(nk0 + r) * DD + ch * 8)
                                               : (Vh + (size_t)(nk0 + r) * DD + ch * 8);
                CPA(base + arr * 18432 + r * 144 + ch * 16, src);
            }
            CPC();
            CPW1();
        } else {
            CPW0();
        }
        __syncthreads();

        const uint32_t kvb = smb + SKV + buf * 36864;

        #pragma unroll
        for (int hf = 0; hf < 2; hf++) {
            const int khalf0 = kt * 128 + hf * 64;
            int jjn = (wmax >= khalf0) ? (((wmax - khalf0) >> 4) + 1) : 0;
            if (jjn > 4) jjn = 4;
            if (jjn == 0) continue;

            const uint32_t kbase = kvb + (uint32_t)(hf * 64 * 144) + klane;
            const uint32_t vbase = kvb + 18432 + (uint32_t)(hf * 64 * 144) + vlane;

            // ---- S = (Qh+Ql) Kh^T ----
            float sacc[8][4];
            #pragma unroll
            for (int j = 0; j < 8; j++)
                #pragma unroll
                for (int e = 0; e < 4; e++) sacc[j][e] = 0.f;

            #pragma unroll
            for (int jj = 0; jj < 4; jj++) {
                if (jj >= jjn) break;
                #pragma unroll
                for (int kk = 0; kk < 4; kk++) {
                    uint32_t bhr[4];
                    ldm_x4(bhr, kbase + (uint32_t)(jj * 16 * 144 + kk * 32));
                    mma16816(sacc[2*jj],   qh[kk][0], qh[kk][1], qh[kk][2], qh[kk][3], bhr[0], bhr[1]);
                    mma16816(sacc[2*jj],   qlr[kk][0], qlr[kk][1], qlr[kk][2], qlr[kk][3], bhr[0], bhr[1]);
                    mma16816(sacc[2*jj+1], qh[kk][0], qh[kk][1], qh[kk][2], qh[kk][3], bhr[2], bhr[3]);
                    mma16816(sacc[2*jj+1], qlr[kk][0], qlr[kk][1], qlr[kk][2], qlr[kk][3], bhr[2], bhr[3]);
                }
            }
            // blank untouched groups
            #pragma unroll
            for (int j = 0; j < 8; j++)
                if (j >= 2 * jjn) {
                    sacc[j][0] = sacc[j][1] = sacc[j][2] = sacc[j][3] = -1e30f;
                }

            // ---- causal element mask (only if this half straddles diag) ----
            if (khalf0 + 63 > rg0) {
                #pragma unroll
                for (int j = 0; j < 8; j++) {
                    const int cbase = khalf0 + j * 8 + 2 * (lane & 3);
                    if (cbase     > rg0)     sacc[j][0] = -1e30f;
                    if (cbase + 1 > rg0)     sacc[j][1] = -1e30f;
                    if (cbase     > rg0 + 8) sacc[j][2] = -1e30f;
                    if (cbase + 1 > rg0 + 8) sacc[j][3] = -1e30f;
                }
            }

            // ---- online softmax (base-2) ----
            float mx0 = -1e30f, mx1 = -1e30f;
            #pragma unroll
            for (int j = 0; j < 8; j++) {
                mx0 = fmaxf(mx0, fmaxf(sacc[j][0], sacc[j][1]));
                mx1 = fmaxf(mx1, fmaxf(sacc[j][2], sacc[j][3]));
            }
            mx0 = fmaxf(mx0, __shfl_xor_sync(0xffffffffu, mx0, 1));
            mx0 = fmaxf(mx0, __shfl_xor_sync(0xffffffffu, mx0, 2));
            mx1 = fmaxf(mx1, __shfl_xor_sync(0xffffffffu, mx1, 1));
            mx1 = fmaxf(mx1, __shfl_xor_sync(0xffffffffu, mx1, 2));

            const float nm0 = fmaxf(m0, mx0);
            const float nm1 = fmaxf(m1, mx1);
            const float corr0 = ex2(m0 - nm0);
            const float corr1 = ex2(m1 - nm1);
            m0 = nm0; m1 = nm1;

            uint32_t ph[8][2], pl[8][2];
            float s0 = 0.f, s1 = 0.f;
            #pragma unroll
            for (int j = 0; j < 8; j++) {
                float p0 = ex2(sacc[j][0] - nm0);
                float p1 = ex2(sacc[j][1] - nm0);
                float p2 = ex2(sacc[j][2] - nm1);
                float p3 = ex2(sacc[j][3] - nm1);
                s0 += p0 + p1;
                s1 += p2 + p3;
                __half h0 = __float2half_rn(p0), h1 = __float2half_rn(p1);
                __half h2 = __float2half_rn(p2), h3 = __float2half_rn(p3);
                ph[j][0] = pack2h(p0, p1);
                ph[j][1] = pack2h(p2, p3);
                pl[j][0] = pack2h(p0 - __half2float(h0), p1 - __half2float(h1));
                pl[j][1] = pack2h(p2 - __half2float(h2), p3 - __half2float(h3));
            }
            s0 += __shfl_xor_sync(0xffffffffu, s0, 1);
            s0 += __shfl_xor_sync(0xffffffffu, s0, 2);
            s1 += __shfl_xor_sync(0xffffffffu, s1, 1);
            s1 += __shfl_xor_sync(0xffffffffu, s1, 2);
            l0 = l0 * corr0 + s0;
            l1 = l1 * corr1 + s1;

            #pragma unroll
            for (int j = 0; j < 8; j++) {
                o[j][0] *= corr0; o[j][1] *= corr0;
                o[j][2] *= corr1; o[j][3] *= corr1;
            }

            // ---- O += (Ph+Pl) Vh ----
            #pragma unroll
            for (int kk = 0; kk < 4; kk++) {
                if (kk >= jjn) break;
                #pragma unroll
                for (int dd = 0; dd < 4; dd++) {
                    uint32_t vh[4];
                    ldm_x4_t(vh, vbase + (uint32_t)(kk * 16 * 144 + dd * 32));
                    mma16816(o[2*dd],   ph[2*kk][0], ph[2*kk][1], ph[2*kk+1][0], ph[2*kk+1][1], vh[0], vh[1]);
                    mma16816(o[2*dd],   pl[2*kk][0], pl[2*kk][1], pl[2*kk+1][0], pl[2*kk+1][1], vh[0], vh[1]);
                    mma16816(o[2*dd+1], ph[2*kk][0], ph[2*kk][1], ph[2*kk+1][0], ph[2*kk+1][1], vh[2], vh[3]);
                    mma16816(o[2*dd+1], pl[2*kk][0], pl[2*kk][1], pl[2*kk+1][0], pl[2*kk+1][1], vh[2], vh[3]);
                }
            }
        }
        __syncthreads();
    }

    // ---- epilogue: normalize, split hi/lo, write fp16 [B,S,HID] ----
    const float inv0 = 1.f / l0;
    const float inv1 = 1.f / l1;
    const size_t db0 = ((size_t)b * SS + rg0) * HID + h * 64;
    const size_t db1 = db0 + (size_t)8 * HID;
    #pragma unroll
    for (int j = 0; j < 8; j++) {
        const int c = j * 8 + 2 * (lane & 3);
        {
            float v0 = o[j][0] * inv0, v1 = o[j][1] * inv0;
            __half h0 = __float2half_rn(v0), h1 = __float2half_rn(v1);
            *(uint32_t*)&g_attnh[db0 + c] = pack2h(v0, v1);
            *(uint32_t*)&g_attnl[db0 + c] = pack2h(v0 - __half2float(h0), v1 - __half2float(h1));
        }
        {
            float v0 = o[j][2] * inv1, v1 = o[j][3] * inv1;
            __half h0 = __float2half_rn(v0), h1 = __float2half_rn(v1);
            *(uint32_t*)&g_attnh[db1 + c] = pack2h(v0, v1);
            *(uint32_t*)&g_attnl[db1 + c] = pack2h(v0 - __half2float(h0), v1 - __half2float(h1));
        }
    }
}

// ---------------------------------------------------------------------------
// Kernel 3: output projection via HMMA: (Ah+Al) @ Woh + bo.
// grid = BS/64, block = 128.  K=1024 in 16 double-buffered steps.
// ---------------------------------------------------------------------------
// per buffer: AH, AL, WH @ 9216 each = 27648; two buffers = 55296.
#define OPROJ_SMEM (2 * 27648)
__global__ void __launch_bounds__(128) oproj_mma_kernel(const float* __restrict__ bo,
                                                        float* __restrict__ out) {
    extern __shared__ char smem[];
    const uint32_t smb = smem_u32(smem);

    const int m0  = blockIdx.x * 64;
    const int tid = threadIdx.x;
    const int w   = tid >> 5;
    const int lane = tid & 31;

    {
        const uint32_t base = smb;
        for (int idx = tid; idx < 1536; idx += 128) {
            int arr = idx >> 9, rem = idx & 511, r = rem >> 3, ch = rem & 7;
            const __half* src;
            if      (arr == 0) src = g_attnh + (size_t)(m0 + r) * HID + ch * 8;
            else if (arr == 1) src = g_attnl + (size_t)(m0 + r) * HID + ch * 8;
            else               src = g_WoTh + (size_t)r * HID + ch * 8;
            CPA(base + arr * 9216 + r * 144 + ch * 16, src);
        }
        CPC();
    }

    float sacc[8][4];
    #pragma unroll
    for (int j = 0; j < 8; j++)
        #pragma unroll
        for (int e = 0; e < 4; e++) sacc[j][e] = 0.f;

    const uint32_t a_off = (uint32_t)((w * 16 + (lane & 15)) * 144 + (lane >> 4) * 16);
    const uint32_t b_off = (uint32_t)(((lane & 7) + ((lane >> 4) & 1) * 8) * 144 + ((lane >> 3) & 1) * 16);

    for (int kt = 0; kt < 16; kt++) {
        const int buf = kt & 1;
        if (kt < 15) {
            const int nk0 = (kt + 1) * 64;
            const uint32_t base = smb + (buf ^ 1) * 27648;
            for (int idx = tid; idx < 1536; idx += 128) {
                int arr = idx >> 9, rem = idx & 511, r = rem >> 3, ch = rem & 7;
                const __half* src;
                if      (arr == 0) src = g_attnh + (size_t)(m0 + r) * HID + nk0 + ch * 8;
                else if (arr == 1) src = g_attnl + (size_t)(m0 + r) * HID + nk0 + ch * 8;
                else               src = g_WoTh + (size_t)r * HID + nk0 + ch * 8;
                CPA(base + arr * 9216 + r * 144 + ch * 16, src);
            }
            CPC();
            CPW1();
        } else {
            CPW0();
        }
        __syncthreads();

        const uint32_t bb = smb + buf * 27648;
        const uint32_t abase = bb + a_off;
        const uint32_t bbase = bb + 18432 + b_off;

        #pragma unroll
        for (int kk = 0; kk < 4; kk++) {
            uint32_t ah[4], al[4];
            ldm_x4(ah, abase + kk * 32);
            ldm_x4(al, abase + kk * 32 + 9216);
            #pragma unroll
            for (int jj = 0; jj < 4; jj++) {
                uint32_t bhr[4];
                ldm_x4(bhr, bbase + (uint32_t)(jj * 16 * 144 + kk * 32));
                mma16816(sacc[2*jj],   ah[0], ah[1], ah[2], ah[3], bhr[0], bhr[1]);
                mma16816(sacc[2*jj],   al[0], al[1], al[2], al[3], bhr[0], bhr[1]);
                mma16816(sacc[2*jj+1], ah[0], ah[1], ah[2], ah[3], bhr[2], bhr[3]);
                mma16816(sacc[2*jj+1], al[0], al[1], al[2], al[3], bhr[2], bhr[3]);
            }
        }
        __syncthreads();
    }

    const int r0 = w * 16 + (lane >> 2);
    #pragma unroll
    for (int j = 0; j < 8; j++) {
        const int c = j * 8 + 2 * (lane & 3);
        out[(size_t)(m0 + r0) * DD + c]     = sacc[j][0] + bo[c];
        out[(size_t)(m0 + r0) * DD + c + 1] = sacc[j][1] + bo[c + 1];
        out[(size_t)(m0 + r0 + 8) * DD + c]     = sacc[j][2] + bo[c];
        out[(size_t)(m0 + r0 + 8) * DD + c + 1] = sacc[j][3] + bo[c + 1];
    }
}

// ---------------------------------------------------------------------------
extern "C" void kernel_launch(void* const* d_in, const int* in_sizes, int n_in,
                              void* d_out, int out_size) {
    (void)in_sizes; (void)n_in; (void)out_size;
    const float* x  = (const float*)d_in[0];
    const float* Wq = (const float*)d_in[1];
    const float* bq = (const float*)d_in[2];
    const float* Wk = (const float*)d_in[3];
    const float* bk = (const float*)d_in[4];
    const float* Wv = (const float*)d_in[5];
    const float* bv = (const float*)d_in[6];
    const float* Wo = (const float*)d_in[7];
    const float* bo = (const float*)d_in[8];
    float* out = (float*)d_out;

    prep_kernel<<<1024, 256>>>(x, Wq, Wk, Wv, Wo);

    qkv_mma_kernel<<<dim3(BS / 64, HID / 64, 3), 128>>>(bq, bk, bv);

    cudaFuncSetAttribute(attn_kernel, cudaFuncAttributeMaxDynamicSharedMemorySize, ATTN_SMEM);
    attn_kernel<<<dim3(SS / 128, HH, BB), 256, ATTN_SMEM>>>();

    cudaFuncSetAttribute(oproj_mma_kernel, cudaFuncAttributeMaxDynamicSharedMemorySize, OPROJ_SMEM);
    oproj_mma_kernel<<<BS / 64, 128, OPROJ_SMEM>>>(bo, out);
}

// round 9
// speedup vs baseline: 5.6467x; 1.0964x over previous
#include <cuda_runtime.h>
#include <cuda_fp16.h>
#include <math.h>
#include <stdint.h>

#define BB 4
#define SS 2048
#define HH 16
#define DD 64
#define HID 1024
#define BS (BB*SS)
#define LOG2E 1.4426950408889634f

// ---------------- scratch (device globals: allocation-free rule) ------------
__device__ __half g_xh[BS*DD];           // x split (compensated operand)
__device__ __half g_xl[BS*DD];
__device__ __half g_WTh[3*HID*DD];       // QKV W^T hi only: [which][n][k]
__device__ __half g_WoTh[DD*HID];        // Wo^T hi only: [n][k]
// Q pre-scaled by (1/sqrt(D)) * log2(e). All [b,h,s,d].
__device__ __half g_Qh[BB*HH*SS*DD];
__device__ __half g_Ql[BB*HH*SS*DD];
__device__ __half g_Kh[BB*HH*SS*DD];     // hi only (uncompensated)
__device__ __half g_Vh[BB*HH*SS*DD];     // hi only
__device__ __half g_attnh[BS*HID];       // attn out split, [B,S,HID]
__device__ __half g_attnl[BS*HID];

// ---------------- helpers ---------------------------------------------------
static __device__ __forceinline__ uint32_t smem_u32(const void* p) {
    return (uint32_t)__cvta_generic_to_shared(p);
}
static __device__ __forceinline__ void ldm_x4(uint32_t* r, uint32_t addr) {
    asm volatile("ldmatrix.sync.aligned.m8n8.x4.shared.b16 {%0,%1,%2,%3}, [%4];"
                 : "=r"(r[0]), "=r"(r[1]), "=r"(r[2]), "=r"(r[3]) : "r"(addr));
}
static __device__ __forceinline__ void ldm_x4_t(uint32_t* r, uint32_t addr) {
    asm volatile("ldmatrix.sync.aligned.m8n8.x4.trans.shared.b16 {%0,%1,%2,%3}, [%4];"
                 : "=r"(r[0]), "=r"(r[1]), "=r"(r[2]), "=r"(r[3]) : "r"(addr));
}
static __device__ __forceinline__ void mma16816(float* c,
                                                uint32_t a0, uint32_t a1, uint32_t a2, uint32_t a3,
                                                uint32_t b0, uint32_t b1) {
    asm volatile(
        "mma.sync.aligned.m16n8k16.row.col.f32.f16.f16.f32 "
        "{%0,%1,%2,%3}, {%4,%5,%6,%7}, {%8,%9}, {%0,%1,%2,%3};"
        : "+f"(c[0]), "+f"(c[1]), "+f"(c[2]), "+f"(c[3])
        : "r"(a0), "r"(a1), "r"(a2), "r"(a3), "r"(b0), "r"(b1));
}
static __device__ __forceinline__ uint32_t pack2h(float f0, float f1) {
    __half2 t = __halves2half2(__float2half_rn(f0), __float2half_rn(f1));
    return *reinterpret_cast<uint32_t*>(&t);
}
static __device__ __forceinline__ float ex2(float x) {
    float y;
    asm("ex2.approx.ftz.f32 %0, %1;" : "=f"(y) : "f"(x));
    return y;
}
#define CPA(dst, src) asm volatile("cp.async.ca.shared.global [%0], [%1], 16;" :: "r"(dst), "l"(src))
#define CPC()   asm volatile("cp.async.commit_group;" ::: "memory")
#define CPW1()  asm volatile("cp.async.wait_group 1;" ::: "memory")
#define CPW0()  asm volatile("cp.async.wait_group 0;" ::: "memory")

// ---------------------------------------------------------------------------
// Kernel 0: prep — split x to fp16 hi/lo; W^T, Wo^T to fp16 hi.
// ---------------------------------------------------------------------------
#define NX (BS*DD)          // 524288
#define NW (3*HID*DD)       // 196608
#define NWO (DD*HID)        // 65536
__global__ void prep_kernel(const float* __restrict__ x,
                            const float* __restrict__ Wq,
                            const float* __restrict__ Wk,
                            const float* __restrict__ Wv,
                            const float* __restrict__ Wo) {
    for (int idx = blockIdx.x * blockDim.x + threadIdx.x; idx < NX + NW + NWO;
         idx += gridDim.x * blockDim.x) {
        if (idx < NX) {
            float f = x[idx];
            __half hi = __float2half_rn(f);
            g_xh[idx] = hi;
            g_xl[idx] = __float2half_rn(f - __half2float(hi));
        } else if (idx < NX + NW) {
            int r = idx - NX;
            int which = r >> 16;
            int t = r & 65535;
            int n = t >> 6, k = t & 63;
            const float* W = (which == 0) ? Wq : (which == 1) ? Wk : Wv;
            g_WTh[r] = __float2half_rn(W[k * HID + n]);
        } else {
            int r = idx - NX - NW;          // r = n*1024 + k
            int n = r >> 10, k = r & 1023;
            g_WoTh[r] = __float2half_rn(Wo[k * DD + n]);
        }
    }
}

// ---------------------------------------------------------------------------
// Kernel 1: QKV projection via HMMA: (xh+xl) @ Wh.
// grid = (BS/64, HID/64, 3), block = 128.
// ---------------------------------------------------------------------------
__global__ void __launch_bounds__(128) qkv_mma_kernel(const float* __restrict__ bq,
                                                      const float* __restrict__ bk,
                                                      const float* __restrict__ bv) {
    __shared__ __align__(16) char smem[3 * 9216];   // XH, XL, WH
    const uint32_t smb = smem_u32(smem);

    const int m0    = blockIdx.x * 64;
    const int h     = blockIdx.y;
    const int which = blockIdx.z;
    const int c0    = h * 64;

    const int tid  = threadIdx.x;
    const int w    = tid >> 5;
    const int lane = tid & 31;

    const float* bp = (which == 0) ? bq : (which == 1) ? bk : bv;

    for (int idx = tid; idx < 1536; idx += 128) {
        int arr = idx >> 9, rem = idx & 511, r = rem >> 3, ch = rem & 7;
        const __half* src;
        if      (arr == 0) src = g_xh  + (size_t)(m0 + r) * DD + ch * 8;
        else if (arr == 1) src = g_xl  + (size_t)(m0 + r) * DD + ch * 8;
        else               src = g_WTh + (size_t)which * HID * DD + (size_t)(c0 + r) * DD + ch * 8;
        *(uint4*)(smem + arr * 9216 + r * 144 + ch * 16) = *(const uint4*)src;
    }
    __syncthreads();

    uint32_t ah[4][4], al[4][4];
    {
        const uint32_t abase = smb + (uint32_t)((w * 16 + (lane & 15)) * 144 + (lane >> 4) * 16);
        #pragma unroll
        for (int kk = 0; kk < 4; kk++) {
            ldm_x4(ah[kk], abase + kk * 32);
            ldm_x4(al[kk], abase + kk * 32 + 9216);
        }
    }
    const uint32_t bbase = smb + 18432 +
        (uint32_t)(((lane & 7) + ((lane >> 4) & 1) * 8) * 144 + ((lane >> 3) & 1) * 16);

    float sacc[8][4];
    #pragma unroll
    for (int j = 0; j < 8; j++)
        #pragma unroll
        for (int e = 0; e < 4; e++) sacc[j][e] = 0.f;

    #pragma unroll
    for (int jj = 0; jj < 4; jj++) {
        #pragma unroll
        for (int kk = 0; kk < 4; kk++) {
            uint32_t bhr[4];
            ldm_x4(bhr, bbase + (uint32_t)(jj * 16 * 144 + kk * 32));
            mma16816(sacc[2*jj],   ah[kk][0], ah[kk][1], ah[kk][2], ah[kk][3], bhr[0], bhr[1]);
            mma16816(sacc[2*jj],   al[kk][0], al[kk][1], al[kk][2], al[kk][3], bhr[0], bhr[1]);
            mma16816(sacc[2*jj+1], ah[kk][0], ah[kk][1], ah[kk][2], ah[kk][3], bhr[2], bhr[3]);
            mma16816(sacc[2*jj+1], al[kk][0], al[kk][1], al[kk][2], al[kk][3], bhr[2], bhr[3]);
        }
    }

    const float scale = (which == 0) ? 0.125f * LOG2E : 1.0f;
    const int b   = m0 >> 11;
    const int ss0 = m0 & 2047;
    const int r0  = w * 16 + (lane >> 2);
    const size_t base0 = (((size_t)b * HH + h) * SS + (ss0 + r0)) * DD;
    const size_t base1 = base0 + (size_t)8 * DD;

    if (which == 0) {   // Q: hi + lo (compensated side of QK^T)
        #pragma unroll
        for (int j = 0; j < 8; j++) {
            const int c = j * 8 + 2 * (lane & 3);
            {
                float v0 = (sacc[j][0] + bp[c0 + c]) * scale;
                float v1 = (sacc[j][1] + bp[c0 + c + 1]) * scale;
                __half h0 = __float2half_rn(v0), h1 = __float2half_rn(v1);
                *(uint32_t*)&g_Qh[base0 + c] = pack2h(v0, v1);
                *(uint32_t*)&g_Ql[base0 + c] = pack2h(v0 - __half2float(h0), v1 - __half2float(h1));
            }
            {
                float v0 = (sacc[j][2] + bp[c0 + c]) * scale;
                float v1 = (sacc[j][3] + bp[c0 + c + 1]) * scale;
                __half h0 = __float2half_rn(v0), h1 = __float2half_rn(v1);
                *(uint32_t*)&g_Qh[base1 + c] = pack2h(v0, v1);
                *(uint32_t*)&g_Ql[base1 + c] = pack2h(v0 - __half2float(h0), v1 - __half2float(h1));
            }
        }
    } else {            // K, V: hi only
        __half* Ah = (which == 1) ? g_Kh : g_Vh;
        #pragma unroll
        for (int j = 0; j < 8; j++) {
            const int c = j * 8 + 2 * (lane & 3);
            *(uint32_t*)&Ah[base0 + c] = pack2h(sacc[j][0] + bp[c0 + c], sacc[j][1] + bp[c0 + c + 1]);
            *(uint32_t*)&Ah[base1 + c] = pack2h(sacc[j][2] + bp[c0 + c], sacc[j][3] + bp[c0 + c + 1]);
        }
    }
}

// ---------------------------------------------------------------------------
// Kernel 2: causal flash attention (fp16 HMMA, Q-side compensated QK only).
// Q-tile 128, K-tile 128 (two 64-key halves), double-buffered cp.async.
// grid = (S/128, H, B), block = 256.  qt order reversed for load balance.
// ---------------------------------------------------------------------------
#define SQH 0
#define SQL 18432
#define SKV 36864            // two buffers of 36864 (KH, VH @ 18432 each)
#define ATTN_SMEM (36864 + 2*36864)   // 110592

__global__ void __launch_bounds__(256) attn_kernel() {
    extern __shared__ char smem[];
    const uint32_t smb = smem_u32(smem);

    const int qt = gridDim.x - 1 - blockIdx.x;   // heavy tiles first
    const int h  = blockIdx.y;
    const int b  = blockIdx.z;
    const int q0 = qt * 128;

    const int tid  = threadIdx.x;
    const int w    = tid >> 5;
    const int lane = tid & 31;

    const size_t bh = (size_t)b * HH + h;
    const __half* Qh = g_Qh + (bh * SS + q0) * DD;
    const __half* Ql = g_Ql + (bh * SS + q0) * DD;
    const __half* Kh = g_Kh + bh * SS * DD;
    const __half* Vh = g_Vh + bh * SS * DD;

    const int ktmax = qt;   // 128-key tiles, kt <= qt

    // prefetch K/V tile 0 into buffer 0 (K: 128x64, V: 128x64)
    {
        const uint32_t base = smb + SKV;
        for (int idx = tid; idx < 2048; idx += 256) {
            int arr = idx >> 10, rem = idx & 1023, r = rem >> 3, ch = rem & 7;
            const __half* src = (arr == 0) ? (Kh + (size_t)r * DD + ch * 8)
                                           : (Vh + (size_t)r * DD + ch * 8);
            CPA(base + arr * 18432 + r * 144 + ch * 16, src);
        }
        CPC();
    }

    // load Q tile (hi + lo)
    for (int idx = tid; idx < 1024; idx += 256) {
        int r = idx >> 3, ch = idx & 7;
        *(uint4*)(smem + SQH + r * 144 + ch * 16) = *(const uint4*)(Qh + (size_t)r * DD + ch * 8);
        *(uint4*)(smem + SQL + r * 144 + ch * 16) = *(const uint4*)(Ql + (size_t)r * DD + ch * 8);
    }
    __syncthreads();

    uint32_t qh[4][4], qlr[4][4];
    {
        const uint32_t qbase = smb + SQH + (uint32_t)((w * 16 + (lane & 15)) * 144 + (lane >> 4) * 16);
        #pragma unroll
        for (int kk = 0; kk < 4; kk++) {
            ldm_x4(qh[kk],  qbase + kk * 32);
            ldm_x4(qlr[kk], qbase + kk * 32 + (SQL - SQH));
        }
    }

    float o[8][4];
    #pragma unroll
    for (int j = 0; j < 8; j++)
        #pragma unroll
        for (int e = 0; e < 4; e++) o[j][e] = 0.f;
    float m0 = -1e30f, m1 = -1e30f, l0 = 0.f, l1 = 0.f;

    const int rg0  = q0 + w * 16 + (lane >> 2);
    const int wmax = q0 + w * 16 + 15;

    const uint32_t klane = (uint32_t)(((lane & 7) + ((lane >> 4) & 1) * 8) * 144 + ((lane >> 3) & 1) * 16);
    const uint32_t vlane = (uint32_t)(((lane & 7) + ((lane >> 3) & 1) * 8) * 144 + ((lane >> 4) & 1) * 16);

    for (int kt = 0; kt <= ktmax; kt++) {
        const int buf = kt & 1;

        if (kt < ktmax) {
            const int nk0 = (kt + 1) * 128;
            const uint32_t base = smb + SKV + (buf ^ 1) * 36864;
            for (int idx = tid; idx < 2048; idx += 256) {
                int arr = idx >> 10, rem = idx & 1023, r = rem >> 3, ch = rem & 7;
                const __half* src = (arr == 0) ? (Kh + (size_t)(nk0 + r) * DD + ch * 8)
                                               : (Vh + (size_t)(nk0 + r) * DD + ch * 8);
                CPA(base + arr * 18432 + r * 144 + ch * 16, src);
            }
            CPC();
            CPW1();
        } else {
            CPW0();
        }
        __syncthreads();

        const uint32_t kvb = smb + SKV + buf * 36864;

        #pragma unroll
        for (int hf = 0; hf < 2; hf++) {
            const int khalf0 = kt * 128 + hf * 64;
            int jjn = (wmax >= khalf0) ? (((wmax - khalf0) >> 4) + 1) : 0;
            if (jjn > 4) jjn = 4;
            if (jjn == 0) continue;

            const uint32_t kbase = kvb + (uint32_t)(hf * 64 * 144) + klane;
            const uint32_t vbase = kvb + 18432 + (uint32_t)(hf * 64 * 144) + vlane;

            // ---- S = (Qh+Ql) Kh^T ----
            float sacc[8][4];
            #pragma unroll
            for (int j = 0; j < 8; j++)
                #pragma unroll
                for (int e = 0; e < 4; e++) sacc[j][e] = 0.f;

            #pragma unroll
            for (int jj = 0; jj < 4; jj++) {
                if (jj >= jjn) break;
                #pragma unroll
                for (int kk = 0; kk < 4; kk++) {
                    uint32_t bhr[4];
                    ldm_x4(bhr, kbase + (uint32_t)(jj * 16 * 144 + kk * 32));
                    mma16816(sacc[2*jj],   qh[kk][0], qh[kk][1], qh[kk][2], qh[kk][3], bhr[0], bhr[1]);
                    mma16816(sacc[2*jj],   qlr[kk][0], qlr[kk][1], qlr[kk][2], qlr[kk][3], bhr[0], bhr[1]);
                    mma16816(sacc[2*jj+1], qh[kk][0], qh[kk][1], qh[kk][2], qh[kk][3], bhr[2], bhr[3]);
                    mma16816(sacc[2*jj+1], qlr[kk][0], qlr[kk][1], qlr[kk][2], qlr[kk][3], bhr[2], bhr[3]);
                }
            }
            // blank untouched groups
            #pragma unroll
            for (int j = 0; j < 8; j++)
                if (j >= 2 * jjn) {
                    sacc[j][0] = sacc[j][1] = sacc[j][2] = sacc[j][3] = -1e30f;
                }

            // ---- causal element mask (only if this half straddles diag) ----
            if (khalf0 + 63 > rg0) {
                #pragma unroll
                for (int j = 0; j < 8; j++) {
                    const int cbase = khalf0 + j * 8 + 2 * (lane & 3);
                    if (cbase     > rg0)     sacc[j][0] = -1e30f;
                    if (cbase + 1 > rg0)     sacc[j][1] = -1e30f;
                    if (cbase     > rg0 + 8) sacc[j][2] = -1e30f;
                    if (cbase + 1 > rg0 + 8) sacc[j][3] = -1e30f;
                }
            }

            // ---- online softmax (base-2) ----
            float mx0 = -1e30f, mx1 = -1e30f;
            #pragma unroll
            for (int j = 0; j < 8; j++) {
                mx0 = fmaxf(mx0, fmaxf(sacc[j][0], sacc[j][1]));
                mx1 = fmaxf(mx1, fmaxf(sacc[j][2], sacc[j][3]));
            }
            mx0 = fmaxf(mx0, __shfl_xor_sync(0xffffffffu, mx0, 1));
            mx0 = fmaxf(mx0, __shfl_xor_sync(0xffffffffu, mx0, 2));
            mx1 = fmaxf(mx1, __shfl_xor_sync(0xffffffffu, mx1, 1));
            mx1 = fmaxf(mx1, __shfl_xor_sync(0xffffffffu, mx1, 2));

            const float nm0 = fmaxf(m0, mx0);
            const float nm1 = fmaxf(m1, mx1);
            const float corr0 = ex2(m0 - nm0);
            const float corr1 = ex2(m1 - nm1);
            m0 = nm0; m1 = nm1;

            uint32_t ph[8][2];
            float s0 = 0.f, s1 = 0.f;
            #pragma unroll
            for (int j = 0; j < 8; j++) {
                float p0 = ex2(sacc[j][0] - nm0);
                float p1 = ex2(sacc[j][1] - nm0);
                float p2 = ex2(sacc[j][2] - nm1);
                float p3 = ex2(sacc[j][3] - nm1);
                s0 += p0 + p1;
                s1 += p2 + p3;
                ph[j][0] = pack2h(p0, p1);
                ph[j][1] = pack2h(p2, p3);
            }
            s0 += __shfl_xor_sync(0xffffffffu, s0, 1);
            s0 += __shfl_xor_sync(0xffffffffu, s0, 2);
            s1 += __shfl_xor_sync(0xffffffffu, s1, 1);
            s1 += __shfl_xor_sync(0xffffffffu, s1, 2);
            l0 = l0 * corr0 + s0;
            l1 = l1 * corr1 + s1;

            #pragma unroll
            for (int j = 0; j < 8; j++) {
                o[j][0] *= corr0; o[j][1] *= corr0;
                o[j][2] *= corr1; o[j][3] *= corr1;
            }

            // ---- O += Ph Vh ----
            #pragma unroll
            for (int kk = 0; kk < 4; kk++) {
                if (kk >= jjn) break;
                #pragma unroll
                for (int dd = 0; dd < 4; dd++) {
                    uint32_t vh[4];
                    ldm_x4_t(vh, vbase + (uint32_t)(kk * 16 * 144 + dd * 32));
                    mma16816(o[2*dd],   ph[2*kk][0], ph[2*kk][1], ph[2*kk+1][0], ph[2*kk+1][1], vh[0], vh[1]);
                    mma16816(o[2*dd+1], ph[2*kk][0], ph[2*kk][1], ph[2*kk+1][0], ph[2*kk+1][1], vh[2], vh[3]);
                }
            }
        }
        __syncthreads();
    }

    // ---- epilogue: normalize, split hi/lo, write fp16 [B,S,HID] ----
    const float inv0 = 1.f / l0;
    const float inv1 = 1.f / l1;
    const size_t db0 = ((size_t)b * SS + rg0) * HID + h * 64;
    const size_t db1 = db0 + (size_t)8 * HID;
    #pragma unroll
    for (int j = 0; j < 8; j++) {
        const int c = j * 8 + 2 * (lane & 3);
        {
            float v0 = o[j][0] * inv0, v1 = o[j][1] * inv0;
            __half h0 = __float2half_rn(v0), h1 = __float2half_rn(v1);
            *(uint32_t*)&g_attnh[db0 + c] = pack2h(v0, v1);
            *(uint32_t*)&g_attnl[db0 + c] = pack2h(v0 - __half2float(h0), v1 - __half2float(h1));
        }
        {
            float v0 = o[j][2] * inv1, v1 = o[j][3] * inv1;
            __half h0 = __float2half_rn(v0), h1 = __float2half_rn(v1);
            *(uint32_t*)&g_attnh[db1 + c] = pack2h(v0, v1);
            *(uint32_t*)&g_attnl[db1 + c] = pack2h(v0 - __half2float(h0), v1 - __half2float(h1));
        }
    }
}

// ---------------------------------------------------------------------------
// Kernel 3: output projection via HMMA: (Ah+Al) @ Woh + bo.
// grid = BS/64, block = 128.  K=1024 in 16 double-buffered steps.
// ---------------------------------------------------------------------------
// per buffer: AH, AL, WH @ 9216 each = 27648; two buffers = 55296.
#define OPROJ_SMEM (2 * 27648)
__global__ void __launch_bounds__(128) oproj_mma_kernel(const float* __restrict__ bo,
                                                        float* __restrict__ out) {
    extern __shared__ char smem[];
    const uint32_t smb = smem_u32(smem);

    const int m0  = blockIdx.x * 64;
    const int tid = threadIdx.x;
    const int w   = tid >> 5;
    const int lane = tid & 31;

    {
        const uint32_t base = smb;
        for (int idx = tid; idx < 1536; idx += 128) {
            int arr = idx >> 9, rem = idx & 511, r = rem >> 3, ch = rem & 7;
            const __half* src;
            if      (arr == 0) src = g_attnh + (size_t)(m0 + r) * HID + ch * 8;
            else if (arr == 1) src = g_attnl + (size_t)(m0 + r) * HID + ch * 8;
            else               src = g_WoTh + (size_t)r * HID + ch * 8;
            CPA(base + arr * 9216 + r * 144 + ch * 16, src);
        }
        CPC();
    }

    float sacc[8][4];
    #pragma unroll
    for (int j = 0; j < 8; j++)
        #pragma unroll
        for (int e = 0; e < 4; e++) sacc[j][e] = 0.f;

    const uint32_t a_off = (uint32_t)((w * 16 + (lane & 15)) * 144 + (lane >> 4) * 16);
    const uint32_t b_off = (uint32_t)(((lane & 7) + ((lane >> 4) & 1) * 8) * 144 + ((lane >> 3) & 1) * 16);

    for (int kt = 0; kt < 16; kt++) {
        const int buf = kt & 1;
        if (kt < 15) {
            const int nk0 = (kt + 1) * 64;
            const uint32_t base = smb + (buf ^ 1) * 27648;
            for (int idx = tid; idx < 1536; idx += 128) {
                int arr = idx >> 9, rem = idx & 511, r = rem >> 3, ch = rem & 7;
                const __half* src;
                if      (arr == 0) src = g_attnh + (size_t)(m0 + r) * HID + nk0 + ch * 8;
                else if (arr == 1) src = g_attnl + (size_t)(m0 + r) * HID + nk0 + ch * 8;
                else               src = g_WoTh + (size_t)r * HID + nk0 + ch * 8;
                CPA(base + arr * 9216 + r * 144 + ch * 16, src);
            }
            CPC();
            CPW1();
        } else {
            CPW0();
        }
        __syncthreads();

        const uint32_t bb = smb + buf * 27648;
        const uint32_t abase = bb + a_off;
        const uint32_t bbase = bb + 18432 + b_off;

        #pragma unroll
        for (int kk = 0; kk < 4; kk++) {
            uint32_t ah[4], al[4];
            ldm_x4(ah, abase + kk * 32);
            ldm_x4(al, abase + kk * 32 + 9216);
            #pragma unroll
            for (int jj = 0; jj < 4; jj++) {
                uint32_t bhr[4];
                ldm_x4(bhr, bbase + (uint32_t)(jj * 16 * 144 + kk * 32));
                mma16816(sacc[2*jj],   ah[0], ah[1], ah[2], ah[3], bhr[0], bhr[1]);
                mma16816(sacc[2*jj],   al[0], al[1], al[2], al[3], bhr[0], bhr[1]);
                mma16816(sacc[2*jj+1], ah[0], ah[1], ah[2], ah[3], bhr[2], bhr[3]);
                mma16816(sacc[2*jj+1], al[0], al[1], al[2], al[3], bhr[2], bhr[3]);
            }
        }
        __syncthreads();
    }

    const int r0 = w * 16 + (lane >> 2);
    #pragma unroll
    for (int j = 0; j < 8; j++) {
        const int c = j * 8 + 2 * (lane & 3);
        out[(size_t)(m0 + r0) * DD + c]     = sacc[j][0] + bo[c];
        out[(size_t)(m0 + r0) * DD + c + 1] = sacc[j][1] + bo[c + 1];
        out[(size_t)(m0 + r0 + 8) * DD + c]     = sacc[j][2] + bo[c];
        out[(size_t)(m0 + r0 + 8) * DD + c + 1] = sacc[j][3] + bo[c + 1];
    }
}

// ---------------------------------------------------------------------------
extern "C" void kernel_launch(void* const* d_in, const int* in_sizes, int n_in,
                              void* d_out, int out_size) {
    (void)in_sizes; (void)n_in; (void)out_size;
    const float* x  = (const float*)d_in[0];
    const float* Wq = (const float*)d_in[1];
    const float* bq = (const float*)d_in[2];
    const float* Wk = (const float*)d_in[3];
    const float* bk = (const float*)d_in[4];
    const float* Wv = (const float*)d_in[5];
    const float* bv = (const float*)d_in[6];
    const float* Wo = (const float*)d_in[7];
    const float* bo = (const float*)d_in[8];
    float* out = (float*)d_out;

    prep_kernel<<<1024, 256>>>(x, Wq, Wk, Wv, Wo);

    qkv_mma_kernel<<<dim3(BS / 64, HID / 64, 3), 128>>>(bq, bk, bv);

    cudaFuncSetAttribute(attn_kernel, cudaFuncAttributeMaxDynamicSharedMemorySize, ATTN_SMEM);
    attn_kernel<<<dim3(SS / 128, HH, BB), 256, ATTN_SMEM>>>();

    cudaFuncSetAttribute(oproj_mma_kernel, cudaFuncAttributeMaxDynamicSharedMemorySize, OPROJ_SMEM);
    oproj_mma_kernel<<<BS / 64, 128, OPROJ_SMEM>>>(bo, out);
}

// round 11
// speedup vs baseline: 6.9745x; 1.2351x over previous
#include <cuda_runtime.h>
#include <cuda_fp16.h>
#include <math.h>
#include <stdint.h>

#define BB 4
#define SS 2048
#define HH 16
#define DD 64
#define HID 1024
#define BS (BB*SS)
#define LOG2E 1.4426950408889634f

// ---------------- scratch (device globals: allocation-free rule) ------------
__device__ __half g_xh[BS*DD];           // x split (compensated operand)
__device__ __half g_xl[BS*DD];
__device__ __half g_WTh[3*HID*DD];       // QKV W^T hi only: [which][n][k]
__device__ __half g_WoTh[DD*HID];        // Wo^T hi only: [n][k]
// Q pre-scaled by (1/sqrt(D)) * log2(e). All [b,h,s,d]. All hi-only now.
__device__ __half g_Qh[BB*HH*SS*DD];
__device__ __half g_Kh[BB*HH*SS*DD];
__device__ __half g_Vh[BB*HH*SS*DD];
__device__ __half g_attnh[BS*HID];       // attn out split, [B,S,HID]
__device__ __half g_attnl[BS*HID];

// ---------------- helpers ---------------------------------------------------
static __device__ __forceinline__ uint32_t smem_u32(const void* p) {
    return (uint32_t)__cvta_generic_to_shared(p);
}
static __device__ __forceinline__ void ldm_x4(uint32_t* r, uint32_t addr) {
    asm volatile("ldmatrix.sync.aligned.m8n8.x4.shared.b16 {%0,%1,%2,%3}, [%4];"
                 : "=r"(r[0]), "=r"(r[1]), "=r"(r[2]), "=r"(r[3]) : "r"(addr));
}
static __device__ __forceinline__ void ldm_x4_t(uint32_t* r, uint32_t addr) {
    asm volatile("ldmatrix.sync.aligned.m8n8.x4.trans.shared.b16 {%0,%1,%2,%3}, [%4];"
                 : "=r"(r[0]), "=r"(r[1]), "=r"(r[2]), "=r"(r[3]) : "r"(addr));
}
static __device__ __forceinline__ void mma16816(float* c,
                                                uint32_t a0, uint32_t a1, uint32_t a2, uint32_t a3,
                                                uint32_t b0, uint32_t b1) {
    asm volatile(
        "mma.sync.aligned.m16n8k16.row.col.f32.f16.f16.f32 "
        "{%0,%1,%2,%3}, {%4,%5,%6,%7}, {%8,%9}, {%0,%1,%2,%3};"
        : "+f"(c[0]), "+f"(c[1]), "+f"(c[2]), "+f"(c[3])
        : "r"(a0), "r"(a1), "r"(a2), "r"(a3), "r"(b0), "r"(b1));
}
static __device__ __forceinline__ uint32_t pack2h(float f0, float f1) {
    __half2 t = __halves2half2(__float2half_rn(f0), __float2half_rn(f1));
    return *reinterpret_cast<uint32_t*>(&t);
}
static __device__ __forceinline__ float ex2(float x) {
    float y;
    asm("ex2.approx.ftz.f32 %0, %1;" : "=f"(y) : "f"(x));
    return y;
}
#define CPA(dst, src) asm volatile("cp.async.ca.shared.global [%0], [%1], 16;" :: "r"(dst), "l"(src))
#define CPC()   asm volatile("cp.async.commit_group;" ::: "memory")
#define CPW1()  asm volatile("cp.async.wait_group 1;" ::: "memory")
#define CPW0()  asm volatile("cp.async.wait_group 0;" ::: "memory")

// ---------------------------------------------------------------------------
// Kernel 0: prep — split x to fp16 hi/lo; W^T, Wo^T to fp16 hi.
// ---------------------------------------------------------------------------
#define NX (BS*DD)          // 524288
#define NW (3*HID*DD)       // 196608
#define NWO (DD*HID)        // 65536
__global__ void prep_kernel(const float* __restrict__ x,
                            const float* __restrict__ Wq,
                            const float* __restrict__ Wk,
                            const float* __restrict__ Wv,
                            const float* __restrict__ Wo) {
    for (int idx = blockIdx.x * blockDim.x + threadIdx.x; idx < NX + NW + NWO;
         idx += gridDim.x * blockDim.x) {
        if (idx < NX) {
            float f = x[idx];
            __half hi = __float2half_rn(f);
            g_xh[idx] = hi;
            g_xl[idx] = __float2half_rn(f - __half2float(hi));
        } else if (idx < NX + NW) {
            int r = idx - NX;
            int which = r >> 16;
            int t = r & 65535;
            int n = t >> 6, k = t & 63;
            const float* W = (which == 0) ? Wq : (which == 1) ? Wk : Wv;
            g_WTh[r] = __float2half_rn(W[k * HID + n]);
        } else {
            int r = idx - NX - NW;          // r = n*1024 + k
            int n = r >> 10, k = r & 1023;
            g_WoTh[r] = __float2half_rn(Wo[k * DD + n]);
        }
    }
}

// ---------------------------------------------------------------------------
// Kernel 1: QKV projection via HMMA: (xh+xl) @ Wh.  All outputs hi-only.
// grid = (BS/64, HID/64, 3), block = 128.
// ---------------------------------------------------------------------------
__global__ void __launch_bounds__(128) qkv_mma_kernel(const float* __restrict__ bq,
                                                      const float* __restrict__ bk,
                                                      const float* __restrict__ bv) {
    __shared__ __align__(16) char smem[3 * 9216];   // XH, XL, WH
    const uint32_t smb = smem_u32(smem);

    const int m0    = blockIdx.x * 64;
    const int h     = blockIdx.y;
    const int which = blockIdx.z;
    const int c0    = h * 64;

    const int tid  = threadIdx.x;
    const int w    = tid >> 5;
    const int lane = tid & 31;

    const float* bp = (which == 0) ? bq : (which == 1) ? bk : bv;

    for (int idx = tid; idx < 1536; idx += 128) {
        int arr = idx >> 9, rem = idx & 511, r = rem >> 3, ch = rem & 7;
        const __half* src;
        if      (arr == 0) src = g_xh  + (size_t)(m0 + r) * DD + ch * 8;
        else if (arr == 1) src = g_xl  + (size_t)(m0 + r) * DD + ch * 8;
        else               src = g_WTh + (size_t)which * HID * DD + (size_t)(c0 + r) * DD + ch * 8;
        *(uint4*)(smem + arr * 9216 + r * 144 + ch * 16) = *(const uint4*)src;
    }
    __syncthreads();

    uint32_t ah[4][4], al[4][4];
    {
        const uint32_t abase = smb + (uint32_t)((w * 16 + (lane & 15)) * 144 + (lane >> 4) * 16);
        #pragma unroll
        for (int kk = 0; kk < 4; kk++) {
            ldm_x4(ah[kk], abase + kk * 32);
            ldm_x4(al[kk], abase + kk * 32 + 9216);
        }
    }
    const uint32_t bbase = smb + 18432 +
        (uint32_t)(((lane & 7) + ((lane >> 4) & 1) * 8) * 144 + ((lane >> 3) & 1) * 16);

    float sacc[8][4];
    #pragma unroll
    for (int j = 0; j < 8; j++)
        #pragma unroll
        for (int e = 0; e < 4; e++) sacc[j][e] = 0.f;

    #pragma unroll
    for (int jj = 0; jj < 4; jj++) {
        #pragma unroll
        for (int kk = 0; kk < 4; kk++) {
            uint32_t bhr[4];
            ldm_x4(bhr, bbase + (uint32_t)(jj * 16 * 144 + kk * 32));
            mma16816(sacc[2*jj],   ah[kk][0], ah[kk][1], ah[kk][2], ah[kk][3], bhr[0], bhr[1]);
            mma16816(sacc[2*jj],   al[kk][0], al[kk][1], al[kk][2], al[kk][3], bhr[0], bhr[1]);
            mma16816(sacc[2*jj+1], ah[kk][0], ah[kk][1], ah[kk][2], ah[kk][3], bhr[2], bhr[3]);
            mma16816(sacc[2*jj+1], al[kk][0], al[kk][1], al[kk][2], al[kk][3], bhr[2], bhr[3]);
        }
    }

    const float scale = (which == 0) ? 0.125f * LOG2E : 1.0f;
    __half* Ah = (which == 0) ? g_Qh : (which == 1) ? g_Kh : g_Vh;
    const int b   = m0 >> 11;
    const int ss0 = m0 & 2047;
    const int r0  = w * 16 + (lane >> 2);
    const size_t base0 = (((size_t)b * HH + h) * SS + (ss0 + r0)) * DD;
    const size_t base1 = base0 + (size_t)8 * DD;
    #pragma unroll
    for (int j = 0; j < 8; j++) {
        const int c = j * 8 + 2 * (lane & 3);
        *(uint32_t*)&Ah[base0 + c] = pack2h((sacc[j][0] + bp[c0 + c]) * scale,
                                            (sacc[j][1] + bp[c0 + c + 1]) * scale);
        *(uint32_t*)&Ah[base1 + c] = pack2h((sacc[j][2] + bp[c0 + c]) * scale,
                                            (sacc[j][3] + bp[c0 + c + 1]) * scale);
    }
}

// ---------------------------------------------------------------------------
// Kernel 2: causal flash attention (fp16 HMMA, hi-only operands).
// Q-tile 128, K-tile 128 (two 64-key halves), double-buffered cp.async.
// grid = (S/128, H, B), block = 256.  qt order reversed for load balance.
// ---------------------------------------------------------------------------
#define SQH 0
#define SKV 18432            // two buffers of 36864 (KH, VH @ 18432 each)
#define ATTN_SMEM (18432 + 2*36864)   // 92160

__global__ void __launch_bounds__(256) attn_kernel() {
    extern __shared__ char smem[];
    const uint32_t smb = smem_u32(smem);

    const int qt = gridDim.x - 1 - blockIdx.x;   // heavy tiles first
    const int h  = blockIdx.y;
    const int b  = blockIdx.z;
    const int q0 = qt * 128;

    const int tid  = threadIdx.x;
    const int w    = tid >> 5;
    const int lane = tid & 31;

    const size_t bh = (size_t)b * HH + h;
    const __half* Qh = g_Qh + (bh * SS + q0) * DD;
    const __half* Kh = g_Kh + bh * SS * DD;
    const __half* Vh = g_Vh + bh * SS * DD;

    const int ktmax = qt;   // 128-key tiles, kt <= qt

    // prefetch K/V tile 0 into buffer 0 (K: 128x64, V: 128x64)
    {
        const uint32_t base = smb + SKV;
        for (int idx = tid; idx < 2048; idx += 256) {
            int arr = idx >> 10, rem = idx & 1023, r = rem >> 3, ch = rem & 7;
            const __half* src = (arr == 0) ? (Kh + (size_t)r * DD + ch * 8)
                                           : (Vh + (size_t)r * DD + ch * 8);
            CPA(base + arr * 18432 + r * 144 + ch * 16, src);
        }
        CPC();
    }

    // load Q tile (hi only)
    for (int idx = tid; idx < 1024; idx += 256) {
        int r = idx >> 3, ch = idx & 7;
        *(uint4*)(smem + SQH + r * 144 + ch * 16) = *(const uint4*)(Qh + (size_t)r * DD + ch * 8);
    }
    __syncthreads();

    uint32_t qh[4][4];
    {
        const uint32_t qbase = smb + SQH + (uint32_t)((w * 16 + (lane & 15)) * 144 + (lane >> 4) * 16);
        #pragma unroll
        for (int kk = 0; kk < 4; kk++) ldm_x4(qh[kk], qbase + kk * 32);
    }

    float o[8][4];
    #pragma unroll
    for (int j = 0; j < 8; j++)
        #pragma unroll
        for (int e = 0; e < 4; e++) o[j][e] = 0.f;
    float m0 = -1e30f, m1 = -1e30f, l0 = 0.f, l1 = 0.f;

    const int rg0  = q0 + w * 16 + (lane >> 2);
    const int wmax = q0 + w * 16 + 15;

    const uint32_t klane = (uint32_t)(((lane & 7) + ((lane >> 4) & 1) * 8) * 144 + ((lane >> 3) & 1) * 16);
    const uint32_t vlane = (uint32_t)(((lane & 7) + ((lane >> 3) & 1) * 8) * 144 + ((lane >> 4) & 1) * 16);

    for (int kt = 0; kt <= ktmax; kt++) {
        const int buf = kt & 1;

        if (kt < ktmax) {
            const int nk0 = (kt + 1) * 128;
            const uint32_t base = smb + SKV + (buf ^ 1) * 36864;
            for (int idx = tid; idx < 2048; idx += 256) {
                int arr = idx >> 10, rem = idx & 1023, r = rem >> 3, ch = rem & 7;
                const __half* src = (arr == 0) ? (Kh + (size_t)(nk0 + r) * DD + ch * 8)
                                               : (Vh + (size_t)(nk0 + r) * DD + ch * 8);
                CPA(base + arr * 18432 + r * 144 + ch * 16, src);
            }
            CPC();
            CPW1();
        } else {
            CPW0();
        }
        __syncthreads();

        const uint32_t kvb = smb + SKV + buf * 36864;

        #pragma unroll
        for (int hf = 0; hf < 2; hf++) {
            const int khalf0 = kt * 128 + hf * 64;
            int jjn = (wmax >= khalf0) ? (((wmax - khalf0) >> 4) + 1) : 0;
            if (jjn > 4) jjn = 4;
            if (jjn == 0) continue;

            const uint32_t kbase = kvb + (uint32_t)(hf * 64 * 144) + klane;
            const uint32_t vbase = kvb + 18432 + (uint32_t)(hf * 64 * 144) + vlane;

            // ---- S = Qh Kh^T ----
            float sacc[8][4];
            #pragma unroll
            for (int j = 0; j < 8; j++)
                #pragma unroll
                for (int e = 0; e < 4; e++) sacc[j][e] = 0.f;

            #pragma unroll
            for (int jj = 0; jj < 4; jj++) {
                if (jj >= jjn) break;
                #pragma unroll
                for (int kk = 0; kk < 4; kk++) {
                    uint32_t bhr[4];
                    ldm_x4(bhr, kbase + (uint32_t)(jj * 16 * 144 + kk * 32));
                    mma16816(sacc[2*jj],   qh[kk][0], qh[kk][1], qh[kk][2], qh[kk][3], bhr[0], bhr[1]);
                    mma16816(sacc[2*jj+1], qh[kk][0], qh[kk][1], qh[kk][2], qh[kk][3], bhr[2], bhr[3]);
                }
            }
            // blank untouched groups
            #pragma unroll
            for (int j = 0; j < 8; j++)
                if (j >= 2 * jjn) {
                    sacc[j][0] = sacc[j][1] = sacc[j][2] = sacc[j][3] = -1e30f;
                }

            // ---- causal element mask (only if this half straddles diag) ----
            if (khalf0 + 63 > rg0) {
                #pragma unroll
                for (int j = 0; j < 8; j++) {
                    const int cbase = khalf0 + j * 8 + 2 * (lane & 3);
                    if (cbase     > rg0)     sacc[j][0] = -1e30f;
                    if (cbase + 1 > rg0)     sacc[j][1] = -1e30f;
                    if (cbase     > rg0 + 8) sacc[j][2] = -1e30f;
                    if (cbase + 1 > rg0 + 8) sacc[j][3] = -1e30f;
                }
            }

            // ---- online softmax (base-2) ----
            float mx0 = -1e30f, mx1 = -1e30f;
            #pragma unroll
            for (int j = 0; j < 8; j++) {
                mx0 = fmaxf(mx0, fmaxf(sacc[j][0], sacc[j][1]));
                mx1 = fmaxf(mx1, fmaxf(sacc[j][2], sacc[j][3]));
            }
            mx0 = fmaxf(mx0, __shfl_xor_sync(0xffffffffu, mx0, 1));
            mx0 = fmaxf(mx0, __shfl_xor_sync(0xffffffffu, mx0, 2));
            mx1 = fmaxf(mx1, __shfl_xor_sync(0xffffffffu, mx1, 1));
            mx1 = fmaxf(mx1, __shfl_xor_sync(0xffffffffu, mx1, 2));

            const float nm0 = fmaxf(m0, mx0);
            const float nm1 = fmaxf(m1, mx1);
            const float corr0 = ex2(m0 - nm0);
            const float corr1 = ex2(m1 - nm1);
            m0 = nm0; m1 = nm1;

            uint32_t ph[8][2];
            float s0 = 0.f, s1 = 0.f;
            #pragma unroll
            for (int j = 0; j < 8; j++) {
                float p0 = ex2(sacc[j][0] - nm0);
                float p1 = ex2(sacc[j][1] - nm0);
                float p2 = ex2(sacc[j][2] - nm1);
                float p3 = ex2(sacc[j][3] - nm1);
                s0 += p0 + p1;
                s1 += p2 + p3;
                ph[j][0] = pack2h(p0, p1);
                ph[j][1] = pack2h(p2, p3);
            }
            s0 += __shfl_xor_sync(0xffffffffu, s0, 1);
            s0 += __shfl_xor_sync(0xffffffffu, s0, 2);
            s1 += __shfl_xor_sync(0xffffffffu, s1, 1);
            s1 += __shfl_xor_sync(0xffffffffu, s1, 2);
            l0 = l0 * corr0 + s0;
            l1 = l1 * corr1 + s1;

            #pragma unroll
            for (int j = 0; j < 8; j++) {
                o[j][0] *= corr0; o[j][1] *= corr0;
                o[j][2] *= corr1; o[j][3] *= corr1;
            }

            // ---- O += Ph Vh ----
            #pragma unroll
            for (int kk = 0; kk < 4; kk++) {
                if (kk >= jjn) break;
                #pragma unroll
                for (int dd = 0; dd < 4; dd++) {
                    uint32_t vh[4];
                    ldm_x4_t(vh, vbase + (uint32_t)(kk * 16 * 144 + dd * 32));
                    mma16816(o[2*dd],   ph[2*kk][0], ph[2*kk][1], ph[2*kk+1][0], ph[2*kk+1][1], vh[0], vh[1]);
                    mma16816(o[2*dd+1], ph[2*kk][0], ph[2*kk][1], ph[2*kk+1][0], ph[2*kk+1][1], vh[2], vh[3]);
                }
            }
        }
        __syncthreads();
    }

    // ---- epilogue: normalize, split hi/lo, write fp16 [B,S,HID] ----
    const float inv0 = 1.f / l0;
    const float inv1 = 1.f / l1;
    const size_t db0 = ((size_t)b * SS + rg0) * HID + h * 64;
    const size_t db1 = db0 + (size_t)8 * HID;
    #pragma unroll
    for (int j = 0; j < 8; j++) {
        const int c = j * 8 + 2 * (lane & 3);
        {
            float v0 = o[j][0] * inv0, v1 = o[j][1] * inv0;
            __half h0 = __float2half_rn(v0), h1 = __float2half_rn(v1);
            *(uint32_t*)&g_attnh[db0 + c] = pack2h(v0, v1);
            *(uint32_t*)&g_attnl[db0 + c] = pack2h(v0 - __half2float(h0), v1 - __half2float(h1));
        }
        {
            float v0 = o[j][2] * inv1, v1 = o[j][3] * inv1;
            __half h0 = __float2half_rn(v0), h1 = __float2half_rn(v1);
            *(uint32_t*)&g_attnh[db1 + c] = pack2h(v0, v1);
            *(uint32_t*)&g_attnl[db1 + c] = pack2h(v0 - __half2float(h0), v1 - __half2float(h1));
        }
    }
}

// ---------------------------------------------------------------------------
// Kernel 3: output projection via HMMA: (Ah+Al) @ Woh + bo.
// grid = BS/64, block = 128.  K=1024 in 16 double-buffered steps.
// ---------------------------------------------------------------------------
// per buffer: AH, AL, WH @ 9216 each = 27648; two buffers = 55296.
#define OPROJ_SMEM (2 * 27648)
__global__ void __launch_bounds__(128) oproj_mma_kernel(const float* __restrict__ bo,
                                                        float* __restrict__ out) {
    extern __shared__ char smem[];
    const uint32_t smb = smem_u32(smem);

    const int m0  = blockIdx.x * 64;
    const int tid = threadIdx.x;
    const int w   = tid >> 5;
    const int lane = tid & 31;

    {
        const uint32_t base = smb;
        for (int idx = tid; idx < 1536; idx += 128) {
            int arr = idx >> 9, rem = idx & 511, r = rem >> 3, ch = rem & 7;
            const __half* src;
            if      (arr == 0) src = g_attnh + (size_t)(m0 + r) * HID + ch * 8;
            else if (arr == 1) src = g_attnl + (size_t)(m0 + r) * HID + ch * 8;
            else               src = g_WoTh + (size_t)r * HID + ch * 8;
            CPA(base + arr * 9216 + r * 144 + ch * 16, src);
        }
        CPC();
    }

    float sacc[8][4];
    #pragma unroll
    for (int j = 0; j < 8; j++)
        #pragma unroll
        for (int e = 0; e < 4; e++) sacc[j][e] = 0.f;

    const uint32_t a_off = (uint32_t)((w * 16 + (lane & 15)) * 144 + (lane >> 4) * 16);
    const uint32_t b_off = (uint32_t)(((lane & 7) + ((lane >> 4) & 1) * 8) * 144 + ((lane >> 3) & 1) * 16);

    for (int kt = 0; kt < 16; kt++) {
        const int buf = kt & 1;
        if (kt < 15) {
            const int nk0 = (kt + 1) * 64;
            const uint32_t base = smb + (buf ^ 1) * 27648;
            for (int idx = tid; idx < 1536; idx += 128) {
                int arr = idx >> 9, rem = idx & 511, r = rem >> 3, ch = rem & 7;
                const __half* src;
                if      (arr == 0) src = g_attnh + (size_t)(m0 + r) * HID + nk0 + ch * 8;
                else if (arr == 1) src = g_attnl + (size_t)(m0 + r) * HID + nk0 + ch * 8;
                else               src = g_WoTh + (size_t)r * HID + nk0 + ch * 8;
                CPA(base + arr * 9216 + r * 144 + ch * 16, src);
            }
            CPC();
            CPW1();
        } else {
            CPW0();
        }
        __syncthreads();

        const uint32_t bb = smb + buf * 27648;
        const uint32_t abase = bb + a_off;
        const uint32_t bbase = bb + 18432 + b_off;

        #pragma unroll
        for (int kk = 0; kk < 4; kk++) {
            uint32_t ah[4], al[4];
            ldm_x4(ah, abase + kk * 32);
            ldm_x4(al, abase + kk * 32 + 9216);
            #pragma unroll
            for (int jj = 0; jj < 4; jj++) {
                uint32_t bhr[4];
                ldm_x4(bhr, bbase + (uint32_t)(jj * 16 * 144 + kk * 32));
                mma16816(sacc[2*jj],   ah[0], ah[1], ah[2], ah[3], bhr[0], bhr[1]);
                mma16816(sacc[2*jj],   al[0], al[1], al[2], al[3], bhr[0], bhr[1]);
                mma16816(sacc[2*jj+1], ah[0], ah[1], ah[2], ah[3], bhr[2], bhr[3]);
                mma16816(sacc[2*jj+1], al[0], al[1], al[2], al[3], bhr[2], bhr[3]);
            }
        }
        __syncthreads();
    }

    const int r0 = w * 16 + (lane >> 2);
    #pragma unroll
    for (int j = 0; j < 8; j++) {
        const int c = j * 8 + 2 * (lane & 3);
        out[(size_t)(m0 + r0) * DD + c]     = sacc[j][0] + bo[c];
        out[(size_t)(m0 + r0) * DD + c + 1] = sacc[j][1] + bo[c + 1];
        out[(size_t)(m0 + r0 + 8) * DD + c]     = sacc[j][2] + bo[c];
        out[(size_t)(m0 + r0 + 8) * DD + c + 1] = sacc[j][3] + bo[c + 1];
    }
}

// ---------------------------------------------------------------------------
extern "C" void kernel_launch(void* const* d_in, const int* in_sizes, int n_in,
                              void* d_out, int out_size) {
    (void)in_sizes; (void)n_in; (void)out_size;
    const float* x  = (const float*)d_in[0];
    const float* Wq = (const float*)d_in[1];
    const float* bq = (const float*)d_in[2];
    const float* Wk = (const float*)d_in[3];
    const float* bk = (const float*)d_in[4];
    const float* Wv = (const float*)d_in[5];
    const float* bv = (const float*)d_in[6];
    const float* Wo = (const float*)d_in[7];
    const float* bo = (const float*)d_in[8];
    float* out = (float*)d_out;

    prep_kernel<<<1024, 256>>>(x, Wq, Wk, Wv, Wo);

    qkv_mma_kernel<<<dim3(BS / 64, HID / 64, 3), 128>>>(bq, bk, bv);

    cudaFuncSetAttribute(attn_kernel, cudaFuncAttributeMaxDynamicSharedMemorySize, ATTN_SMEM);
    attn_kernel<<<dim3(SS / 128, HH, BB), 256, ATTN_SMEM>>>();

    cudaFuncSetAttribute(oproj_mma_kernel, cudaFuncAttributeMaxDynamicSharedMemorySize, OPROJ_SMEM);
    oproj_mma_kernel<<<BS / 64, 128, OPROJ_SMEM>>>(bo, out);
}

// round 12
// speedup vs baseline: 6.9947x; 1.0029x over previous
#include <cuda_runtime.h>
#include <cuda_fp16.h>
#include <math.h>
#include <stdint.h>

#define BB 4
#define SS 2048
#define HH 16
#define DD 64
#define HID 1024
#define BS (BB*SS)
#define LOG2E 1.4426950408889634f

// ---------------- scratch (device globals: allocation-free rule) ------------
__device__ __half g_xh[BS*DD];           // x split (compensated operand)
__device__ __half g_xl[BS*DD];
__device__ __half g_WTh[3*HID*DD];       // QKV W^T hi only: [which][n][k]
__device__ __half g_WoTh[DD*HID];        // Wo^T hi only: [n][k]
// Q pre-scaled by (1/sqrt(D)) * log2(e). All [b,h,s,d]. All hi-only.
__device__ __half g_Qh[BB*HH*SS*DD];
__device__ __half g_Kh[BB*HH*SS*DD];
__device__ __half g_Vh[BB*HH*SS*DD];
__device__ __half g_attnh[BS*HID];       // attn out split, [B,S,HID]
__device__ __half g_attnl[BS*HID];

// ---------------- helpers ---------------------------------------------------
static __device__ __forceinline__ uint32_t smem_u32(const void* p) {
    return (uint32_t)__cvta_generic_to_shared(p);
}
static __device__ __forceinline__ void ldm_x4(uint32_t* r, uint32_t addr) {
    asm volatile("ldmatrix.sync.aligned.m8n8.x4.shared.b16 {%0,%1,%2,%3}, [%4];"
                 : "=r"(r[0]), "=r"(r[1]), "=r"(r[2]), "=r"(r[3]) : "r"(addr));
}
static __device__ __forceinline__ void ldm_x4_t(uint32_t* r, uint32_t addr) {
    asm volatile("ldmatrix.sync.aligned.m8n8.x4.trans.shared.b16 {%0,%1,%2,%3}, [%4];"
                 : "=r"(r[0]), "=r"(r[1]), "=r"(r[2]), "=r"(r[3]) : "r"(addr));
}
static __device__ __forceinline__ void mma16816(float* c,
                                                uint32_t a0, uint32_t a1, uint32_t a2, uint32_t a3,
                                                uint32_t b0, uint32_t b1) {
    asm volatile(
        "mma.sync.aligned.m16n8k16.row.col.f32.f16.f16.f32 "
        "{%0,%1,%2,%3}, {%4,%5,%6,%7}, {%8,%9}, {%0,%1,%2,%3};"
        : "+f"(c[0]), "+f"(c[1]), "+f"(c[2]), "+f"(c[3])
        : "r"(a0), "r"(a1), "r"(a2), "r"(a3), "r"(b0), "r"(b1));
}
static __device__ __forceinline__ uint32_t pack2h(float f0, float f1) {
    __half2 t = __halves2half2(__float2half_rn(f0), __float2half_rn(f1));
    return *reinterpret_cast<uint32_t*>(&t);
}
static __device__ __forceinline__ float ex2(float x) {
    float y;
    asm("ex2.approx.ftz.f32 %0, %1;" : "=f"(y) : "f"(x));
    return y;
}
static __device__ __forceinline__ uint32_t h2ex2(uint32_t x) {
    uint32_t y;
    asm("ex2.approx.f16x2 %0, %1;" : "=r"(y) : "r"(x));
    return y;
}
#define ONES2H 0x3C003C00u   // half2(1.0, 1.0)
#define CPA(dst, src) asm volatile("cp.async.ca.shared.global [%0], [%1], 16;" :: "r"(dst), "l"(src))
#define CPC()   asm volatile("cp.async.commit_group;" ::: "memory")
#define CPW1()  asm volatile("cp.async.wait_group 1;" ::: "memory")
#define CPW0()  asm volatile("cp.async.wait_group 0;" ::: "memory")

// ---------------------------------------------------------------------------
// Kernel 0: prep — split x to fp16 hi/lo; W^T, Wo^T to fp16 hi.
// ---------------------------------------------------------------------------
#define NX (BS*DD)          // 524288
#define NW (3*HID*DD)       // 196608
#define NWO (DD*HID)        // 65536
__global__ void prep_kernel(const float* __restrict__ x,
                            const float* __restrict__ Wq,
                            const float* __restrict__ Wk,
                            const float* __restrict__ Wv,
                            const float* __restrict__ Wo) {
    for (int idx = blockIdx.x * blockDim.x + threadIdx.x; idx < NX + NW + NWO;
         idx += gridDim.x * blockDim.x) {
        if (idx < NX) {
            float f = x[idx];
            __half hi = __float2half_rn(f);
            g_xh[idx] = hi;
            g_xl[idx] = __float2half_rn(f - __half2float(hi));
        } else if (idx < NX + NW) {
            int r = idx - NX;
            int which = r >> 16;
            int t = r & 65535;
            int n = t >> 6, k = t & 63;
            const float* W = (which == 0) ? Wq : (which == 1) ? Wk : Wv;
            g_WTh[r] = __float2half_rn(W[k * HID + n]);
        } else {
            int r = idx - NX - NW;          // r = n*1024 + k
            int n = r >> 10, k = r & 1023;
            g_WoTh[r] = __float2half_rn(Wo[k * DD + n]);
        }
    }
}

// ---------------------------------------------------------------------------
// Kernel 1: QKV projection via HMMA: (xh+xl) @ Wh.  All outputs hi-only.
// grid = (BS/64, HID/64, 3), block = 128.
// ---------------------------------------------------------------------------
__global__ void __launch_bounds__(128) qkv_mma_kernel(const float* __restrict__ bq,
                                                      const float* __restrict__ bk,
                                                      const float* __restrict__ bv) {
    __shared__ __align__(16) char smem[3 * 9216];   // XH, XL, WH
    const uint32_t smb = smem_u32(smem);

    const int m0    = blockIdx.x * 64;
    const int h     = blockIdx.y;
    const int which = blockIdx.z;
    const int c0    = h * 64;

    const int tid  = threadIdx.x;
    const int w    = tid >> 5;
    const int lane = tid & 31;

    const float* bp = (which == 0) ? bq : (which == 1) ? bk : bv;

    for (int idx = tid; idx < 1536; idx += 128) {
        int arr = idx >> 9, rem = idx & 511, r = rem >> 3, ch = rem & 7;
        const __half* src;
        if      (arr == 0) src = g_xh  + (size_t)(m0 + r) * DD + ch * 8;
        else if (arr == 1) src = g_xl  + (size_t)(m0 + r) * DD + ch * 8;
        else               src = g_WTh + (size_t)which * HID * DD + (size_t)(c0 + r) * DD + ch * 8;
        *(uint4*)(smem + arr * 9216 + r * 144 + ch * 16) = *(const uint4*)src;
    }
    __syncthreads();

    uint32_t ah[4][4], al[4][4];
    {
        const uint32_t abase = smb + (uint32_t)((w * 16 + (lane & 15)) * 144 + (lane >> 4) * 16);
        #pragma unroll
        for (int kk = 0; kk < 4; kk++) {
            ldm_x4(ah[kk], abase + kk * 32);
            ldm_x4(al[kk], abase + kk * 32 + 9216);
        }
    }
    const uint32_t bbase = smb + 18432 +
        (uint32_t)(((lane & 7) + ((lane >> 4) & 1) * 8) * 144 + ((lane >> 3) & 1) * 16);

    float sacc[8][4];
    #pragma unroll
    for (int j = 0; j < 8; j++)
        #pragma unroll
        for (int e = 0; e < 4; e++) sacc[j][e] = 0.f;

    #pragma unroll
    for (int jj = 0; jj < 4; jj++) {
        #pragma unroll
        for (int kk = 0; kk < 4; kk++) {
            uint32_t bhr[4];
            ldm_x4(bhr, bbase + (uint32_t)(jj * 16 * 144 + kk * 32));
            mma16816(sacc[2*jj],   ah[kk][0], ah[kk][1], ah[kk][2], ah[kk][3], bhr[0], bhr[1]);
            mma16816(sacc[2*jj],   al[kk][0], al[kk][1], al[kk][2], al[kk][3], bhr[0], bhr[1]);
            mma16816(sacc[2*jj+1], ah[kk][0], ah[kk][1], ah[kk][2], ah[kk][3], bhr[2], bhr[3]);
            mma16816(sacc[2*jj+1], al[kk][0], al[kk][1], al[kk][2], al[kk][3], bhr[2], bhr[3]);
        }
    }

    const float scale = (which == 0) ? 0.125f * LOG2E : 1.0f;
    __half* Ah = (which == 0) ? g_Qh : (which == 1) ? g_Kh : g_Vh;
    const int b   = m0 >> 11;
    const int ss0 = m0 & 2047;
    const int r0  = w * 16 + (lane >> 2);
    const size_t base0 = (((size_t)b * HH + h) * SS + (ss0 + r0)) * DD;
    const size_t base1 = base0 + (size_t)8 * DD;
    #pragma unroll
    for (int j = 0; j < 8; j++) {
        const int c = j * 8 + 2 * (lane & 3);
        *(uint32_t*)&Ah[base0 + c] = pack2h((sacc[j][0] + bp[c0 + c]) * scale,
                                            (sacc[j][1] + bp[c0 + c + 1]) * scale);
        *(uint32_t*)&Ah[base1 + c] = pack2h((sacc[j][2] + bp[c0 + c]) * scale,
                                            (sacc[j][3] + bp[c0 + c + 1]) * scale);
    }
}

// ---------------------------------------------------------------------------
// Kernel 2: causal flash attention (fp16 HMMA, hi-only operands).
// Softmax: half2 exp (ex2.approx.f16x2) + row-sum via B=ones MMA.
// grid = (S/128, H, B), block = 256.  qt order reversed for load balance.
// ---------------------------------------------------------------------------
#define SQH 0
#define SKV 18432            // two buffers of 36864 (KH, VH @ 18432 each)
#define ATTN_SMEM (18432 + 2*36864)   // 92160

__global__ void __launch_bounds__(256) attn_kernel() {
    extern __shared__ char smem[];
    const uint32_t smb = smem_u32(smem);

    const int qt = gridDim.x - 1 - blockIdx.x;   // heavy tiles first
    const int h  = blockIdx.y;
    const int b  = blockIdx.z;
    const int q0 = qt * 128;

    const int tid  = threadIdx.x;
    const int w    = tid >> 5;
    const int lane = tid & 31;

    const size_t bh = (size_t)b * HH + h;
    const __half* Qh = g_Qh + (bh * SS + q0) * DD;
    const __half* Kh = g_Kh + bh * SS * DD;
    const __half* Vh = g_Vh + bh * SS * DD;

    const int ktmax = qt;   // 128-key tiles, kt <= qt

    // prefetch K/V tile 0 into buffer 0 (K: 128x64, V: 128x64)
    {
        const uint32_t base = smb + SKV;
        for (int idx = tid; idx < 2048; idx += 256) {
            int arr = idx >> 10, rem = idx & 1023, r = rem >> 3, ch = rem & 7;
            const __half* src = (arr == 0) ? (Kh + (size_t)r * DD + ch * 8)
                                           : (Vh + (size_t)r * DD + ch * 8);
            CPA(base + arr * 18432 + r * 144 + ch * 16, src);
        }
        CPC();
    }

    // load Q tile (hi only)
    for (int idx = tid; idx < 1024; idx += 256) {
        int r = idx >> 3, ch = idx & 7;
        *(uint4*)(smem + SQH + r * 144 + ch * 16) = *(const uint4*)(Qh + (size_t)r * DD + ch * 8);
    }
    __syncthreads();

    uint32_t qh[4][4];
    {
        const uint32_t qbase = smb + SQH + (uint32_t)((w * 16 + (lane & 15)) * 144 + (lane >> 4) * 16);
        #pragma unroll
        for (int kk = 0; kk < 4; kk++) ldm_x4(qh[kk], qbase + kk * 32);
    }

    float o[8][4];
    #pragma unroll
    for (int j = 0; j < 8; j++)
        #pragma unroll
        for (int e = 0; e < 4; e++) o[j][e] = 0.f;
    float lacc[4] = {0.f, 0.f, 0.f, 0.f};   // row-sum accumulator (B=ones MMA)
    float m0 = -1e30f, m1 = -1e30f;

    const int rg0  = q0 + w * 16 + (lane >> 2);
    const int wmax = q0 + w * 16 + 15;

    const uint32_t klane = (uint32_t)(((lane & 7) + ((lane >> 4) & 1) * 8) * 144 + ((lane >> 3) & 1) * 16);
    const uint32_t vlane = (uint32_t)(((lane & 7) + ((lane >> 3) & 1) * 8) * 144 + ((lane >> 4) & 1) * 16);

    for (int kt = 0; kt <= ktmax; kt++) {
        const int buf = kt & 1;

        if (kt < ktmax) {
            const int nk0 = (kt + 1) * 128;
            const uint32_t base = smb + SKV + (buf ^ 1) * 36864;
            for (int idx = tid; idx < 2048; idx += 256) {
                int arr = idx >> 10, rem = idx & 1023, r = rem >> 3, ch = rem & 7;
                const __half* src = (arr == 0) ? (Kh + (size_t)(nk0 + r) * DD + ch * 8)
                                               : (Vh + (size_t)(nk0 + r) * DD + ch * 8);
                CPA(base + arr * 18432 + r * 144 + ch * 16, src);
            }
            CPC();
            CPW1();
        } else {
            CPW0();
        }
        __syncthreads();

        const uint32_t kvb = smb + SKV + buf * 36864;

        #pragma unroll
        for (int hf = 0; hf < 2; hf++) {
            const int khalf0 = kt * 128 + hf * 64;
            int jjn = (wmax >= khalf0) ? (((wmax - khalf0) >> 4) + 1) : 0;
            if (jjn > 4) jjn = 4;
            if (jjn == 0) continue;

            const uint32_t kbase = kvb + (uint32_t)(hf * 64 * 144) + klane;
            const uint32_t vbase = kvb + 18432 + (uint32_t)(hf * 64 * 144) + vlane;

            // ---- S = Qh Kh^T ----
            float sacc[8][4];
            #pragma unroll
            for (int j = 0; j < 8; j++)
                #pragma unroll
                for (int e = 0; e < 4; e++) sacc[j][e] = 0.f;

            #pragma unroll
            for (int jj = 0; jj < 4; jj++) {
                if (jj >= jjn) break;
                #pragma unroll
                for (int kk = 0; kk < 4; kk++) {
                    uint32_t bhr[4];
                    ldm_x4(bhr, kbase + (uint32_t)(jj * 16 * 144 + kk * 32));
                    mma16816(sacc[2*jj],   qh[kk][0], qh[kk][1], qh[kk][2], qh[kk][3], bhr[0], bhr[1]);
                    mma16816(sacc[2*jj+1], qh[kk][0], qh[kk][1], qh[kk][2], qh[kk][3], bhr[2], bhr[3]);
                }
            }
            // blank untouched groups (so max is unaffected; exp gives 0)
            #pragma unroll
            for (int j = 0; j < 8; j++)
                if (j >= 2 * jjn) {
                    sacc[j][0] = sacc[j][1] = sacc[j][2] = sacc[j][3] = -1e30f;
                }

            // ---- causal element mask (only if this half straddles diag) ----
            if (khalf0 + 63 > rg0) {
                #pragma unroll
                for (int j = 0; j < 8; j++) {
                    const int cbase = khalf0 + j * 8 + 2 * (lane & 3);
                    if (cbase     > rg0)     sacc[j][0] = -1e30f;
                    if (cbase + 1 > rg0)     sacc[j][1] = -1e30f;
                    if (cbase     > rg0 + 8) sacc[j][2] = -1e30f;
                    if (cbase + 1 > rg0 + 8) sacc[j][3] = -1e30f;
                }
            }

            // ---- online softmax (base-2), exp in half2 ----
            float mx0 = -1e30f, mx1 = -1e30f;
            #pragma unroll
            for (int j = 0; j < 8; j++) {
                mx0 = fmaxf(mx0, fmaxf(sacc[j][0], sacc[j][1]));
                mx1 = fmaxf(mx1, fmaxf(sacc[j][2], sacc[j][3]));
            }
            mx0 = fmaxf(mx0, __shfl_xor_sync(0xffffffffu, mx0, 1));
            mx0 = fmaxf(mx0, __shfl_xor_sync(0xffffffffu, mx0, 2));
            mx1 = fmaxf(mx1, __shfl_xor_sync(0xffffffffu, mx1, 1));
            mx1 = fmaxf(mx1, __shfl_xor_sync(0xffffffffu, mx1, 2));

            const float nm0 = fmaxf(m0, mx0);
            const float nm1 = fmaxf(m1, mx1);
            const float corr0 = ex2(m0 - nm0);
            const float corr1 = ex2(m1 - nm1);
            m0 = nm0; m1 = nm1;

            uint32_t ph[8][2];
            #pragma unroll
            for (int j = 0; j < 8; j++) {
                ph[j][0] = h2ex2(pack2h(sacc[j][0] - nm0, sacc[j][1] - nm0));
                ph[j][1] = h2ex2(pack2h(sacc[j][2] - nm1, sacc[j][3] - nm1));
            }

            // rescale running O and l
            #pragma unroll
            for (int j = 0; j < 8; j++) {
                o[j][0] *= corr0; o[j][1] *= corr0;
                o[j][2] *= corr1; o[j][3] *= corr1;
            }
            lacc[0] *= corr0; lacc[1] *= corr0;
            lacc[2] *= corr1; lacc[3] *= corr1;

            // ---- O += Ph Vh;  l += Ph @ ones ----
            #pragma unroll
            for (int kk = 0; kk < 4; kk++) {
                if (kk >= jjn) break;
                mma16816(lacc, ph[2*kk][0], ph[2*kk][1], ph[2*kk+1][0], ph[2*kk+1][1], ONES2H, ONES2H);
                #pragma unroll
                for (int dd = 0; dd < 4; dd++) {
                    uint32_t vh[4];
                    ldm_x4_t(vh, vbase + (uint32_t)(kk * 16 * 144 + dd * 32));
                    mma16816(o[2*dd],   ph[2*kk][0], ph[2*kk][1], ph[2*kk+1][0], ph[2*kk+1][1], vh[0], vh[1]);
                    mma16816(o[2*dd+1], ph[2*kk][0], ph[2*kk][1], ph[2*kk+1][0], ph[2*kk+1][1], vh[2], vh[3]);
                }
            }
        }
        __syncthreads();
    }

    // ---- epilogue: normalize, split hi/lo, write fp16 [B,S,HID] ----
    const float inv0 = 1.f / lacc[0];
    const float inv1 = 1.f / lacc[2];
    const size_t db0 = ((size_t)b * SS + rg0) * HID + h * 64;
    const size_t db1 = db0 + (size_t)8 * HID;
    #pragma unroll
    for (int j = 0; j < 8; j++) {
        const int c = j * 8 + 2 * (lane & 3);
        {
            float v0 = o[j][0] * inv0, v1 = o[j][1] * inv0;
            __half h0 = __float2half_rn(v0), h1 = __float2half_rn(v1);
            *(uint32_t*)&g_attnh[db0 + c] = pack2h(v0, v1);
            *(uint32_t*)&g_attnl[db0 + c] = pack2h(v0 - __half2float(h0), v1 - __half2float(h1));
        }
        {
            float v0 = o[j][2] * inv1, v1 = o[j][3] * inv1;
            __half h0 = __float2half_rn(v0), h1 = __float2half_rn(v1);
            *(uint32_t*)&g_attnh[db1 + c] = pack2h(v0, v1);
            *(uint32_t*)&g_attnl[db1 + c] = pack2h(v0 - __half2float(h0), v1 - __half2float(h1));
        }
    }
}

// ---------------------------------------------------------------------------
// Kernel 3: output projection via HMMA: (Ah+Al) @ Woh + bo.
// grid = BS/64, block = 128.  K=1024 in 16 double-buffered steps.
// ---------------------------------------------------------------------------
// per buffer: AH, AL, WH @ 9216 each = 27648; two buffers = 55296.
#define OPROJ_SMEM (2 * 27648)
__global__ void __launch_bounds__(128) oproj_mma_kernel(const float* __restrict__ bo,
                                                        float* __restrict__ out) {
    extern __shared__ char smem[];
    const uint32_t smb = smem_u32(smem);

    const int m0  = blockIdx.x * 64;
    const int tid = threadIdx.x;
    const int w   = tid >> 5;
    const int lane = tid & 31;

    {
        const uint32_t base = smb;
        for (int idx = tid; idx < 1536; idx += 128) {
            int arr = idx >> 9, rem = idx & 511, r = rem >> 3, ch = rem & 7;
            const __half* src;
            if      (arr == 0) src = g_attnh + (size_t)(m0 + r) * HID + ch * 8;
            else if (arr == 1) src = g_attnl + (size_t)(m0 + r) * HID + ch * 8;
            else               src = g_WoTh + (size_t)r * HID + ch * 8;
            CPA(base + arr * 9216 + r * 144 + ch * 16, src);
        }
        CPC();
    }

    float sacc[8][4];
    #pragma unroll
    for (int j = 0; j < 8; j++)
        #pragma unroll
        for (int e = 0; e < 4; e++) sacc[j][e] = 0.f;

    const uint32_t a_off = (uint32_t)((w * 16 + (lane & 15)) * 144 + (lane >> 4) * 16);
    const uint32_t b_off = (uint32_t)(((lane & 7) + ((lane >> 4) & 1) * 8) * 144 + ((lane >> 3) & 1) * 16);

    for (int kt = 0; kt < 16; kt++) {
        const int buf = kt & 1;
        if (kt < 15) {
            const int nk0 = (kt + 1) * 64;
            const uint32_t base = smb + (buf ^ 1) * 27648;
            for (int idx = tid; idx < 1536; idx += 128) {
                int arr = idx >> 9, rem = idx & 511, r = rem >> 3, ch = rem & 7;
                const __half* src;
                if      (arr == 0) src = g_attnh + (size_t)(m0 + r) * HID + nk0 + ch * 8;
                else if (arr == 1) src = g_attnl + (size_t)(m0 + r) * HID + nk0 + ch * 8;
                else               src = g_WoTh + (size_t)r * HID + nk0 + ch * 8;
                CPA(base + arr * 9216 + r * 144 + ch * 16, src);
            }
            CPC();
            CPW1();
        } else {
            CPW0();
        }
        __syncthreads();

        const uint32_t bb = smb + buf * 27648;
        const uint32_t abase = bb + a_off;
        const uint32_t bbase = bb + 18432 + b_off;

        #pragma unroll
        for (int kk = 0; kk < 4; kk++) {
            uint32_t ah[4], al[4];
            ldm_x4(ah, abase + kk * 32);
            ldm_x4(al, abase + kk * 32 + 9216);
            #pragma unroll
            for (int jj = 0; jj < 4; jj++) {
                uint32_t bhr[4];
                ldm_x4(bhr, bbase + (uint32_t)(jj * 16 * 144 + kk * 32));
                mma16816(sacc[2*jj],   ah[0], ah[1], ah[2], ah[3], bhr[0], bhr[1]);
                mma16816(sacc[2*jj],   al[0], al[1], al[2], al[3], bhr[0], bhr[1]);
                mma16816(sacc[2*jj+1], ah[0], ah[1], ah[2], ah[3], bhr[2], bhr[3]);
                mma16816(sacc[2*jj+1], al[0], al[1], al[2], al[3], bhr[2], bhr[3]);
            }
        }
        __syncthreads();
    }

    const int r0 = w * 16 + (lane >> 2);
    #pragma unroll
    for (int j = 0; j < 8; j++) {
        const int c = j * 8 + 2 * (lane & 3);
        out[(size_t)(m0 + r0) * DD + c]     = sacc[j][0] + bo[c];
        out[(size_t)(m0 + r0) * DD + c + 1] = sacc[j][1] + bo[c + 1];
        out[(size_t)(m0 + r0 + 8) * DD + c]     = sacc[j][2] + bo[c];
        out[(size_t)(m0 + r0 + 8) * DD + c + 1] = sacc[j][3] + bo[c + 1];
    }
}

// ---------------------------------------------------------------------------
extern "C" void kernel_launch(void* const* d_in, const int* in_sizes, int n_in,
                              void* d_out, int out_size) {
    (void)in_sizes; (void)n_in; (void)out_size;
    const float* x  = (const float*)d_in[0];
    const float* Wq = (const float*)d_in[1];
    const float* bq = (const float*)d_in[2];
    const float* Wk = (const float*)d_in[3];
    const float* bk = (const float*)d_in[4];
    const float* Wv = (const float*)d_in[5];
    const float* bv = (const float*)d_in[6];
    const float* Wo = (const float*)d_in[7];
    const float* bo = (const float*)d_in[8];
    float* out = (float*)d_out;

    prep_kernel<<<1024, 256>>>(x, Wq, Wk, Wv, Wo);

    qkv_mma_kernel<<<dim3(BS / 64, HID / 64, 3), 128>>>(bq, bk, bv);

    cudaFuncSetAttribute(attn_kernel, cudaFuncAttributeMaxDynamicSharedMemorySize, ATTN_SMEM);
    attn_kernel<<<dim3(SS / 128, HH, BB), 256, ATTN_SMEM>>>();

    cudaFuncSetAttribute(oproj_mma_kernel, cudaFuncAttributeMaxDynamicSharedMemorySize, OPROJ_SMEM);
    oproj_mma_kernel<<<BS / 64, 128, OPROJ_SMEM>>>(bo, out);
}

// round 13
// speedup vs baseline: 7.5275x; 1.0762x over previous
#include <cuda_runtime.h>
#include <cuda_fp16.h>
#include <math.h>
#include <stdint.h>

#define BB 4
#define SS 2048
#define HH 16
#define DD 64
#define HID 1024
#define BS (BB*SS)
#define LOG2E 1.4426950408889634f

// ---------------- scratch (device globals: allocation-free rule) ------------
__device__ __half g_xh[BS*DD];           // x split (compensated operand)
__device__ __half g_xl[BS*DD];
__device__ __half g_WTh[3*HID*DD];       // QKV W^T hi only: [which][n][k]
__device__ __half g_WoTh[DD*HID];        // Wo^T hi only: [n][k]
// Q pre-scaled by (1/sqrt(D)) * log2(e). All [b,h,s,d]. All hi-only.
__device__ __half g_Qh[BB*HH*SS*DD];
__device__ __half g_Kh[BB*HH*SS*DD];
__device__ __half g_Vh[BB*HH*SS*DD];
__device__ __half g_attnh[BS*HID];       // attn out split, [B,S,HID]
__device__ __half g_attnl[BS*HID];

// ---------------- helpers ---------------------------------------------------
static __device__ __forceinline__ uint32_t smem_u32(const void* p) {
    return (uint32_t)__cvta_generic_to_shared(p);
}
static __device__ __forceinline__ void ldm_x4(uint32_t* r, uint32_t addr) {
    asm volatile("ldmatrix.sync.aligned.m8n8.x4.shared.b16 {%0,%1,%2,%3}, [%4];"
                 : "=r"(r[0]), "=r"(r[1]), "=r"(r[2]), "=r"(r[3]) : "r"(addr));
}
static __device__ __forceinline__ void ldm_x4_t(uint32_t* r, uint32_t addr) {
    asm volatile("ldmatrix.sync.aligned.m8n8.x4.trans.shared.b16 {%0,%1,%2,%3}, [%4];"
                 : "=r"(r[0]), "=r"(r[1]), "=r"(r[2]), "=r"(r[3]) : "r"(addr));
}
static __device__ __forceinline__ void mma16816(float* c,
                                                uint32_t a0, uint32_t a1, uint32_t a2, uint32_t a3,
                                                uint32_t b0, uint32_t b1) {
    asm volatile(
        "mma.sync.aligned.m16n8k16.row.col.f32.f16.f16.f32 "
        "{%0,%1,%2,%3}, {%4,%5,%6,%7}, {%8,%9}, {%0,%1,%2,%3};"
        : "+f"(c[0]), "+f"(c[1]), "+f"(c[2]), "+f"(c[3])
        : "r"(a0), "r"(a1), "r"(a2), "r"(a3), "r"(b0), "r"(b1));
}
static __device__ __forceinline__ uint32_t pack2h(float f0, float f1) {
    __half2 t = __halves2half2(__float2half_rn(f0), __float2half_rn(f1));
    return *reinterpret_cast<uint32_t*>(&t);
}
static __device__ __forceinline__ float ex2(float x) {
    float y;
    asm("ex2.approx.ftz.f32 %0, %1;" : "=f"(y) : "f"(x));
    return y;
}
static __device__ __forceinline__ uint32_t h2ex2(uint32_t x) {
    uint32_t y;
    asm("ex2.approx.f16x2 %0, %1;" : "=r"(y) : "r"(x));
    return y;
}
#define ONES2H 0x3C003C00u   // half2(1.0, 1.0)
#define CPA(dst, src) asm volatile("cp.async.ca.shared.global [%0], [%1], 16;" :: "r"(dst), "l"(src))
#define CPC()   asm volatile("cp.async.commit_group;" ::: "memory")
#define CPW1()  asm volatile("cp.async.wait_group 1;" ::: "memory")
#define CPW0()  asm volatile("cp.async.wait_group 0;" ::: "memory")

// ---------------------------------------------------------------------------
// Kernel 0: prep — split x to fp16 hi/lo; W^T, Wo^T to fp16 hi.
// ---------------------------------------------------------------------------
#define NX (BS*DD)          // 524288
#define NW (3*HID*DD)       // 196608
#define NWO (DD*HID)        // 65536
__global__ void prep_kernel(const float* __restrict__ x,
                            const float* __restrict__ Wq,
                            const float* __restrict__ Wk,
                            const float* __restrict__ Wv,
                            const float* __restrict__ Wo) {
    for (int idx = blockIdx.x * blockDim.x + threadIdx.x; idx < NX + NW + NWO;
         idx += gridDim.x * blockDim.x) {
        if (idx < NX) {
            float f = x[idx];
            __half hi = __float2half_rn(f);
            g_xh[idx] = hi;
            g_xl[idx] = __float2half_rn(f - __half2float(hi));
        } else if (idx < NX + NW) {
            int r = idx - NX;
            int which = r >> 16;
            int t = r & 65535;
            int n = t >> 6, k = t & 63;
            const float* W = (which == 0) ? Wq : (which == 1) ? Wk : Wv;
            g_WTh[r] = __float2half_rn(W[k * HID + n]);
        } else {
            int r = idx - NX - NW;          // r = n*1024 + k
            int n = r >> 10, k = r & 1023;
            g_WoTh[r] = __float2half_rn(Wo[k * DD + n]);
        }
    }
}

// ---------------------------------------------------------------------------
// Kernel 1: QKV projection via HMMA: (xh+xl) @ Wh.  All outputs hi-only.
// grid = (BS/64, HID/64, 3), block = 128.
// ---------------------------------------------------------------------------
__global__ void __launch_bounds__(128) qkv_mma_kernel(const float* __restrict__ bq,
                                                      const float* __restrict__ bk,
                                                      const float* __restrict__ bv) {
    __shared__ __align__(16) char smem[3 * 9216];   // XH, XL, WH
    const uint32_t smb = smem_u32(smem);

    const int m0    = blockIdx.x * 64;
    const int h     = blockIdx.y;
    const int which = blockIdx.z;
    const int c0    = h * 64;

    const int tid  = threadIdx.x;
    const int w    = tid >> 5;
    const int lane = tid & 31;

    const float* bp = (which == 0) ? bq : (which == 1) ? bk : bv;

    for (int idx = tid; idx < 1536; idx += 128) {
        int arr = idx >> 9, rem = idx & 511, r = rem >> 3, ch = rem & 7;
        const __half* src;
        if      (arr == 0) src = g_xh  + (size_t)(m0 + r) * DD + ch * 8;
        else if (arr == 1) src = g_xl  + (size_t)(m0 + r) * DD + ch * 8;
        else               src = g_WTh + (size_t)which * HID * DD + (size_t)(c0 + r) * DD + ch * 8;
        *(uint4*)(smem + arr * 9216 + r * 144 + ch * 16) = *(const uint4*)src;
    }
    __syncthreads();

    uint32_t ah[4][4], al[4][4];
    {
        const uint32_t abase = smb + (uint32_t)((w * 16 + (lane & 15)) * 144 + (lane >> 4) * 16);
        #pragma unroll
        for (int kk = 0; kk < 4; kk++) {
            ldm_x4(ah[kk], abase + kk * 32);
            ldm_x4(al[kk], abase + kk * 32 + 9216);
        }
    }
    const uint32_t bbase = smb + 18432 +
        (uint32_t)(((lane & 7) + ((lane >> 4) & 1) * 8) * 144 + ((lane >> 3) & 1) * 16);

    float sacc[8][4];
    #pragma unroll
    for (int j = 0; j < 8; j++)
        #pragma unroll
        for (int e = 0; e < 4; e++) sacc[j][e] = 0.f;

    #pragma unroll
    for (int jj = 0; jj < 4; jj++) {
        #pragma unroll
        for (int kk = 0; kk < 4; kk++) {
            uint32_t bhr[4];
            ldm_x4(bhr, bbase + (uint32_t)(jj * 16 * 144 + kk * 32));
            mma16816(sacc[2*jj],   ah[kk][0], ah[kk][1], ah[kk][2], ah[kk][3], bhr[0], bhr[1]);
            mma16816(sacc[2*jj],   al[kk][0], al[kk][1], al[kk][2], al[kk][3], bhr[0], bhr[1]);
            mma16816(sacc[2*jj+1], ah[kk][0], ah[kk][1], ah[kk][2], ah[kk][3], bhr[2], bhr[3]);
            mma16816(sacc[2*jj+1], al[kk][0], al[kk][1], al[kk][2], al[kk][3], bhr[2], bhr[3]);
        }
    }

    const float scale = (which == 0) ? 0.125f * LOG2E : 1.0f;
    __half* Ah = (which == 0) ? g_Qh : (which == 1) ? g_Kh : g_Vh;
    const int b   = m0 >> 11;
    const int ss0 = m0 & 2047;
    const int r0  = w * 16 + (lane >> 2);
    const size_t base0 = (((size_t)b * HH + h) * SS + (ss0 + r0)) * DD;
    const size_t base1 = base0 + (size_t)8 * DD;
    #pragma unroll
    for (int j = 0; j < 8; j++) {
        const int c = j * 8 + 2 * (lane & 3);
        *(uint32_t*)&Ah[base0 + c] = pack2h((sacc[j][0] + bp[c0 + c]) * scale,
                                            (sacc[j][1] + bp[c0 + c + 1]) * scale);
        *(uint32_t*)&Ah[base1 + c] = pack2h((sacc[j][2] + bp[c0 + c]) * scale,
                                            (sacc[j][3] + bp[c0 + c + 1]) * scale);
    }
}

// ---------------------------------------------------------------------------
// Kernel 2: causal flash attention (fp16 HMMA, hi-only operands).
// 2 CTAs/SM for phase overlap.  grid = (S/128, H, B), block = 256.
// ---------------------------------------------------------------------------
#define SQH 0
#define SKV 18432            // two buffers of 36864 (KH, VH @ 18432 each)
#define ATTN_SMEM (18432 + 2*36864)   // 92160; x2 CTAs = 184320 < 227KB

__global__ void __launch_bounds__(256, 2) attn_kernel() {
    extern __shared__ char smem[];
    const uint32_t smb = smem_u32(smem);

    const int qt = gridDim.x - 1 - blockIdx.x;   // heavy tiles first
    const int h  = blockIdx.y;
    const int b  = blockIdx.z;
    const int q0 = qt * 128;

    const int tid  = threadIdx.x;
    const int w    = tid >> 5;
    const int lane = tid & 31;

    const size_t bh = (size_t)b * HH + h;
    const __half* Qh = g_Qh + (bh * SS + q0) * DD;
    const __half* Kh = g_Kh + bh * SS * DD;
    const __half* Vh = g_Vh + bh * SS * DD;

    const int ktmax = qt;   // 128-key tiles, kt <= qt

    // prefetch K/V tile 0 into buffer 0 (K: 128x64, V: 128x64)
    {
        const uint32_t base = smb + SKV;
        for (int idx = tid; idx < 2048; idx += 256) {
            int arr = idx >> 10, rem = idx & 1023, r = rem >> 3, ch = rem & 7;
            const __half* src = (arr == 0) ? (Kh + (size_t)r * DD + ch * 8)
                                           : (Vh + (size_t)r * DD + ch * 8);
            CPA(base + arr * 18432 + r * 144 + ch * 16, src);
        }
        CPC();
    }

    // load Q tile (hi only)
    for (int idx = tid; idx < 1024; idx += 256) {
        int r = idx >> 3, ch = idx & 7;
        *(uint4*)(smem + SQH + r * 144 + ch * 16) = *(const uint4*)(Qh + (size_t)r * DD + ch * 8);
    }
    __syncthreads();

    uint32_t qh[4][4];
    {
        const uint32_t qbase = smb + SQH + (uint32_t)((w * 16 + (lane & 15)) * 144 + (lane >> 4) * 16);
        #pragma unroll
        for (int kk = 0; kk < 4; kk++) ldm_x4(qh[kk], qbase + kk * 32);
    }

    float o[8][4];
    #pragma unroll
    for (int j = 0; j < 8; j++)
        #pragma unroll
        for (int e = 0; e < 4; e++) o[j][e] = 0.f;
    float lacc[4] = {0.f, 0.f, 0.f, 0.f};   // row-sum accumulator (B=ones MMA)
    float m0 = -1e30f, m1 = -1e30f;

    const int rg0  = q0 + w * 16 + (lane >> 2);
    const int wmax = q0 + w * 16 + 15;

    const uint32_t klane = (uint32_t)(((lane & 7) + ((lane >> 4) & 1) * 8) * 144 + ((lane >> 3) & 1) * 16);
    const uint32_t vlane = (uint32_t)(((lane & 7) + ((lane >> 3) & 1) * 8) * 144 + ((lane >> 4) & 1) * 16);

    for (int kt = 0; kt <= ktmax; kt++) {
        const int buf = kt & 1;

        if (kt < ktmax) {
            const int nk0 = (kt + 1) * 128;
            const uint32_t base = smb + SKV + (buf ^ 1) * 36864;
            for (int idx = tid; idx < 2048; idx += 256) {
                int arr = idx >> 10, rem = idx & 1023, r = rem >> 3, ch = rem & 7;
                const __half* src = (arr == 0) ? (Kh + (size_t)(nk0 + r) * DD + ch * 8)
                                               : (Vh + (size_t)(nk0 + r) * DD + ch * 8);
                CPA(base + arr * 18432 + r * 144 + ch * 16, src);
            }
            CPC();
            CPW1();
        } else {
            CPW0();
        }
        __syncthreads();

        const uint32_t kvb = smb + SKV + buf * 36864;

        #pragma unroll
        for (int hf = 0; hf < 2; hf++) {
            const int khalf0 = kt * 128 + hf * 64;
            int jjn = (wmax >= khalf0) ? (((wmax - khalf0) >> 4) + 1) : 0;
            if (jjn > 4) jjn = 4;
            if (jjn == 0) continue;

            const uint32_t kbase = kvb + (uint32_t)(hf * 64 * 144) + klane;
            const uint32_t vbase = kvb + 18432 + (uint32_t)(hf * 64 * 144) + vlane;

            // ---- S = Qh Kh^T ----
            float sacc[8][4];
            #pragma unroll
            for (int j = 0; j < 8; j++)
                #pragma unroll
                for (int e = 0; e < 4; e++) sacc[j][e] = 0.f;

            #pragma unroll
            for (int jj = 0; jj < 4; jj++) {
                if (jj >= jjn) break;
                #pragma unroll
                for (int kk = 0; kk < 4; kk++) {
                    uint32_t bhr[4];
                    ldm_x4(bhr, kbase + (uint32_t)(jj * 16 * 144 + kk * 32));
                    mma16816(sacc[2*jj],   qh[kk][0], qh[kk][1], qh[kk][2], qh[kk][3], bhr[0], bhr[1]);
                    mma16816(sacc[2*jj+1], qh[kk][0], qh[kk][1], qh[kk][2], qh[kk][3], bhr[2], bhr[3]);
                }
            }
            // blank untouched groups (so max is unaffected; exp gives 0)
            #pragma unroll
            for (int j = 0; j < 8; j++)
                if (j >= 2 * jjn) {
                    sacc[j][0] = sacc[j][1] = sacc[j][2] = sacc[j][3] = -1e30f;
                }

            // ---- causal element mask (only if this half straddles diag) ----
            if (khalf0 + 63 > rg0) {
                #pragma unroll
                for (int j = 0; j < 8; j++) {
                    const int cbase = khalf0 + j * 8 + 2 * (lane & 3);
                    if (cbase     > rg0)     sacc[j][0] = -1e30f;
                    if (cbase + 1 > rg0)     sacc[j][1] = -1e30f;
                    if (cbase     > rg0 + 8) sacc[j][2] = -1e30f;
                    if (cbase + 1 > rg0 + 8) sacc[j][3] = -1e30f;
                }
            }

            // ---- online softmax (base-2), exp in half2 ----
            float mx0 = -1e30f, mx1 = -1e30f;
            #pragma unroll
            for (int j = 0; j < 8; j++) {
                mx0 = fmaxf(mx0, fmaxf(sacc[j][0], sacc[j][1]));
                mx1 = fmaxf(mx1, fmaxf(sacc[j][2], sacc[j][3]));
            }
            mx0 = fmaxf(mx0, __shfl_xor_sync(0xffffffffu, mx0, 1));
            mx0 = fmaxf(mx0, __shfl_xor_sync(0xffffffffu, mx0, 2));
            mx1 = fmaxf(mx1, __shfl_xor_sync(0xffffffffu, mx1, 1));
            mx1 = fmaxf(mx1, __shfl_xor_sync(0xffffffffu, mx1, 2));

            const float nm0 = fmaxf(m0, mx0);
            const float nm1 = fmaxf(m1, mx1);
            const float corr0 = ex2(m0 - nm0);
            const float corr1 = ex2(m1 - nm1);
            m0 = nm0; m1 = nm1;

            uint32_t ph[8][2];
            #pragma unroll
            for (int j = 0; j < 8; j++) {
                ph[j][0] = h2ex2(pack2h(sacc[j][0] - nm0, sacc[j][1] - nm0));
                ph[j][1] = h2ex2(pack2h(sacc[j][2] - nm1, sacc[j][3] - nm1));
            }

            // rescale running O and l
            #pragma unroll
            for (int j = 0; j < 8; j++) {
                o[j][0] *= corr0; o[j][1] *= corr0;
                o[j][2] *= corr1; o[j][3] *= corr1;
            }
            lacc[0] *= corr0; lacc[1] *= corr0;
            lacc[2] *= corr1; lacc[3] *= corr1;

            // ---- O += Ph Vh;  l += Ph @ ones ----
            #pragma unroll
            for (int kk = 0; kk < 4; kk++) {
                if (kk >= jjn) break;
                mma16816(lacc, ph[2*kk][0], ph[2*kk][1], ph[2*kk+1][0], ph[2*kk+1][1], ONES2H, ONES2H);
                #pragma unroll
                for (int dd = 0; dd < 4; dd++) {
                    uint32_t vh[4];
                    ldm_x4_t(vh, vbase + (uint32_t)(kk * 16 * 144 + dd * 32));
                    mma16816(o[2*dd],   ph[2*kk][0], ph[2*kk][1], ph[2*kk+1][0], ph[2*kk+1][1], vh[0], vh[1]);
                    mma16816(o[2*dd+1], ph[2*kk][0], ph[2*kk][1], ph[2*kk+1][0], ph[2*kk+1][1], vh[2], vh[3]);
                }
            }
        }
        __syncthreads();
    }

    // ---- epilogue: normalize, split hi/lo, write fp16 [B,S,HID] ----
    const float inv0 = 1.f / lacc[0];
    const float inv1 = 1.f / lacc[2];
    const size_t db0 = ((size_t)b * SS + rg0) * HID + h * 64;
    const size_t db1 = db0 + (size_t)8 * HID;
    #pragma unroll
    for (int j = 0; j < 8; j++) {
        const int c = j * 8 + 2 * (lane & 3);
        {
            float v0 = o[j][0] * inv0, v1 = o[j][1] * inv0;
            __half h0 = __float2half_rn(v0), h1 = __float2half_rn(v1);
            *(uint32_t*)&g_attnh[db0 + c] = pack2h(v0, v1);
            *(uint32_t*)&g_attnl[db0 + c] = pack2h(v0 - __half2float(h0), v1 - __half2float(h1));
        }
        {
            float v0 = o[j][2] * inv1, v1 = o[j][3] * inv1;
            __half h0 = __float2half_rn(v0), h1 = __float2half_rn(v1);
            *(uint32_t*)&g_attnh[db1 + c] = pack2h(v0, v1);
            *(uint32_t*)&g_attnl[db1 + c] = pack2h(v0 - __half2float(h0), v1 - __half2float(h1));
        }
    }
}

// ---------------------------------------------------------------------------
// Kernel 3: output projection via HMMA: (Ah+Al) @ Woh + bo.
// grid = BS/64, block = 128.  K=1024 in 16 double-buffered steps.
// ---------------------------------------------------------------------------
// per buffer: AH, AL, WH @ 9216 each = 27648; two buffers = 55296.
#define OPROJ_SMEM (2 * 27648)
__global__ void __launch_bounds__(128) oproj_mma_kernel(const float* __restrict__ bo,
                                                        float* __restrict__ out) {
    extern __shared__ char smem[];
    const uint32_t smb = smem_u32(smem);

    const int m0  = blockIdx.x * 64;
    const int tid = threadIdx.x;
    const int w   = tid >> 5;
    const int lane = tid & 31;

    {
        const uint32_t base = smb;
        for (int idx = tid; idx < 1536; idx += 128) {
            int arr = idx >> 9, rem = idx & 511, r = rem >> 3, ch = rem & 7;
            const __half* src;
            if      (arr == 0) src = g_attnh + (size_t)(m0 + r) * HID + ch * 8;
            else if (arr == 1) src = g_attnl + (size_t)(m0 + r) * HID + ch * 8;
            else               src = g_WoTh + (size_t)r * HID + ch * 8;
            CPA(base + arr * 9216 + r * 144 + ch * 16, src);
        }
        CPC();
    }

    float sacc[8][4];
    #pragma unroll
    for (int j = 0; j < 8; j++)
        #pragma unroll
        for (int e = 0; e < 4; e++) sacc[j][e] = 0.f;

    const uint32_t a_off = (uint32_t)((w * 16 + (lane & 15)) * 144 + (lane >> 4) * 16);
    const uint32_t b_off = (uint32_t)(((lane & 7) + ((lane >> 4) & 1) * 8) * 144 + ((lane >> 3) & 1) * 16);

    for (int kt = 0; kt < 16; kt++) {
        const int buf = kt & 1;
        if (kt < 15) {
            const int nk0 = (kt + 1) * 64;
            const uint32_t base = smb + (buf ^ 1) * 27648;
            for (int idx = tid; idx < 1536; idx += 128) {
                int arr = idx >> 9, rem = idx & 511, r = rem >> 3, ch = rem & 7;
                const __half* src;
                if      (arr == 0) src = g_attnh + (size_t)(m0 + r) * HID + nk0 + ch * 8;
                else if (arr == 1) src = g_attnl + (size_t)(m0 + r) * HID + nk0 + ch * 8;
                else               src = g_WoTh + (size_t)r * HID + nk0 + ch * 8;
                CPA(base + arr * 9216 + r * 144 + ch * 16, src);
            }
            CPC();
            CPW1();
        } else {
            CPW0();
        }
        __syncthreads();

        const uint32_t bb = smb + buf * 27648;
        const uint32_t abase = bb + a_off;
        const uint32_t bbase = bb + 18432 + b_off;

        #pragma unroll
        for (int kk = 0; kk < 4; kk++) {
            uint32_t ah[4], al[4];
            ldm_x4(ah, abase + kk * 32);
            ldm_x4(al, abase + kk * 32 + 9216);
            #pragma unroll
            for (int jj = 0; jj < 4; jj++) {
                uint32_t bhr[4];
                ldm_x4(bhr, bbase + (uint32_t)(jj * 16 * 144 + kk * 32));
                mma16816(sacc[2*jj],   ah[0], ah[1], ah[2], ah[3], bhr[0], bhr[1]);
                mma16816(sacc[2*jj],   al[0], al[1], al[2], al[3], bhr[0], bhr[1]);
                mma16816(sacc[2*jj+1], ah[0], ah[1], ah[2], ah[3], bhr[2], bhr[3]);
                mma16816(sacc[2*jj+1], al[0], al[1], al[2], al[3], bhr[2], bhr[3]);
            }
        }
        __syncthreads();
    }

    const int r0 = w * 16 + (lane >> 2);
    #pragma unroll
    for (int j = 0; j < 8; j++) {
        const int c = j * 8 + 2 * (lane & 3);
        out[(size_t)(m0 + r0) * DD + c]     = sacc[j][0] + bo[c];
        out[(size_t)(m0 + r0) * DD + c + 1] = sacc[j][1] + bo[c + 1];
        out[(size_t)(m0 + r0 + 8) * DD + c]     = sacc[j][2] + bo[c];
        out[(size_t)(m0 + r0 + 8) * DD + c + 1] = sacc[j][3] + bo[c + 1];
    }
}

// ---------------------------------------------------------------------------
extern "C" void kernel_launch(void* const* d_in, const int* in_sizes, int n_in,
                              void* d_out, int out_size) {
    (void)in_sizes; (void)n_in; (void)out_size;
    const float* x  = (const float*)d_in[0];
    const float* Wq = (const float*)d_in[1];
    const float* bq = (const float*)d_in[2];
    const float* Wk = (const float*)d_in[3];
    const float* bk = (const float*)d_in[4];
    const float* Wv = (const float*)d_in[5];
    const float* bv = (const float*)d_in[6];
    const float* Wo = (const float*)d_in[7];
    const float* bo = (const float*)d_in[8];
    float* out = (float*)d_out;

    prep_kernel<<<1024, 256>>>(x, Wq, Wk, Wv, Wo);

    qkv_mma_kernel<<<dim3(BS / 64, HID / 64, 3), 128>>>(bq, bk, bv);

    cudaFuncSetAttribute(attn_kernel, cudaFuncAttributeMaxDynamicSharedMemorySize, ATTN_SMEM);
    attn_kernel<<<dim3(SS / 128, HH, BB), 256, ATTN_SMEM>>>();

    cudaFuncSetAttribute(oproj_mma_kernel, cudaFuncAttributeMaxDynamicSharedMemorySize, OPROJ_SMEM);
    oproj_mma_kernel<<<BS / 64, 128, OPROJ_SMEM>>>(bo, out);
}